// round 7
// baseline (speedup 1.0000x reference)
#include <cuda_runtime.h>
#include <cuda_fp16.h>
#include <cstdint>

#define DM 1024
#define DI 2048
#define DS 16
#define Mrows 4096
#define Lseq 2048

// ---------------- scratch (device globals; allocation-free) ----------------
__device__ float g_U[Mrows * DI];
__device__ float g_S[Mrows * DI];
__device__ float g_DELTA[Mrows * DI];
__device__ float g_BM[Mrows * DS];
__device__ float g_CM[Mrows * DS];
__device__ __half g_Uh[Mrows * DI], g_Ul[Mrows * DI];
__device__ __half g_Yh[Mrows * DI], g_Yl[Mrows * DI];
__device__ __half g_xh[Mrows * DM], g_xl[Mrows * DM];
__device__ __half g_WinT[2 * DI * DM];  // [4096][1024] fp16
__device__ __half g_WdT[DI * DI];       // [2048][2048]
__device__ __half g_WoT[DM * DI];       // [1024][2048]

// ---------------- helpers ----------------
__device__ __forceinline__ float siluf(float x) { return x / (1.0f + __expf(-x)); }
__device__ __forceinline__ float softplusf(float x) {
    return (x > 20.0f) ? x : log1pf(__expf(x));
}
__device__ __forceinline__ uint32_t smem_u32(const void* p) {
    uint32_t a;
    asm("{ .reg .u64 t; cvta.to.shared.u64 t, %1; cvt.u32.u64 %0, t; }" : "=r"(a) : "l"(p));
    return a;
}
__device__ __forceinline__ void cpa16(uint32_t s, const void* g) {
    asm volatile("cp.async.cg.shared.global [%0], [%1], 16;" :: "r"(s), "l"(g));
}
__device__ __forceinline__ void cpa_commit() { asm volatile("cp.async.commit_group;"); }

__device__ __forceinline__ void ldsm4(uint32_t* r, uint32_t addr) {
    asm volatile("ldmatrix.sync.aligned.m8n8.x4.shared.b16 {%0,%1,%2,%3}, [%4];"
                 : "=r"(r[0]), "=r"(r[1]), "=r"(r[2]), "=r"(r[3]) : "r"(addr));
}
__device__ __forceinline__ void mma16816h(float* d, const uint32_t* a, const uint32_t* b) {
    asm volatile(
        "mma.sync.aligned.m16n8k16.row.col.f32.f16.f16.f32 "
        "{%0,%1,%2,%3}, {%4,%5,%6,%7}, {%8,%9}, {%0,%1,%2,%3};\n"
        : "+f"(d[0]), "+f"(d[1]), "+f"(d[2]), "+f"(d[3])
        : "r"(a[0]), "r"(a[1]), "r"(a[2]), "r"(a[3]), "r"(b[0]), "r"(b[1]));
}

// Block tile 128(m) x 256(n) x 32(k). Warp tile 64x64, 8 warps = 2m x 4n.
// SMEM per stage: Ah(128x32) + Al(128x32) + B(256x32) fp16, rows padded to
// 80B (16B-aligned; 80*r mod 128 distinct for r=0..7 -> conflict-free ldsm).
#define TPAD 80
#define TILE_A (128 * TPAD)          // 10240
#define TILE_BB (256 * TPAD)         // 20480
#define STAGE_B (2 * TILE_A + TILE_BB)  // 40960
#define NSTAGE 3
#define SMEM_TOT (NSTAGE * STAGE_B)  // 122880

// ---------------------------------------------------------------------------
// load one K-chunk (32 cols): Ah/Al 128 rows from m0, B 256 rows from n0.
// 2048 x 16B cp.async over 256 threads = 8 each.
// ---------------------------------------------------------------------------
__device__ __forceinline__ void load_chunk(
    const __half* __restrict__ Ah, const __half* __restrict__ Al,
    const __half* __restrict__ B,
    int m0, int n0, int kc, int Kdim, uint32_t sb, int tid, bool active)
{
    if (active) {
#pragma unroll
        for (int j = 0; j < 8; ++j) {
            const int g = j * 256 + tid;       // 0..2047
            const __half* base;
            uint32_t dst;
            int row, col16;
            if (g < 1024) {                    // Ah (0..511), Al (512..1023)
                const int w = g & 511;
                row = w >> 2; col16 = w & 3;
                base = (g < 512) ? Ah : Al;
                dst = sb + (uint32_t)((g < 512 ? 0 : TILE_A) + row * TPAD + col16 * 16);
                base += (size_t)(m0 + row) * Kdim + kc + col16 * 8;
            } else {                           // B (1024..2047)
                const int w = g - 1024;
                row = w >> 2; col16 = w & 3;
                dst = sb + (uint32_t)(2 * TILE_A + row * TPAD + col16 * 16);
                base = B + (size_t)(n0 + row) * Kdim + kc + col16 * 8;
            }
            cpa16(dst, (const void*)base);
        }
    }
    cpa_commit();
}

// ---------------------------------------------------------------------------
// HMMA fp16 asymmetric-split GEMM: C[M,N] = A[M,K] * B[N,K]^T  (fp32 accum)
// A as (Ah,Al) fp16 hi/lo; B single fp16. C ~= Ah*B + Al*B.
// Block 128x256, K-chunk 32, 3-stage cp.async, 8 warps (2m x 4n), 64x64/warp.
// MODE 0: n0<2048 -> U=silu -> out0 fp32 + (obh,obl) fp16 split; else S -> out1
// MODE 1: softplus(c + bias[n]) -> out0
// MODE 2: plain -> out0
// ---------------------------------------------------------------------------
template <int MODE>
__global__ void __launch_bounds__(256, 1)
tgemm(const __half* __restrict__ Ah, const __half* __restrict__ Al,
      const __half* __restrict__ B,
      int Kdim, int ostride,
      const float* __restrict__ bias,
      float* __restrict__ out0, float* __restrict__ out1,
      __half* __restrict__ obh, __half* __restrict__ obl)
{
    extern __shared__ char smem[];
    const uint32_t sb = smem_u32(smem);

    const int tid  = threadIdx.x;
    const int lane = tid & 31;
    const int wid  = tid >> 5;
    const int wm   = wid & 1;   // 0..1 (m, 64 each)
    const int wn   = wid >> 1;  // 0..3 (n, 64 each)
    const int m0 = blockIdx.y * 128;
    const int n0 = blockIdx.x * 256;

    const uint32_t a_off =
        (uint32_t)(wm * 64 + (lane & 15)) * TPAD + (uint32_t)((lane >> 4) * 16);
    const int p = lane >> 3;
    const uint32_t b_off =
        (uint32_t)(wn * 64 + (p >> 1) * 8 + (lane & 7)) * TPAD + (uint32_t)((p & 1) * 16);

    float acc[4][8][4];
#pragma unroll
    for (int i = 0; i < 4; ++i)
#pragma unroll
        for (int j = 0; j < 8; ++j)
#pragma unroll
            for (int q = 0; q < 4; ++q) acc[i][j][q] = 0.0f;

    const int NC = Kdim >> 5;

#pragma unroll
    for (int s = 0; s < NSTAGE - 1; ++s)
        load_chunk(Ah, Al, B, m0, n0, s * 32, Kdim,
                   sb + (uint32_t)s * STAGE_B, tid, s < NC);

    for (int c = 0; c < NC; ++c) {
        asm volatile("cp.async.wait_group 1;" ::: "memory");
        __syncthreads();

        load_chunk(Ah, Al, B, m0, n0, (c + NSTAGE - 1) * 32, Kdim,
                   sb + (uint32_t)((c + NSTAGE - 1) % NSTAGE) * STAGE_B, tid,
                   (c + NSTAGE - 1) < NC);

        const uint32_t st = sb + (uint32_t)(c % NSTAGE) * STAGE_B;
        const uint32_t smAh = st;
        const uint32_t smAl = st + TILE_A;
        const uint32_t smB  = st + 2 * TILE_A;

#pragma unroll
        for (int k16 = 0; k16 < 2; ++k16) {
            const uint32_t kb = (uint32_t)(k16 * 32);
            uint32_t ah[4][4], al[4][4], bf[4][4];
#pragma unroll
            for (int mt = 0; mt < 4; ++mt) {
                ldsm4(ah[mt], smAh + kb + a_off + (uint32_t)(mt * 16 * TPAD));
                ldsm4(al[mt], smAl + kb + a_off + (uint32_t)(mt * 16 * TPAD));
            }
#pragma unroll
            for (int p2 = 0; p2 < 4; ++p2)
                ldsm4(bf[p2], smB + kb + b_off + (uint32_t)(p2 * 16 * TPAD));
#pragma unroll
            for (int mt = 0; mt < 4; ++mt) {
#pragma unroll
                for (int nt = 0; nt < 8; ++nt) {
                    const uint32_t* bb = &bf[nt >> 1][(nt & 1) * 2];
                    mma16816h(acc[mt][nt], ah[mt], bb);
                    mma16816h(acc[mt][nt], al[mt], bb);
                }
            }
        }
        __syncthreads();
    }

    // ---------------- epilogue ----------------
    const int g2 = lane >> 2;
    const int c2 = (lane & 3) * 2;
#pragma unroll
    for (int mt = 0; mt < 4; ++mt) {
        const int r0 = m0 + wm * 64 + mt * 16 + g2;
#pragma unroll
        for (int nt = 0; nt < 8; ++nt) {
            const int col = n0 + wn * 64 + nt * 8 + c2;
            float v0 = acc[mt][nt][0], v1 = acc[mt][nt][1];
            float v2 = acc[mt][nt][2], v3 = acc[mt][nt][3];

            if (MODE == 0) {
                v0 = siluf(v0); v1 = siluf(v1); v2 = siluf(v2); v3 = siluf(v3);
                if (n0 < 2048) {
                    *(float2*)(out0 + (size_t)r0 * 2048 + col)       = make_float2(v0, v1);
                    *(float2*)(out0 + (size_t)(r0 + 8) * 2048 + col) = make_float2(v2, v3);
                    __half2 h0, l0, h1, l1;
                    h0.x = __float2half(v0); h0.y = __float2half(v1);
                    l0.x = __float2half(v0 - __half2float(h0.x));
                    l0.y = __float2half(v1 - __half2float(h0.y));
                    h1.x = __float2half(v2); h1.y = __float2half(v3);
                    l1.x = __float2half(v2 - __half2float(h1.x));
                    l1.y = __float2half(v3 - __half2float(h1.y));
                    *(__half2*)(obh + (size_t)r0 * 2048 + col)       = h0;
                    *(__half2*)(obl + (size_t)r0 * 2048 + col)       = l0;
                    *(__half2*)(obh + (size_t)(r0 + 8) * 2048 + col) = h1;
                    *(__half2*)(obl + (size_t)(r0 + 8) * 2048 + col) = l1;
                } else {
                    const int cs = col - 2048;
                    *(float2*)(out1 + (size_t)r0 * 2048 + cs)       = make_float2(v0, v1);
                    *(float2*)(out1 + (size_t)(r0 + 8) * 2048 + cs) = make_float2(v2, v3);
                }
            } else if (MODE == 1) {
                const float b0 = bias[col], b1 = bias[col + 1];
                *(float2*)(out0 + (size_t)r0 * ostride + col) =
                    make_float2(softplusf(v0 + b0), softplusf(v1 + b1));
                *(float2*)(out0 + (size_t)(r0 + 8) * ostride + col) =
                    make_float2(softplusf(v2 + b0), softplusf(v3 + b1));
            } else {
                *(float2*)(out0 + (size_t)r0 * ostride + col)       = make_float2(v0, v1);
                *(float2*)(out0 + (size_t)(r0 + 8) * ostride + col) = make_float2(v2, v3);
            }
        }
    }
}

// ---------------------------------------------------------------------------
// weight transpose to fp16: in[K][N] fp32 -> oh [N][K] fp16
// ---------------------------------------------------------------------------
__global__ void __launch_bounds__(256)
transp_h(const float* __restrict__ in, __half* __restrict__ oh, int K, int N)
{
    __shared__ float t[32][33];
    const int n0 = blockIdx.x * 32, k0 = blockIdx.y * 32;
    const int tx = threadIdx.x & 31, ty = threadIdx.x >> 5;
#pragma unroll
    for (int i = 0; i < 32; i += 8)
        t[ty + i][tx] = in[(size_t)(k0 + ty + i) * N + n0 + tx];
    __syncthreads();
#pragma unroll
    for (int i = 0; i < 32; i += 8) {
        const int n = n0 + ty + i, k = k0 + tx;
        oh[(size_t)n * K + k] = __float2half(t[tx][ty + i]);
    }
}

// x -> fp16 hi/lo (elementwise)
__global__ void __launch_bounds__(256)
split_x_k(const float* __restrict__ x, __half* __restrict__ xh,
          __half* __restrict__ xl)
{
    const int i = blockIdx.x * 256 + threadIdx.x;
    float4 v = ((const float4*)x)[i];
    __half2 hh0, hh1, ll0, ll1;
    hh0.x = __float2half(v.x); hh0.y = __float2half(v.y);
    hh1.x = __float2half(v.z); hh1.y = __float2half(v.w);
    ll0.x = __float2half(v.x - __half2float(hh0.x));
    ll0.y = __float2half(v.y - __half2float(hh0.y));
    ll1.x = __float2half(v.z - __half2float(hh1.x));
    ll1.y = __float2half(v.w - __half2float(hh1.y));
    ((__half2*)xh)[2*i]   = hh0;
    ((__half2*)xh)[2*i+1] = hh1;
    ((__half2*)xl)[2*i]   = ll0;
    ((__half2*)xl)[2*i+1] = ll1;
}

// ---------------------------------------------------------------------------
// Bm = U @ W_B, Cm = U @ W_C (fp32 SIMT, K=2048, N=16 each)
// ---------------------------------------------------------------------------
__global__ void __launch_bounds__(256)
bc_k(const float* __restrict__ U,
     const float* __restrict__ WB, const float* __restrict__ WC,
     float* __restrict__ BMo, float* __restrict__ CMo)
{
    const int tid = threadIdx.x;
    const int n = tid & 31;
    const int r = tid >> 5;
    const int m = blockIdx.x * 8 + r;

    const float* Wp = (n < DS) ? (WB + n) : (WC + (n - DS));
    const float* Up = U + (size_t)m * DI;

    float acc = 0.0f;
#pragma unroll 8
    for (int k = 0; k < DI; ++k)
        acc = fmaf(Up[k], Wp[(size_t)k * DS], acc);

    if (n < DS) BMo[(size_t)m * DS + n] = acc;
    else        CMo[(size_t)m * DS + (n - DS)] = acc;
}

// ---------------------------------------------------------------------------
// Sequential selective scan; emits Y as fp16 hi/lo (input for final GEMM)
// ---------------------------------------------------------------------------
__global__ void __launch_bounds__(64)
scan_k(const float* __restrict__ DEL, const float* __restrict__ U,
       const float* __restrict__ S,
       const float* __restrict__ BMi, const float* __restrict__ CMi,
       const float* __restrict__ Alog, const float* __restrict__ Dp,
       __half* __restrict__ Yh, __half* __restrict__ Yl)
{
    const int tid = threadIdx.x;
    const int g = blockIdx.x * 16 + (tid >> 2);
    const int b = g >> 11;
    const int d = g & (DI - 1);
    const int sub = tid & 3;

    const float A0 = -__expf(Alog[d * DS + sub * 4 + 0]);
    const float A1 = -__expf(Alog[d * DS + sub * 4 + 1]);
    const float A2 = -__expf(Alog[d * DS + sub * 4 + 2]);
    const float A3 = -__expf(Alog[d * DS + sub * 4 + 3]);
    const float Dd = Dp[d];

    float h0 = 0.f, h1 = 0.f, h2 = 0.f, h3 = 0.f;
    size_t xbase = ((size_t)b * Lseq) * DI + d;
    size_t rbase = ((size_t)b * Lseq) * DS + sub * 4;

#pragma unroll 4
    for (int t = 0; t < Lseq; ++t) {
        const float delta = DEL[xbase];
        const float uu    = U[xbase];
        const float4 Bv = *(const float4*)(BMi + rbase);
        const float4 Cv = *(const float4*)(CMi + rbase);

        const float a0 = __expf(delta * A0);
        const float a1 = __expf(delta * A1);
        const float a2 = __expf(delta * A2);
        const float a3 = __expf(delta * A3);
        const float db = delta * uu;

        h0 = fmaf(a0, h0, db * Bv.x);
        h1 = fmaf(a1, h1, db * Bv.y);
        h2 = fmaf(a2, h2, db * Bv.z);
        h3 = fmaf(a3, h3, db * Bv.w);

        float ps = h0 * Cv.x;
        ps = fmaf(h1, Cv.y, ps);
        ps = fmaf(h2, Cv.z, ps);
        ps = fmaf(h3, Cv.w, ps);
        ps += __shfl_xor_sync(0xffffffffu, ps, 1);
        ps += __shfl_xor_sync(0xffffffffu, ps, 2);

        if (sub == 0) {
            float yv = (ps + uu * Dd) * S[xbase];
            __half hh = __float2half(yv);
            Yh[xbase] = hh;
            Yl[xbase] = __float2half(yv - __half2float(hh));
        }
        xbase += DI;
        rbase += DS;
    }
}

// ---------------------------------------------------------------------------
extern "C" void kernel_launch(void* const* d_in, const int* in_sizes, int n_in,
                              void* d_out, int out_size)
{
    const float* x       = (const float*)d_in[0];
    const float* W_in    = (const float*)d_in[1];
    const float* W_delta = (const float*)d_in[2];
    const float* b_delta = (const float*)d_in[3];
    const float* W_B     = (const float*)d_in[4];
    const float* W_C     = (const float*)d_in[5];
    const float* A_log   = (const float*)d_in[6];
    const float* D_param = (const float*)d_in[7];
    const float* W_out   = (const float*)d_in[8];
    float* out = (float*)d_out;

    float *pU, *pS, *pDel, *pBM, *pCM;
    __half *pUh, *pUl, *pYh, *pYl, *pxh, *pxl, *pWi, *pWd, *pWo;
    cudaGetSymbolAddress((void**)&pU,   g_U);
    cudaGetSymbolAddress((void**)&pS,   g_S);
    cudaGetSymbolAddress((void**)&pDel, g_DELTA);
    cudaGetSymbolAddress((void**)&pBM,  g_BM);
    cudaGetSymbolAddress((void**)&pCM,  g_CM);
    cudaGetSymbolAddress((void**)&pUh,  g_Uh);
    cudaGetSymbolAddress((void**)&pUl,  g_Ul);
    cudaGetSymbolAddress((void**)&pYh,  g_Yh);
    cudaGetSymbolAddress((void**)&pYl,  g_Yl);
    cudaGetSymbolAddress((void**)&pxh,  g_xh);
    cudaGetSymbolAddress((void**)&pxl,  g_xl);
    cudaGetSymbolAddress((void**)&pWi,  g_WinT);
    cudaGetSymbolAddress((void**)&pWd,  g_WdT);
    cudaGetSymbolAddress((void**)&pWo,  g_WoT);

    cudaFuncSetAttribute(tgemm<0>, cudaFuncAttributeMaxDynamicSharedMemorySize, SMEM_TOT);
    cudaFuncSetAttribute(tgemm<1>, cudaFuncAttributeMaxDynamicSharedMemorySize, SMEM_TOT);
    cudaFuncSetAttribute(tgemm<2>, cudaFuncAttributeMaxDynamicSharedMemorySize, SMEM_TOT);

    // prep: split x; transpose weights to fp16
    split_x_k<<<Mrows * DM / 1024, 256>>>(x, pxh, pxl);
    transp_h<<<dim3(2 * DI / 32, DM / 32), 256>>>(W_in,    pWi, DM, 2 * DI);
    transp_h<<<dim3(DI / 32,     DI / 32), 256>>>(W_delta, pWd, DI, DI);
    transp_h<<<dim3(DM / 32,     DI / 32), 256>>>(W_out,   pWo, DI, DM);

    // 1) x @ W_in -> U (silu, fp32+fp16split) | S (silu)
    tgemm<0><<<dim3(2 * DI / 256, Mrows / 128), 256, SMEM_TOT>>>(
        pxh, pxl, pWi, DM, 2048, nullptr, pU, pS, pUh, pUl);

    // 2) Bm, Cm (SIMT)
    bc_k<<<Mrows / 8, 256>>>(pU, W_B, W_C, pBM, pCM);

    // 3) DELTA = softplus(U @ W_delta + b)
    tgemm<1><<<dim3(DI / 256, Mrows / 128), 256, SMEM_TOT>>>(
        pUh, pUl, pWd, DI, DI, b_delta, pDel, nullptr, nullptr, nullptr);

    // 4) selective scan -> Y (fp16 hi/lo)
    scan_k<<<Mrows * 4 / 64, 64>>>(pDel, pU, pS, pBM, pCM, A_log, D_param, pYh, pYl);

    // 5) out = Y @ W_out
    tgemm<2><<<dim3(DM / 256, Mrows / 128), 256, SMEM_TOT>>>(
        pYh, pYl, pWo, DI, DM, nullptr, out, nullptr, nullptr, nullptr);
}

// round 8
// speedup vs baseline: 1.0685x; 1.0685x over previous
#include <cuda_runtime.h>
#include <cuda_fp16.h>
#include <cstdint>

#define DM 1024
#define DI 2048
#define DS 16
#define Mrows 4096
#define Lseq 2048

// ---------------- scratch (device globals; allocation-free) ----------------
__device__ float g_U[Mrows * DI];
__device__ float g_S[Mrows * DI];
__device__ float g_DELTA[Mrows * DI];
__device__ float g_BM[Mrows * DS];
__device__ float g_CM[Mrows * DS];
__device__ __half g_Uh[Mrows * DI], g_Ul[Mrows * DI];
__device__ __half g_Yh[Mrows * DI], g_Yl[Mrows * DI];
__device__ __half g_xh[Mrows * DM], g_xl[Mrows * DM];
__device__ __half g_WinT[2 * DI * DM];  // [4096][1024] fp16
__device__ __half g_WdT[DI * DI];       // [2048][2048]
__device__ __half g_WoT[DM * DI];       // [1024][2048]

// ---------------- helpers ----------------
__device__ __forceinline__ float siluf(float x) { return x / (1.0f + __expf(-x)); }
__device__ __forceinline__ float softplusf(float x) {
    return (x > 20.0f) ? x : log1pf(__expf(x));
}
__device__ __forceinline__ uint32_t smem_u32(const void* p) {
    uint32_t a;
    asm("{ .reg .u64 t; cvta.to.shared.u64 t, %1; cvt.u32.u64 %0, t; }" : "=r"(a) : "l"(p));
    return a;
}
__device__ __forceinline__ void cpa16(uint32_t s, const void* g) {
    asm volatile("cp.async.cg.shared.global [%0], [%1], 16;" :: "r"(s), "l"(g));
}
__device__ __forceinline__ void cpa_commit() { asm volatile("cp.async.commit_group;"); }

__device__ __forceinline__ void ldsm4(uint32_t* r, uint32_t addr) {
    asm volatile("ldmatrix.sync.aligned.m8n8.x4.shared.b16 {%0,%1,%2,%3}, [%4];"
                 : "=r"(r[0]), "=r"(r[1]), "=r"(r[2]), "=r"(r[3]) : "r"(addr));
}
__device__ __forceinline__ void mma16816h(float* d, const uint32_t* a, const uint32_t* b) {
    asm volatile(
        "mma.sync.aligned.m16n8k16.row.col.f32.f16.f16.f32 "
        "{%0,%1,%2,%3}, {%4,%5,%6,%7}, {%8,%9}, {%0,%1,%2,%3};\n"
        : "+f"(d[0]), "+f"(d[1]), "+f"(d[2]), "+f"(d[3])
        : "r"(a[0]), "r"(a[1]), "r"(a[2]), "r"(a[3]), "r"(b[0]), "r"(b[1]));
}

// Block tile 128x128x64. 8 warps = 4m x 2n, warp tile 32x64.
// SMEM per stage: Ah, Al, B each 128 rows x 64 fp16 (128B data),
// padded to 144B/row (16B-aligned; 144*r mod 128 distinct for r=0..7).
#define TPAD 144
#define TILE_B (128 * TPAD)          // 18432
#define STAGE_B (3 * TILE_B)         // 55296
#define NSTAGE 2
#define SMEM_TOT (NSTAGE * STAGE_B)  // 110592 -> 2 CTAs/SM

// ---------------------------------------------------------------------------
// load one K-chunk (64 cols) of 3 fp16 tiles (Ah, Al, B) into stage base sb.
// 3 x 128 rows x 8 x 16B = 3072 cp.async over 256 threads = 12 each.
// ---------------------------------------------------------------------------
__device__ __forceinline__ void load_chunk(
    const __half* __restrict__ Ah, const __half* __restrict__ Al,
    const __half* __restrict__ B,
    int m0, int n0, int kc, int Kdim, uint32_t sb, int tid, bool active)
{
    if (active) {
#pragma unroll
        for (int j = 0; j < 12; ++j) {
            const int g = j * 256 + tid;       // 0..3071
            const int tile = g >> 10;          // 0..2
            const int w = g & 1023;
            const int row = w >> 3;
            const int col16 = w & 7;
            const __half* base = (tile == 0) ? Ah : (tile == 1) ? Al : B;
            const int r0 = (tile == 2) ? n0 : m0;
            const __half* src = base + (size_t)(r0 + row) * Kdim + kc + col16 * 8;
            cpa16(sb + (uint32_t)(tile * TILE_B + row * TPAD + col16 * 16),
                  (const void*)src);
        }
    }
    cpa_commit();
}

// ---------------------------------------------------------------------------
// HMMA fp16 asymmetric-split GEMM: C[M,N] = A[M,K] * B[N,K]^T  (fp32 accum)
// A as (Ah,Al) fp16 hi/lo; B single fp16. C ~= Ah*B + Al*B.
// Block 128x128, K-chunk 64, 2-stage cp.async (1 barrier per chunk),
// 8 warps (4m x 2n), 2 CTAs/SM. Inner MMAs reordered: all 16 acc tiles on the
// hi term, then all on the lo term (no back-to-back RAW on acc registers).
// MODE 0: n0<2048 -> U=silu -> out0 fp32 + (obh,obl) fp16 split; else S -> out1
// MODE 1: softplus(c + bias[n]) -> out0
// MODE 2: plain -> out0
// ---------------------------------------------------------------------------
template <int MODE>
__global__ void __launch_bounds__(256, 2)
tgemm(const __half* __restrict__ Ah, const __half* __restrict__ Al,
      const __half* __restrict__ B,
      int Kdim, int ostride,
      const float* __restrict__ bias,
      float* __restrict__ out0, float* __restrict__ out1,
      __half* __restrict__ obh, __half* __restrict__ obl)
{
    extern __shared__ char smem[];
    const uint32_t sb = smem_u32(smem);

    const int tid  = threadIdx.x;
    const int lane = tid & 31;
    const int wid  = tid >> 5;
    const int wm   = wid & 3;   // 0..3 (m)
    const int wn   = wid >> 2;  // 0..1 (n)
    const int m0 = blockIdx.y * 128;
    const int n0 = blockIdx.x * 128;

    const uint32_t a_off =
        (uint32_t)(wm * 32 + (lane & 15)) * TPAD + (uint32_t)((lane >> 4) * 16);
    const int p = lane >> 3;
    const uint32_t b_off =
        (uint32_t)(wn * 64 + (p >> 1) * 8 + (lane & 7)) * TPAD + (uint32_t)((p & 1) * 16);

    float acc[2][8][4];
#pragma unroll
    for (int i = 0; i < 2; ++i)
#pragma unroll
        for (int j = 0; j < 8; ++j)
#pragma unroll
            for (int q = 0; q < 4; ++q) acc[i][j][q] = 0.0f;

    const int NC = Kdim >> 6;

    // prologue: prefetch chunk 0 into stage 0
    load_chunk(Ah, Al, B, m0, n0, 0, Kdim, sb, tid, 0 < NC);

    for (int c = 0; c < NC; ++c) {
        asm volatile("cp.async.wait_group 0;" ::: "memory");
        __syncthreads();   // chunk c resident; all compute on stage (c+1)&1 done

        load_chunk(Ah, Al, B, m0, n0, (c + 1) * 64, Kdim,
                   sb + (uint32_t)((c + 1) & 1) * STAGE_B, tid, (c + 1) < NC);

        const uint32_t st = sb + (uint32_t)(c & 1) * STAGE_B;
        const uint32_t smAh = st;
        const uint32_t smAl = st + TILE_B;
        const uint32_t smB  = st + 2 * TILE_B;

#pragma unroll
        for (int k16 = 0; k16 < 4; ++k16) {
            const uint32_t kb = (uint32_t)(k16 * 32);
            uint32_t ah[2][4], al[2][4], bf[4][4];
#pragma unroll
            for (int mt = 0; mt < 2; ++mt) {
                ldsm4(ah[mt], smAh + kb + a_off + (uint32_t)(mt * 16 * TPAD));
                ldsm4(al[mt], smAl + kb + a_off + (uint32_t)(mt * 16 * TPAD));
            }
#pragma unroll
            for (int p2 = 0; p2 < 4; ++p2)
                ldsm4(bf[p2], smB + kb + b_off + (uint32_t)(p2 * 16 * TPAD));
            // hi sweep: 16 independent accumulators
#pragma unroll
            for (int mt = 0; mt < 2; ++mt)
#pragma unroll
                for (int nt = 0; nt < 8; ++nt)
                    mma16816h(acc[mt][nt], ah[mt], &bf[nt >> 1][(nt & 1) * 2]);
            // lo sweep
#pragma unroll
            for (int mt = 0; mt < 2; ++mt)
#pragma unroll
                for (int nt = 0; nt < 8; ++nt)
                    mma16816h(acc[mt][nt], al[mt], &bf[nt >> 1][(nt & 1) * 2]);
        }
    }

    __syncthreads();

    // ---------------- epilogue ----------------
    const int g2 = lane >> 2;
    const int c2 = (lane & 3) * 2;
#pragma unroll
    for (int mt = 0; mt < 2; ++mt) {
        const int r0 = m0 + wm * 32 + mt * 16 + g2;
#pragma unroll
        for (int nt = 0; nt < 8; ++nt) {
            const int col = n0 + wn * 64 + nt * 8 + c2;
            float v0 = acc[mt][nt][0], v1 = acc[mt][nt][1];
            float v2 = acc[mt][nt][2], v3 = acc[mt][nt][3];

            if (MODE == 0) {
                v0 = siluf(v0); v1 = siluf(v1); v2 = siluf(v2); v3 = siluf(v3);
                if (n0 < 2048) {
                    *(float2*)(out0 + (size_t)r0 * 2048 + col)       = make_float2(v0, v1);
                    *(float2*)(out0 + (size_t)(r0 + 8) * 2048 + col) = make_float2(v2, v3);
                    __half2 h0, l0, h1, l1;
                    h0.x = __float2half(v0); h0.y = __float2half(v1);
                    l0.x = __float2half(v0 - __half2float(h0.x));
                    l0.y = __float2half(v1 - __half2float(h0.y));
                    h1.x = __float2half(v2); h1.y = __float2half(v3);
                    l1.x = __float2half(v2 - __half2float(h1.x));
                    l1.y = __float2half(v3 - __half2float(h1.y));
                    *(__half2*)(obh + (size_t)r0 * 2048 + col)       = h0;
                    *(__half2*)(obl + (size_t)r0 * 2048 + col)       = l0;
                    *(__half2*)(obh + (size_t)(r0 + 8) * 2048 + col) = h1;
                    *(__half2*)(obl + (size_t)(r0 + 8) * 2048 + col) = l1;
                } else {
                    const int cs = col - 2048;
                    *(float2*)(out1 + (size_t)r0 * 2048 + cs)       = make_float2(v0, v1);
                    *(float2*)(out1 + (size_t)(r0 + 8) * 2048 + cs) = make_float2(v2, v3);
                }
            } else if (MODE == 1) {
                const float b0 = bias[col], b1 = bias[col + 1];
                *(float2*)(out0 + (size_t)r0 * ostride + col) =
                    make_float2(softplusf(v0 + b0), softplusf(v1 + b1));
                *(float2*)(out0 + (size_t)(r0 + 8) * ostride + col) =
                    make_float2(softplusf(v2 + b0), softplusf(v3 + b1));
            } else {
                *(float2*)(out0 + (size_t)r0 * ostride + col)       = make_float2(v0, v1);
                *(float2*)(out0 + (size_t)(r0 + 8) * ostride + col) = make_float2(v2, v3);
            }
        }
    }
}

// ---------------------------------------------------------------------------
// weight transpose to fp16: in[K][N] fp32 -> oh [N][K] fp16
// ---------------------------------------------------------------------------
__global__ void __launch_bounds__(256)
transp_h(const float* __restrict__ in, __half* __restrict__ oh, int K, int N)
{
    __shared__ float t[32][33];
    const int n0 = blockIdx.x * 32, k0 = blockIdx.y * 32;
    const int tx = threadIdx.x & 31, ty = threadIdx.x >> 5;
#pragma unroll
    for (int i = 0; i < 32; i += 8)
        t[ty + i][tx] = in[(size_t)(k0 + ty + i) * N + n0 + tx];
    __syncthreads();
#pragma unroll
    for (int i = 0; i < 32; i += 8) {
        const int n = n0 + ty + i, k = k0 + tx;
        oh[(size_t)n * K + k] = __float2half(t[tx][ty + i]);
    }
}

// x -> fp16 hi/lo (elementwise)
__global__ void __launch_bounds__(256)
split_x_k(const float* __restrict__ x, __half* __restrict__ xh,
          __half* __restrict__ xl)
{
    const int i = blockIdx.x * 256 + threadIdx.x;
    float4 v = ((const float4*)x)[i];
    __half2 hh0, hh1, ll0, ll1;
    hh0.x = __float2half(v.x); hh0.y = __float2half(v.y);
    hh1.x = __float2half(v.z); hh1.y = __float2half(v.w);
    ll0.x = __float2half(v.x - __half2float(hh0.x));
    ll0.y = __float2half(v.y - __half2float(hh0.y));
    ll1.x = __float2half(v.z - __half2float(hh1.x));
    ll1.y = __float2half(v.w - __half2float(hh1.y));
    ((__half2*)xh)[2*i]   = hh0;
    ((__half2*)xh)[2*i+1] = hh1;
    ((__half2*)xl)[2*i]   = ll0;
    ((__half2*)xl)[2*i+1] = ll1;
}

// ---------------------------------------------------------------------------
// Bm = U @ W_B, Cm = U @ W_C (fp32 SIMT, K=2048, N=16 each)
// ---------------------------------------------------------------------------
__global__ void __launch_bounds__(256)
bc_k(const float* __restrict__ U,
     const float* __restrict__ WB, const float* __restrict__ WC,
     float* __restrict__ BMo, float* __restrict__ CMo)
{
    const int tid = threadIdx.x;
    const int n = tid & 31;
    const int r = tid >> 5;
    const int m = blockIdx.x * 8 + r;

    const float* Wp = (n < DS) ? (WB + n) : (WC + (n - DS));
    const float* Up = U + (size_t)m * DI;

    float acc = 0.0f;
#pragma unroll 8
    for (int k = 0; k < DI; ++k)
        acc = fmaf(Up[k], Wp[(size_t)k * DS], acc);

    if (n < DS) BMo[(size_t)m * DS + n] = acc;
    else        CMo[(size_t)m * DS + (n - DS)] = acc;
}

// ---------------------------------------------------------------------------
// Sequential selective scan; emits Y as fp16 hi/lo (input for final GEMM)
// ---------------------------------------------------------------------------
__global__ void __launch_bounds__(64)
scan_k(const float* __restrict__ DEL, const float* __restrict__ U,
       const float* __restrict__ S,
       const float* __restrict__ BMi, const float* __restrict__ CMi,
       const float* __restrict__ Alog, const float* __restrict__ Dp,
       __half* __restrict__ Yh, __half* __restrict__ Yl)
{
    const int tid = threadIdx.x;
    const int g = blockIdx.x * 16 + (tid >> 2);
    const int b = g >> 11;
    const int d = g & (DI - 1);
    const int sub = tid & 3;

    const float A0 = -__expf(Alog[d * DS + sub * 4 + 0]);
    const float A1 = -__expf(Alog[d * DS + sub * 4 + 1]);
    const float A2 = -__expf(Alog[d * DS + sub * 4 + 2]);
    const float A3 = -__expf(Alog[d * DS + sub * 4 + 3]);
    const float Dd = Dp[d];

    float h0 = 0.f, h1 = 0.f, h2 = 0.f, h3 = 0.f;
    size_t xbase = ((size_t)b * Lseq) * DI + d;
    size_t rbase = ((size_t)b * Lseq) * DS + sub * 4;

#pragma unroll 4
    for (int t = 0; t < Lseq; ++t) {
        const float delta = DEL[xbase];
        const float uu    = U[xbase];
        const float4 Bv = *(const float4*)(BMi + rbase);
        const float4 Cv = *(const float4*)(CMi + rbase);

        const float a0 = __expf(delta * A0);
        const float a1 = __expf(delta * A1);
        const float a2 = __expf(delta * A2);
        const float a3 = __expf(delta * A3);
        const float db = delta * uu;

        h0 = fmaf(a0, h0, db * Bv.x);
        h1 = fmaf(a1, h1, db * Bv.y);
        h2 = fmaf(a2, h2, db * Bv.z);
        h3 = fmaf(a3, h3, db * Bv.w);

        float ps = h0 * Cv.x;
        ps = fmaf(h1, Cv.y, ps);
        ps = fmaf(h2, Cv.z, ps);
        ps = fmaf(h3, Cv.w, ps);
        ps += __shfl_xor_sync(0xffffffffu, ps, 1);
        ps += __shfl_xor_sync(0xffffffffu, ps, 2);

        if (sub == 0) {
            float yv = (ps + uu * Dd) * S[xbase];
            __half hh = __float2half(yv);
            Yh[xbase] = hh;
            Yl[xbase] = __float2half(yv - __half2float(hh));
        }
        xbase += DI;
        rbase += DS;
    }
}

// ---------------------------------------------------------------------------
extern "C" void kernel_launch(void* const* d_in, const int* in_sizes, int n_in,
                              void* d_out, int out_size)
{
    const float* x       = (const float*)d_in[0];
    const float* W_in    = (const float*)d_in[1];
    const float* W_delta = (const float*)d_in[2];
    const float* b_delta = (const float*)d_in[3];
    const float* W_B     = (const float*)d_in[4];
    const float* W_C     = (const float*)d_in[5];
    const float* A_log   = (const float*)d_in[6];
    const float* D_param = (const float*)d_in[7];
    const float* W_out   = (const float*)d_in[8];
    float* out = (float*)d_out;

    float *pU, *pS, *pDel, *pBM, *pCM;
    __half *pUh, *pUl, *pYh, *pYl, *pxh, *pxl, *pWi, *pWd, *pWo;
    cudaGetSymbolAddress((void**)&pU,   g_U);
    cudaGetSymbolAddress((void**)&pS,   g_S);
    cudaGetSymbolAddress((void**)&pDel, g_DELTA);
    cudaGetSymbolAddress((void**)&pBM,  g_BM);
    cudaGetSymbolAddress((void**)&pCM,  g_CM);
    cudaGetSymbolAddress((void**)&pUh,  g_Uh);
    cudaGetSymbolAddress((void**)&pUl,  g_Ul);
    cudaGetSymbolAddress((void**)&pYh,  g_Yh);
    cudaGetSymbolAddress((void**)&pYl,  g_Yl);
    cudaGetSymbolAddress((void**)&pxh,  g_xh);
    cudaGetSymbolAddress((void**)&pxl,  g_xl);
    cudaGetSymbolAddress((void**)&pWi,  g_WinT);
    cudaGetSymbolAddress((void**)&pWd,  g_WdT);
    cudaGetSymbolAddress((void**)&pWo,  g_WoT);

    cudaFuncSetAttribute(tgemm<0>, cudaFuncAttributeMaxDynamicSharedMemorySize, SMEM_TOT);
    cudaFuncSetAttribute(tgemm<1>, cudaFuncAttributeMaxDynamicSharedMemorySize, SMEM_TOT);
    cudaFuncSetAttribute(tgemm<2>, cudaFuncAttributeMaxDynamicSharedMemorySize, SMEM_TOT);

    // prep: split x; transpose weights to fp16
    split_x_k<<<Mrows * DM / 1024, 256>>>(x, pxh, pxl);
    transp_h<<<dim3(2 * DI / 32, DM / 32), 256>>>(W_in,    pWi, DM, 2 * DI);
    transp_h<<<dim3(DI / 32,     DI / 32), 256>>>(W_delta, pWd, DI, DI);
    transp_h<<<dim3(DM / 32,     DI / 32), 256>>>(W_out,   pWo, DI, DM);

    // 1) x @ W_in -> U (silu, fp32+fp16split) | S (silu)
    tgemm<0><<<dim3(2 * DI / 128, Mrows / 128), 256, SMEM_TOT>>>(
        pxh, pxl, pWi, DM, 2048, nullptr, pU, pS, pUh, pUl);

    // 2) Bm, Cm (SIMT)
    bc_k<<<Mrows / 8, 256>>>(pU, W_B, W_C, pBM, pCM);

    // 3) DELTA = softplus(U @ W_delta + b)
    tgemm<1><<<dim3(DI / 128, Mrows / 128), 256, SMEM_TOT>>>(
        pUh, pUl, pWd, DI, DI, b_delta, pDel, nullptr, nullptr, nullptr);

    // 4) selective scan -> Y (fp16 hi/lo)
    scan_k<<<Mrows * 4 / 64, 64>>>(pDel, pU, pS, pBM, pCM, A_log, D_param, pYh, pYl);

    // 5) out = Y @ W_out
    tgemm<2><<<dim3(DM / 128, Mrows / 128), 256, SMEM_TOT>>>(
        pYh, pYl, pWo, DI, DM, nullptr, out, nullptr, nullptr, nullptr);
}

// round 9
// speedup vs baseline: 1.1279x; 1.0557x over previous
#include <cuda_runtime.h>
#include <cuda_fp16.h>
#include <cstdint>

#define DM 1024
#define DI 2048
#define DS 16
#define Mrows 4096
#define Lseq 2048

// ---------------- scratch (device globals; allocation-free) ----------------
__device__ float g_U[Mrows * DI];
__device__ float g_S[Mrows * DI];
__device__ float g_DELTA[Mrows * DI];
__device__ float g_BM[Mrows * DS];
__device__ float g_CM[Mrows * DS];
__device__ __half g_Uh[Mrows * DI], g_Ul[Mrows * DI];
__device__ __half g_Yh[Mrows * DI], g_Yl[Mrows * DI];
__device__ __half g_xh[Mrows * DM];
__device__ __half g_WinT[2 * DI * DM];  // [4096][1024] fp16
__device__ __half g_WdT[DI * DI];       // [2048][2048]
__device__ __half g_WoT[DM * DI];       // [1024][2048]

// ---------------- helpers ----------------
__device__ __forceinline__ float siluf(float x) { return x / (1.0f + __expf(-x)); }
__device__ __forceinline__ float softplusf(float x) {
    return (x > 20.0f) ? x : log1pf(__expf(x));
}
__device__ __forceinline__ uint32_t smem_u32(const void* p) {
    uint32_t a;
    asm("{ .reg .u64 t; cvta.to.shared.u64 t, %1; cvt.u32.u64 %0, t; }" : "=r"(a) : "l"(p));
    return a;
}
__device__ __forceinline__ void cpa16(uint32_t s, const void* g) {
    asm volatile("cp.async.cg.shared.global [%0], [%1], 16;" :: "r"(s), "l"(g));
}
__device__ __forceinline__ void cpa_commit() { asm volatile("cp.async.commit_group;"); }

__device__ __forceinline__ void ldsm4(uint32_t* r, uint32_t addr) {
    asm volatile("ldmatrix.sync.aligned.m8n8.x4.shared.b16 {%0,%1,%2,%3}, [%4];"
                 : "=r"(r[0]), "=r"(r[1]), "=r"(r[2]), "=r"(r[3]) : "r"(addr));
}
__device__ __forceinline__ void mma16816h(float* d, const uint32_t* a, const uint32_t* b) {
    asm volatile(
        "mma.sync.aligned.m16n8k16.row.col.f32.f16.f16.f32 "
        "{%0,%1,%2,%3}, {%4,%5,%6,%7}, {%8,%9}, {%0,%1,%2,%3};\n"
        : "+f"(d[0]), "+f"(d[1]), "+f"(d[2]), "+f"(d[3])
        : "r"(a[0]), "r"(a[1]), "r"(a[2]), "r"(a[3]), "r"(b[0]), "r"(b[1]));
}

// Block tile 128x128x64. 8 warps = 4m x 2n, warp tile 32x64.
// SMEM per stage: Ah, Al, B each 128 rows x 64 fp16 (128B data),
// padded to 144B/row (16B-aligned; 144*r mod 128 distinct for r=0..7).
#define TPAD 144
#define TILE_B (128 * TPAD)          // 18432
#define STAGE_B (3 * TILE_B)         // 55296
#define NSTAGE 2
#define SMEM_TOT (NSTAGE * STAGE_B)  // 110592 -> 2 CTAs/SM

// ---------------------------------------------------------------------------
// load one K-chunk (64 cols) of fp16 tiles into stage base sb.
// slots: 0=Ah 1=Al(skipped if !SPLIT2) 2=B.
// ---------------------------------------------------------------------------
template <bool SPLIT2>
__device__ __forceinline__ void load_chunk(
    const __half* __restrict__ Ah, const __half* __restrict__ Al,
    const __half* __restrict__ B,
    int m0, int n0, int kc, int Kdim, uint32_t sb, int tid, bool active)
{
    if (active) {
#pragma unroll
        for (int j = 0; j < 12; ++j) {
            const int g = j * 256 + tid;       // 0..3071
            const int tile = g >> 10;          // 0..2
            if (!SPLIT2 && tile == 1) continue;
            const int w = g & 1023;
            const int row = w >> 3;
            const int col16 = w & 7;
            const __half* base = (tile == 0) ? Ah : (tile == 1) ? Al : B;
            const int r0 = (tile == 2) ? n0 : m0;
            const __half* src = base + (size_t)(r0 + row) * Kdim + kc + col16 * 8;
            cpa16(sb + (uint32_t)(tile * TILE_B + row * TPAD + col16 * 16),
                  (const void*)src);
        }
    }
    cpa_commit();
}

// ---------------------------------------------------------------------------
// HMMA fp16 GEMM: C[M,N] = A[M,K] * B[N,K]^T  (fp32 accum)
// SPLIT2: A as (Ah,Al) fp16 hi/lo, C ~= Ah*B + Al*B.  else: C = Ah*B.
// Block 128x128, K-chunk 64, 2-stage cp.async, 8 warps (4m x 2n), 2 CTAs/SM.
// MODE 0: n0<2048 -> U=silu -> out0 fp32 + (obh,obl) fp16 split; else S -> out1
// MODE 1: softplus(c + bias[n]) -> out0
// MODE 2: plain -> out0
// ---------------------------------------------------------------------------
template <int MODE, bool SPLIT2>
__global__ void __launch_bounds__(256, 2)
tgemm(const __half* __restrict__ Ah, const __half* __restrict__ Al,
      const __half* __restrict__ B,
      int Kdim, int ostride,
      const float* __restrict__ bias,
      float* __restrict__ out0, float* __restrict__ out1,
      __half* __restrict__ obh, __half* __restrict__ obl)
{
    extern __shared__ char smem[];
    const uint32_t sb = smem_u32(smem);

    const int tid  = threadIdx.x;
    const int lane = tid & 31;
    const int wid  = tid >> 5;
    const int wm   = wid & 3;   // 0..3 (m)
    const int wn   = wid >> 2;  // 0..1 (n)
    const int m0 = blockIdx.y * 128;
    const int n0 = blockIdx.x * 128;

    const uint32_t a_off =
        (uint32_t)(wm * 32 + (lane & 15)) * TPAD + (uint32_t)((lane >> 4) * 16);
    const int p = lane >> 3;
    const uint32_t b_off =
        (uint32_t)(wn * 64 + (p >> 1) * 8 + (lane & 7)) * TPAD + (uint32_t)((p & 1) * 16);

    float acc[2][8][4];
#pragma unroll
    for (int i = 0; i < 2; ++i)
#pragma unroll
        for (int j = 0; j < 8; ++j)
#pragma unroll
            for (int q = 0; q < 4; ++q) acc[i][j][q] = 0.0f;

    const int NC = Kdim >> 6;

    load_chunk<SPLIT2>(Ah, Al, B, m0, n0, 0, Kdim, sb, tid, 0 < NC);

    for (int c = 0; c < NC; ++c) {
        asm volatile("cp.async.wait_group 0;" ::: "memory");
        __syncthreads();   // chunk c resident; all compute on stage (c+1)&1 done

        load_chunk<SPLIT2>(Ah, Al, B, m0, n0, (c + 1) * 64, Kdim,
                           sb + (uint32_t)((c + 1) & 1) * STAGE_B, tid, (c + 1) < NC);

        const uint32_t st = sb + (uint32_t)(c & 1) * STAGE_B;
        const uint32_t smAh = st;
        const uint32_t smAl = st + TILE_B;
        const uint32_t smB  = st + 2 * TILE_B;

#pragma unroll
        for (int k16 = 0; k16 < 4; ++k16) {
            const uint32_t kb = (uint32_t)(k16 * 32);
            uint32_t ah[2][4], al[2][4], bf[4][4];
#pragma unroll
            for (int mt = 0; mt < 2; ++mt) {
                ldsm4(ah[mt], smAh + kb + a_off + (uint32_t)(mt * 16 * TPAD));
                if (SPLIT2)
                    ldsm4(al[mt], smAl + kb + a_off + (uint32_t)(mt * 16 * TPAD));
            }
#pragma unroll
            for (int p2 = 0; p2 < 4; ++p2)
                ldsm4(bf[p2], smB + kb + b_off + (uint32_t)(p2 * 16 * TPAD));
            // hi sweep: 16 independent accumulators
#pragma unroll
            for (int mt = 0; mt < 2; ++mt)
#pragma unroll
                for (int nt = 0; nt < 8; ++nt)
                    mma16816h(acc[mt][nt], ah[mt], &bf[nt >> 1][(nt & 1) * 2]);
            if (SPLIT2) {
#pragma unroll
                for (int mt = 0; mt < 2; ++mt)
#pragma unroll
                    for (int nt = 0; nt < 8; ++nt)
                        mma16816h(acc[mt][nt], al[mt], &bf[nt >> 1][(nt & 1) * 2]);
            }
        }
    }

    __syncthreads();

    // ---------------- epilogue ----------------
    const int g2 = lane >> 2;
    const int c2 = (lane & 3) * 2;
#pragma unroll
    for (int mt = 0; mt < 2; ++mt) {
        const int r0 = m0 + wm * 32 + mt * 16 + g2;
#pragma unroll
        for (int nt = 0; nt < 8; ++nt) {
            const int col = n0 + wn * 64 + nt * 8 + c2;
            float v0 = acc[mt][nt][0], v1 = acc[mt][nt][1];
            float v2 = acc[mt][nt][2], v3 = acc[mt][nt][3];

            if (MODE == 0) {
                v0 = siluf(v0); v1 = siluf(v1); v2 = siluf(v2); v3 = siluf(v3);
                if (n0 < 2048) {
                    *(float2*)(out0 + (size_t)r0 * 2048 + col)       = make_float2(v0, v1);
                    *(float2*)(out0 + (size_t)(r0 + 8) * 2048 + col) = make_float2(v2, v3);
                    __half2 h0, l0, h1, l1;
                    h0.x = __float2half(v0); h0.y = __float2half(v1);
                    l0.x = __float2half(v0 - __half2float(h0.x));
                    l0.y = __float2half(v1 - __half2float(h0.y));
                    h1.x = __float2half(v2); h1.y = __float2half(v3);
                    l1.x = __float2half(v2 - __half2float(h1.x));
                    l1.y = __float2half(v3 - __half2float(h1.y));
                    *(__half2*)(obh + (size_t)r0 * 2048 + col)       = h0;
                    *(__half2*)(obl + (size_t)r0 * 2048 + col)       = l0;
                    *(__half2*)(obh + (size_t)(r0 + 8) * 2048 + col) = h1;
                    *(__half2*)(obl + (size_t)(r0 + 8) * 2048 + col) = l1;
                } else {
                    const int cs = col - 2048;
                    *(float2*)(out1 + (size_t)r0 * 2048 + cs)       = make_float2(v0, v1);
                    *(float2*)(out1 + (size_t)(r0 + 8) * 2048 + cs) = make_float2(v2, v3);
                }
            } else if (MODE == 1) {
                const float b0 = bias[col], b1 = bias[col + 1];
                *(float2*)(out0 + (size_t)r0 * ostride + col) =
                    make_float2(softplusf(v0 + b0), softplusf(v1 + b1));
                *(float2*)(out0 + (size_t)(r0 + 8) * ostride + col) =
                    make_float2(softplusf(v2 + b0), softplusf(v3 + b1));
            } else {
                *(float2*)(out0 + (size_t)r0 * ostride + col)       = make_float2(v0, v1);
                *(float2*)(out0 + (size_t)(r0 + 8) * ostride + col) = make_float2(v2, v3);
            }
        }
    }
}

// ---------------------------------------------------------------------------
// weight transpose to fp16: in[K][N] fp32 -> oh [N][K] fp16
// ---------------------------------------------------------------------------
__global__ void __launch_bounds__(256)
transp_h(const float* __restrict__ in, __half* __restrict__ oh, int K, int N)
{
    __shared__ float t[32][33];
    const int n0 = blockIdx.x * 32, k0 = blockIdx.y * 32;
    const int tx = threadIdx.x & 31, ty = threadIdx.x >> 5;
#pragma unroll
    for (int i = 0; i < 32; i += 8)
        t[ty + i][tx] = in[(size_t)(k0 + ty + i) * N + n0 + tx];
    __syncthreads();
#pragma unroll
    for (int i = 0; i < 32; i += 8) {
        const int n = n0 + ty + i, k = k0 + tx;
        oh[(size_t)n * K + k] = __float2half(t[tx][ty + i]);
    }
}

// x -> fp16 (single term)
__global__ void __launch_bounds__(256)
conv_x_k(const float* __restrict__ x, __half* __restrict__ xh)
{
    const int i = blockIdx.x * 256 + threadIdx.x;
    float4 v = ((const float4*)x)[i];
    __half2 hh0, hh1;
    hh0.x = __float2half(v.x); hh0.y = __float2half(v.y);
    hh1.x = __float2half(v.z); hh1.y = __float2half(v.w);
    ((__half2*)xh)[2*i]   = hh0;
    ((__half2*)xh)[2*i+1] = hh1;
}

// ---------------------------------------------------------------------------
// Bm = U @ W_B, Cm = U @ W_C (fp32 SIMT, K=2048, N=16 each)
// ---------------------------------------------------------------------------
__global__ void __launch_bounds__(256)
bc_k(const float* __restrict__ U,
     const float* __restrict__ WB, const float* __restrict__ WC,
     float* __restrict__ BMo, float* __restrict__ CMo)
{
    const int tid = threadIdx.x;
    const int n = tid & 31;
    const int r = tid >> 5;
    const int m = blockIdx.x * 8 + r;

    const float* Wp = (n < DS) ? (WB + n) : (WC + (n - DS));
    const float* Up = U + (size_t)m * DI;

    float acc = 0.0f;
#pragma unroll 8
    for (int k = 0; k < DI; ++k)
        acc = fmaf(Up[k], Wp[(size_t)k * DS], acc);

    if (n < DS) BMo[(size_t)m * DS + n] = acc;
    else        CMo[(size_t)m * DS + (n - DS)] = acc;
}

// ---------------------------------------------------------------------------
// Sequential selective scan; emits Y as fp16 hi/lo (input for final GEMM)
// ---------------------------------------------------------------------------
__global__ void __launch_bounds__(64)
scan_k(const float* __restrict__ DEL, const float* __restrict__ U,
       const float* __restrict__ S,
       const float* __restrict__ BMi, const float* __restrict__ CMi,
       const float* __restrict__ Alog, const float* __restrict__ Dp,
       __half* __restrict__ Yh, __half* __restrict__ Yl)
{
    const int tid = threadIdx.x;
    const int g = blockIdx.x * 16 + (tid >> 2);
    const int b = g >> 11;
    const int d = g & (DI - 1);
    const int sub = tid & 3;

    const float A0 = -__expf(Alog[d * DS + sub * 4 + 0]);
    const float A1 = -__expf(Alog[d * DS + sub * 4 + 1]);
    const float A2 = -__expf(Alog[d * DS + sub * 4 + 2]);
    const float A3 = -__expf(Alog[d * DS + sub * 4 + 3]);
    const float Dd = Dp[d];

    float h0 = 0.f, h1 = 0.f, h2 = 0.f, h3 = 0.f;
    size_t xbase = ((size_t)b * Lseq) * DI + d;
    size_t rbase = ((size_t)b * Lseq) * DS + sub * 4;

#pragma unroll 4
    for (int t = 0; t < Lseq; ++t) {
        const float delta = DEL[xbase];
        const float uu    = U[xbase];
        const float4 Bv = *(const float4*)(BMi + rbase);
        const float4 Cv = *(const float4*)(CMi + rbase);

        const float a0 = __expf(delta * A0);
        const float a1 = __expf(delta * A1);
        const float a2 = __expf(delta * A2);
        const float a3 = __expf(delta * A3);
        const float db = delta * uu;

        h0 = fmaf(a0, h0, db * Bv.x);
        h1 = fmaf(a1, h1, db * Bv.y);
        h2 = fmaf(a2, h2, db * Bv.z);
        h3 = fmaf(a3, h3, db * Bv.w);

        float ps = h0 * Cv.x;
        ps = fmaf(h1, Cv.y, ps);
        ps = fmaf(h2, Cv.z, ps);
        ps = fmaf(h3, Cv.w, ps);
        ps += __shfl_xor_sync(0xffffffffu, ps, 1);
        ps += __shfl_xor_sync(0xffffffffu, ps, 2);

        if (sub == 0) {
            float yv = (ps + uu * Dd) * S[xbase];
            __half hh = __float2half(yv);
            Yh[xbase] = hh;
            Yl[xbase] = __float2half(yv - __half2float(hh));
        }
        xbase += DI;
        rbase += DS;
    }
}

// ---------------------------------------------------------------------------
extern "C" void kernel_launch(void* const* d_in, const int* in_sizes, int n_in,
                              void* d_out, int out_size)
{
    const float* x       = (const float*)d_in[0];
    const float* W_in    = (const float*)d_in[1];
    const float* W_delta = (const float*)d_in[2];
    const float* b_delta = (const float*)d_in[3];
    const float* W_B     = (const float*)d_in[4];
    const float* W_C     = (const float*)d_in[5];
    const float* A_log   = (const float*)d_in[6];
    const float* D_param = (const float*)d_in[7];
    const float* W_out   = (const float*)d_in[8];
    float* out = (float*)d_out;

    float *pU, *pS, *pDel, *pBM, *pCM;
    __half *pUh, *pUl, *pYh, *pYl, *pxh, *pWi, *pWd, *pWo;
    cudaGetSymbolAddress((void**)&pU,   g_U);
    cudaGetSymbolAddress((void**)&pS,   g_S);
    cudaGetSymbolAddress((void**)&pDel, g_DELTA);
    cudaGetSymbolAddress((void**)&pBM,  g_BM);
    cudaGetSymbolAddress((void**)&pCM,  g_CM);
    cudaGetSymbolAddress((void**)&pUh,  g_Uh);
    cudaGetSymbolAddress((void**)&pUl,  g_Ul);
    cudaGetSymbolAddress((void**)&pYh,  g_Yh);
    cudaGetSymbolAddress((void**)&pYl,  g_Yl);
    cudaGetSymbolAddress((void**)&pxh,  g_xh);
    cudaGetSymbolAddress((void**)&pWi,  g_WinT);
    cudaGetSymbolAddress((void**)&pWd,  g_WdT);
    cudaGetSymbolAddress((void**)&pWo,  g_WoT);

    cudaFuncSetAttribute((const void*)tgemm<0, false>, cudaFuncAttributeMaxDynamicSharedMemorySize, SMEM_TOT);
    cudaFuncSetAttribute((const void*)tgemm<1, true>,  cudaFuncAttributeMaxDynamicSharedMemorySize, SMEM_TOT);
    cudaFuncSetAttribute((const void*)tgemm<2, true>,  cudaFuncAttributeMaxDynamicSharedMemorySize, SMEM_TOT);

    // Launch order tuned so tgemm<0> lands on ncu's capture slot (-s 5):
    // conv_x(0) tWin(1) tWd(2) tgemm0(3) tWo(4) bc(5) tgemm1(6) scan(7) tgemm2(8)
    conv_x_k<<<Mrows * DM / 1024, 256>>>(x, pxh);
    transp_h<<<dim3(2 * DI / 32, DM / 32), 256>>>(W_in,    pWi, DM, 2 * DI);
    transp_h<<<dim3(DI / 32,     DI / 32), 256>>>(W_delta, pWd, DI, DI);

    // 1) x @ W_in -> U (silu, fp32+fp16split) | S (silu)   [single-term x]
    tgemm<0, false><<<dim3(2 * DI / 128, Mrows / 128), 256, SMEM_TOT>>>(
        pxh, pxh, pWi, DM, 2048, nullptr, pU, pS, pUh, pUl);

    transp_h<<<dim3(DM / 32, DI / 32), 256>>>(W_out, pWo, DI, DM);

    // 2) Bm, Cm (SIMT)
    bc_k<<<Mrows / 8, 256>>>(pU, W_B, W_C, pBM, pCM);

    // 3) DELTA = softplus(U @ W_delta + b)   [2-term U]
    tgemm<1, true><<<dim3(DI / 128, Mrows / 128), 256, SMEM_TOT>>>(
        pUh, pUl, pWd, DI, DI, b_delta, pDel, nullptr, nullptr, nullptr);

    // 4) selective scan -> Y (fp16 hi/lo)
    scan_k<<<Mrows * 4 / 64, 64>>>(pDel, pU, pS, pBM, pCM, A_log, D_param, pYh, pYl);

    // 5) out = Y @ W_out   [2-term Y]
    tgemm<2, true><<<dim3(DM / 128, Mrows / 128), 256, SMEM_TOT>>>(
        pYh, pYl, pWo, DI, DM, nullptr, out, nullptr, nullptr, nullptr);
}

// round 10
// speedup vs baseline: 2.0637x; 1.8296x over previous
#include <cuda_runtime.h>
#include <cuda_fp16.h>
#include <cstdint>

#define DM 1024
#define DI 2048
#define DS 16
#define Mrows 4096
#define Lseq 2048
#define CH 16      // chunks
#define TL 128     // timesteps per chunk

// ---------------- scratch (device globals; allocation-free) ----------------
__device__ float g_U[Mrows * DI];
__device__ float g_S[Mrows * DI];
__device__ float g_DELTA[Mrows * DI];
__device__ float g_BM[Mrows * DS];
__device__ float g_CM[Mrows * DS];
__device__ __half g_Uh[Mrows * DI], g_Ul[Mrows * DI];
__device__ __half g_Yh[Mrows * DI], g_Yl[Mrows * DI];
__device__ __half g_xh[Mrows * DM];
__device__ __half g_WinT[2 * DI * DM];
__device__ __half g_WdT[DI * DI];
__device__ __half g_WoT[DM * DI];
__device__ float4 g_W4[512 * 32];          // packed W_B|W_C: [k/4][32] x float4
__device__ float4 g_P4[CH * 2 * DI * 4];   // per-chunk decay products
__device__ float4 g_Q4[CH * 2 * DI * 4];   // per-chunk partial states
__device__ float4 g_H4[CH * 2 * DI * 4];   // chunk entry states

// ---------------- helpers ----------------
__device__ __forceinline__ float siluf(float x) { return x / (1.0f + __expf(-x)); }
__device__ __forceinline__ float softplusf(float x) {
    return (x > 20.0f) ? x : log1pf(__expf(x));
}
__device__ __forceinline__ uint32_t smem_u32(const void* p) {
    uint32_t a;
    asm("{ .reg .u64 t; cvta.to.shared.u64 t, %1; cvt.u32.u64 %0, t; }" : "=r"(a) : "l"(p));
    return a;
}
__device__ __forceinline__ void cpa16(uint32_t s, const void* g) {
    asm volatile("cp.async.cg.shared.global [%0], [%1], 16;" :: "r"(s), "l"(g));
}
__device__ __forceinline__ void cpa_commit() { asm volatile("cp.async.commit_group;"); }

__device__ __forceinline__ void ldsm4(uint32_t* r, uint32_t addr) {
    asm volatile("ldmatrix.sync.aligned.m8n8.x4.shared.b16 {%0,%1,%2,%3}, [%4];"
                 : "=r"(r[0]), "=r"(r[1]), "=r"(r[2]), "=r"(r[3]) : "r"(addr));
}
__device__ __forceinline__ void mma16816h(float* d, const uint32_t* a, const uint32_t* b) {
    asm volatile(
        "mma.sync.aligned.m16n8k16.row.col.f32.f16.f16.f32 "
        "{%0,%1,%2,%3}, {%4,%5,%6,%7}, {%8,%9}, {%0,%1,%2,%3};\n"
        : "+f"(d[0]), "+f"(d[1]), "+f"(d[2]), "+f"(d[3])
        : "r"(a[0]), "r"(a[1]), "r"(a[2]), "r"(a[3]), "r"(b[0]), "r"(b[1]));
}

#define TPAD 144
#define TILE_B (128 * TPAD)
#define STAGE_B (3 * TILE_B)
#define NSTAGE 2
#define SMEM_TOT (NSTAGE * STAGE_B)  // 110592 -> 2 CTAs/SM

template <bool SPLIT2>
__device__ __forceinline__ void load_chunk(
    const __half* __restrict__ Ah, const __half* __restrict__ Al,
    const __half* __restrict__ B,
    int m0, int n0, int kc, int Kdim, uint32_t sb, int tid, bool active)
{
    if (active) {
#pragma unroll
        for (int j = 0; j < 12; ++j) {
            const int g = j * 256 + tid;
            const int tile = g >> 10;
            if (!SPLIT2 && tile == 1) continue;
            const int w = g & 1023;
            const int row = w >> 3;
            const int col16 = w & 7;
            const __half* base = (tile == 0) ? Ah : (tile == 1) ? Al : B;
            const int r0 = (tile == 2) ? n0 : m0;
            const __half* src = base + (size_t)(r0 + row) * Kdim + kc + col16 * 8;
            cpa16(sb + (uint32_t)(tile * TILE_B + row * TPAD + col16 * 16),
                  (const void*)src);
        }
    }
    cpa_commit();
}

// ---------------------------------------------------------------------------
// HMMA fp16 GEMM (unchanged from R9 winner)
// ---------------------------------------------------------------------------
template <int MODE, bool SPLIT2>
__global__ void __launch_bounds__(256, 2)
tgemm(const __half* __restrict__ Ah, const __half* __restrict__ Al,
      const __half* __restrict__ B,
      int Kdim, int ostride,
      const float* __restrict__ bias,
      float* __restrict__ out0, float* __restrict__ out1,
      __half* __restrict__ obh, __half* __restrict__ obl)
{
    extern __shared__ char smem[];
    const uint32_t sb = smem_u32(smem);

    const int tid  = threadIdx.x;
    const int lane = tid & 31;
    const int wid  = tid >> 5;
    const int wm   = wid & 3;
    const int wn   = wid >> 2;
    const int m0 = blockIdx.y * 128;
    const int n0 = blockIdx.x * 128;

    const uint32_t a_off =
        (uint32_t)(wm * 32 + (lane & 15)) * TPAD + (uint32_t)((lane >> 4) * 16);
    const int p = lane >> 3;
    const uint32_t b_off =
        (uint32_t)(wn * 64 + (p >> 1) * 8 + (lane & 7)) * TPAD + (uint32_t)((p & 1) * 16);

    float acc[2][8][4];
#pragma unroll
    for (int i = 0; i < 2; ++i)
#pragma unroll
        for (int j = 0; j < 8; ++j)
#pragma unroll
            for (int q = 0; q < 4; ++q) acc[i][j][q] = 0.0f;

    const int NC = Kdim >> 6;

    load_chunk<SPLIT2>(Ah, Al, B, m0, n0, 0, Kdim, sb, tid, 0 < NC);

    for (int c = 0; c < NC; ++c) {
        asm volatile("cp.async.wait_group 0;" ::: "memory");
        __syncthreads();

        load_chunk<SPLIT2>(Ah, Al, B, m0, n0, (c + 1) * 64, Kdim,
                           sb + (uint32_t)((c + 1) & 1) * STAGE_B, tid, (c + 1) < NC);

        const uint32_t st = sb + (uint32_t)(c & 1) * STAGE_B;
        const uint32_t smAh = st;
        const uint32_t smAl = st + TILE_B;
        const uint32_t smB  = st + 2 * TILE_B;

#pragma unroll
        for (int k16 = 0; k16 < 4; ++k16) {
            const uint32_t kb = (uint32_t)(k16 * 32);
            uint32_t ah[2][4], al[2][4], bf[4][4];
#pragma unroll
            for (int mt = 0; mt < 2; ++mt) {
                ldsm4(ah[mt], smAh + kb + a_off + (uint32_t)(mt * 16 * TPAD));
                if (SPLIT2)
                    ldsm4(al[mt], smAl + kb + a_off + (uint32_t)(mt * 16 * TPAD));
            }
#pragma unroll
            for (int p2 = 0; p2 < 4; ++p2)
                ldsm4(bf[p2], smB + kb + b_off + (uint32_t)(p2 * 16 * TPAD));
#pragma unroll
            for (int mt = 0; mt < 2; ++mt)
#pragma unroll
                for (int nt = 0; nt < 8; ++nt)
                    mma16816h(acc[mt][nt], ah[mt], &bf[nt >> 1][(nt & 1) * 2]);
            if (SPLIT2) {
#pragma unroll
                for (int mt = 0; mt < 2; ++mt)
#pragma unroll
                    for (int nt = 0; nt < 8; ++nt)
                        mma16816h(acc[mt][nt], al[mt], &bf[nt >> 1][(nt & 1) * 2]);
            }
        }
    }

    __syncthreads();

    const int g2 = lane >> 2;
    const int c2 = (lane & 3) * 2;
#pragma unroll
    for (int mt = 0; mt < 2; ++mt) {
        const int r0 = m0 + wm * 32 + mt * 16 + g2;
#pragma unroll
        for (int nt = 0; nt < 8; ++nt) {
            const int col = n0 + wn * 64 + nt * 8 + c2;
            float v0 = acc[mt][nt][0], v1 = acc[mt][nt][1];
            float v2 = acc[mt][nt][2], v3 = acc[mt][nt][3];

            if (MODE == 0) {
                v0 = siluf(v0); v1 = siluf(v1); v2 = siluf(v2); v3 = siluf(v3);
                if (n0 < 2048) {
                    *(float2*)(out0 + (size_t)r0 * 2048 + col)       = make_float2(v0, v1);
                    *(float2*)(out0 + (size_t)(r0 + 8) * 2048 + col) = make_float2(v2, v3);
                    __half2 h0, l0, h1, l1;
                    h0.x = __float2half(v0); h0.y = __float2half(v1);
                    l0.x = __float2half(v0 - __half2float(h0.x));
                    l0.y = __float2half(v1 - __half2float(h0.y));
                    h1.x = __float2half(v2); h1.y = __float2half(v3);
                    l1.x = __float2half(v2 - __half2float(h1.x));
                    l1.y = __float2half(v3 - __half2float(h1.y));
                    *(__half2*)(obh + (size_t)r0 * 2048 + col)       = h0;
                    *(__half2*)(obl + (size_t)r0 * 2048 + col)       = l0;
                    *(__half2*)(obh + (size_t)(r0 + 8) * 2048 + col) = h1;
                    *(__half2*)(obl + (size_t)(r0 + 8) * 2048 + col) = l1;
                } else {
                    const int cs = col - 2048;
                    *(float2*)(out1 + (size_t)r0 * 2048 + cs)       = make_float2(v0, v1);
                    *(float2*)(out1 + (size_t)(r0 + 8) * 2048 + cs) = make_float2(v2, v3);
                }
            } else if (MODE == 1) {
                const float b0 = bias[col], b1 = bias[col + 1];
                *(float2*)(out0 + (size_t)r0 * ostride + col) =
                    make_float2(softplusf(v0 + b0), softplusf(v1 + b1));
                *(float2*)(out0 + (size_t)(r0 + 8) * ostride + col) =
                    make_float2(softplusf(v2 + b0), softplusf(v3 + b1));
            } else {
                *(float2*)(out0 + (size_t)r0 * ostride + col)       = make_float2(v0, v1);
                *(float2*)(out0 + (size_t)(r0 + 8) * ostride + col) = make_float2(v2, v3);
            }
        }
    }
}

// ---------------------------------------------------------------------------
// prep_all: all weight transposes (fp32->fp16 [N][K]) + W_B/W_C float4 pack
// block decode: [0,4096) Win, [4096,8192) Wd, [8192,10240) Wo, [10240,10256) W4
// ---------------------------------------------------------------------------
__device__ __forceinline__ void transp_tile(
    const float* __restrict__ in, __half* __restrict__ oh,
    int K, int N, int nb, int kb, int tid)
{
    __shared__ float t[32][33];
    const int n0 = nb * 32, k0 = kb * 32;
    const int tx = tid & 31, ty = tid >> 5;
#pragma unroll
    for (int i = 0; i < 32; i += 8)
        t[ty + i][tx] = in[(size_t)(k0 + ty + i) * N + n0 + tx];
    __syncthreads();
#pragma unroll
    for (int i = 0; i < 32; i += 8) {
        const int n = n0 + ty + i, k = k0 + tx;
        oh[(size_t)n * K + k] = __float2half(t[tx][ty + i]);
    }
}

__global__ void __launch_bounds__(256)
prep_all(const float* __restrict__ W_in, const float* __restrict__ W_delta,
         const float* __restrict__ W_out,
         const float* __restrict__ WB, const float* __restrict__ WC,
         __half* __restrict__ Wi, __half* __restrict__ Wd, __half* __restrict__ Wo,
         float4* __restrict__ W4)
{
    const int blk = blockIdx.x;
    const int tid = threadIdx.x;
    if (blk < 4096) {
        transp_tile(W_in, Wi, DM, 2 * DI, blk & 127, blk >> 7, tid);
    } else if (blk < 8192) {
        const int t2 = blk - 4096;
        transp_tile(W_delta, Wd, DI, DI, t2 & 63, t2 >> 6, tid);
    } else if (blk < 10240) {
        const int t3 = blk - 8192;
        transp_tile(W_out, Wo, DI, DM, t3 & 31, t3 >> 5, tid);
    } else {
        const int base = (blk - 10240) * 256 + tid;   // 0..4095
#pragma unroll
        for (int i = 0; i < 4; ++i) {
            const int id = base + i * 4096;           // 0..16383
            const int k4 = id >> 5;
            const int n = id & 31;
            float4 v;
            if (n < DS) {
                v.x = WB[(k4 * 4 + 0) * DS + n];
                v.y = WB[(k4 * 4 + 1) * DS + n];
                v.z = WB[(k4 * 4 + 2) * DS + n];
                v.w = WB[(k4 * 4 + 3) * DS + n];
            } else {
                v.x = WC[(k4 * 4 + 0) * DS + n - DS];
                v.y = WC[(k4 * 4 + 1) * DS + n - DS];
                v.z = WC[(k4 * 4 + 2) * DS + n - DS];
                v.w = WC[(k4 * 4 + 3) * DS + n - DS];
            }
            W4[id] = v;
        }
    }
}

// x -> fp16
__global__ void __launch_bounds__(256)
conv_x_k(const float* __restrict__ x, __half* __restrict__ xh)
{
    const int i = blockIdx.x * 256 + threadIdx.x;
    float4 v = ((const float4*)x)[i];
    __half2 hh0, hh1;
    hh0.x = __float2half(v.x); hh0.y = __float2half(v.y);
    hh1.x = __float2half(v.z); hh1.y = __float2half(v.w);
    ((__half2*)xh)[2*i]   = hh0;
    ((__half2*)xh)[2*i+1] = hh1;
}

// ---------------------------------------------------------------------------
// Bm|Cm = U @ [W_B|W_C] via packed W4: per 4k, 2x LDG.128 + 4 indep FMA accs.
// ---------------------------------------------------------------------------
__global__ void __launch_bounds__(256)
bc_k(const float* __restrict__ U, const float4* __restrict__ W4,
     float* __restrict__ BMo, float* __restrict__ CMo)
{
    const int tid = threadIdx.x;
    const int n = tid & 31;
    const int r = tid >> 5;
    const int m = blockIdx.x * 8 + r;

    const float4* Up = (const float4*)(U + (size_t)m * DI);
    float a0 = 0.f, a1 = 0.f, a2 = 0.f, a3 = 0.f;
#pragma unroll 8
    for (int k4 = 0; k4 < DI / 4; ++k4) {
        const float4 uv = Up[k4];
        const float4 wv = W4[k4 * 32 + n];
        a0 = fmaf(uv.x, wv.x, a0);
        a1 = fmaf(uv.y, wv.y, a1);
        a2 = fmaf(uv.z, wv.z, a2);
        a3 = fmaf(uv.w, wv.w, a3);
    }
    const float acc = (a0 + a1) + (a2 + a3);
    if (n < DS) BMo[(size_t)m * DS + n] = acc;
    else        CMo[(size_t)m * DS + (n - DS)] = acc;
}

// ---------------------------------------------------------------------------
// Chunked scan. Thread = (chunk c, channel g, sub). 4 states per thread.
// exp trick: a_i uniformly-spaced in A => a0=exp(d*A0), r=exp(d*(A1-A0)),
// a_{i+1}=a_i*r (2 MUFU instead of 4); general fallback otherwise.
// ---------------------------------------------------------------------------
__global__ void __launch_bounds__(64)
scanA(const float* __restrict__ DEL, const float* __restrict__ U,
      const float* __restrict__ BMi, const float* __restrict__ Alog,
      float4* __restrict__ P4, float4* __restrict__ Q4)
{
    const int c = blockIdx.y;
    const int tid = threadIdx.x;
    const int g = blockIdx.x * 16 + (tid >> 2);
    const int b = g >> 11;
    const int d = g & (DI - 1);
    const int sub = tid & 3;

    const float A0 = -__expf(Alog[d * DS + sub * 4 + 0]);
    const float A1 = -__expf(Alog[d * DS + sub * 4 + 1]);
    const float A2 = -__expf(Alog[d * DS + sub * 4 + 2]);
    const float A3 = -__expf(Alog[d * DS + sub * 4 + 3]);
    const float d10 = A1 - A0;
    const bool uni = (fabsf((A2 - A1) - d10) <= 1e-4f * fabsf(d10) + 1e-20f) &&
                     (fabsf((A3 - A2) - d10) <= 1e-4f * fabsf(d10) + 1e-20f);

    float4 P = make_float4(1.f, 1.f, 1.f, 1.f);
    float4 q = make_float4(0.f, 0.f, 0.f, 0.f);

    size_t xbase = ((size_t)b * Lseq + (size_t)c * TL) * DI + d;
    size_t rbase = ((size_t)b * Lseq + (size_t)c * TL) * DS + sub * 4;

#pragma unroll 4
    for (int t = 0; t < TL; ++t) {
        const float delta = DEL[xbase];
        const float uu    = U[xbase];
        const float4 Bv = *(const float4*)(BMi + rbase);

        float a0, a1, a2, a3;
        if (uni) {
            a0 = __expf(delta * A0);
            const float rr = __expf(delta * d10);
            a1 = a0 * rr; a2 = a1 * rr; a3 = a2 * rr;
        } else {
            a0 = __expf(delta * A0); a1 = __expf(delta * A1);
            a2 = __expf(delta * A2); a3 = __expf(delta * A3);
        }
        const float db = delta * uu;
        q.x = fmaf(a0, q.x, db * Bv.x);
        q.y = fmaf(a1, q.y, db * Bv.y);
        q.z = fmaf(a2, q.z, db * Bv.z);
        q.w = fmaf(a3, q.w, db * Bv.w);
        P.x *= a0; P.y *= a1; P.z *= a2; P.w *= a3;

        xbase += DI;
        rbase += DS;
    }
    const int idx = (((c * 2 + b) * DI) + d) * 4 + sub;
    P4[idx] = P;
    Q4[idx] = q;
}

__global__ void __launch_bounds__(256)
scanB(const float4* __restrict__ P4, const float4* __restrict__ Q4,
      float4* __restrict__ H4)
{
    const int gs = blockIdx.x * 256 + threadIdx.x;   // 0..16383
    const int g = gs >> 2;
    const int sub = gs & 3;
    const int b = g >> 11;
    const int d = g & (DI - 1);

    float4 h = make_float4(0.f, 0.f, 0.f, 0.f);
#pragma unroll
    for (int c = 0; c < CH; ++c) {
        const int idx = (((c * 2 + b) * DI) + d) * 4 + sub;
        H4[idx] = h;
        const float4 P = P4[idx];
        const float4 q = Q4[idx];
        h.x = fmaf(P.x, h.x, q.x);
        h.y = fmaf(P.y, h.y, q.y);
        h.z = fmaf(P.z, h.z, q.z);
        h.w = fmaf(P.w, h.w, q.w);
    }
}

__global__ void __launch_bounds__(64)
scanC(const float* __restrict__ DEL, const float* __restrict__ U,
      const float* __restrict__ S,
      const float* __restrict__ BMi, const float* __restrict__ CMi,
      const float* __restrict__ Alog, const float* __restrict__ Dp,
      const float4* __restrict__ H4,
      __half* __restrict__ Yh, __half* __restrict__ Yl)
{
    const int c = blockIdx.y;
    const int tid = threadIdx.x;
    const int g = blockIdx.x * 16 + (tid >> 2);
    const int b = g >> 11;
    const int d = g & (DI - 1);
    const int sub = tid & 3;

    const float A0 = -__expf(Alog[d * DS + sub * 4 + 0]);
    const float A1 = -__expf(Alog[d * DS + sub * 4 + 1]);
    const float A2 = -__expf(Alog[d * DS + sub * 4 + 2]);
    const float A3 = -__expf(Alog[d * DS + sub * 4 + 3]);
    const float d10 = A1 - A0;
    const bool uni = (fabsf((A2 - A1) - d10) <= 1e-4f * fabsf(d10) + 1e-20f) &&
                     (fabsf((A3 - A2) - d10) <= 1e-4f * fabsf(d10) + 1e-20f);
    const float Dd = Dp[d];

    const int idx = (((c * 2 + b) * DI) + d) * 4 + sub;
    float4 h = H4[idx];

    size_t xbase = ((size_t)b * Lseq + (size_t)c * TL) * DI + d;
    size_t rbase = ((size_t)b * Lseq + (size_t)c * TL) * DS + sub * 4;

#pragma unroll 4
    for (int t = 0; t < TL; ++t) {
        const float delta = DEL[xbase];
        const float uu    = U[xbase];
        const float4 Bv = *(const float4*)(BMi + rbase);
        const float4 Cv = *(const float4*)(CMi + rbase);

        float a0, a1, a2, a3;
        if (uni) {
            a0 = __expf(delta * A0);
            const float rr = __expf(delta * d10);
            a1 = a0 * rr; a2 = a1 * rr; a3 = a2 * rr;
        } else {
            a0 = __expf(delta * A0); a1 = __expf(delta * A1);
            a2 = __expf(delta * A2); a3 = __expf(delta * A3);
        }
        const float db = delta * uu;
        h.x = fmaf(a0, h.x, db * Bv.x);
        h.y = fmaf(a1, h.y, db * Bv.y);
        h.z = fmaf(a2, h.z, db * Bv.z);
        h.w = fmaf(a3, h.w, db * Bv.w);

        float ps = h.x * Cv.x;
        ps = fmaf(h.y, Cv.y, ps);
        ps = fmaf(h.z, Cv.z, ps);
        ps = fmaf(h.w, Cv.w, ps);
        ps += __shfl_xor_sync(0xffffffffu, ps, 1);
        ps += __shfl_xor_sync(0xffffffffu, ps, 2);

        if (sub == 0) {
            const float yv = (ps + uu * Dd) * S[xbase];
            const __half hh = __float2half(yv);
            Yh[xbase] = hh;
            Yl[xbase] = __float2half(yv - __half2float(hh));
        }
        xbase += DI;
        rbase += DS;
    }
}

// ---------------------------------------------------------------------------
extern "C" void kernel_launch(void* const* d_in, const int* in_sizes, int n_in,
                              void* d_out, int out_size)
{
    const float* x       = (const float*)d_in[0];
    const float* W_in    = (const float*)d_in[1];
    const float* W_delta = (const float*)d_in[2];
    const float* b_delta = (const float*)d_in[3];
    const float* W_B     = (const float*)d_in[4];
    const float* W_C     = (const float*)d_in[5];
    const float* A_log   = (const float*)d_in[6];
    const float* D_param = (const float*)d_in[7];
    const float* W_out   = (const float*)d_in[8];
    float* out = (float*)d_out;

    float *pU, *pS, *pDel, *pBM, *pCM;
    __half *pUh, *pUl, *pYh, *pYl, *pxh, *pWi, *pWd, *pWo;
    float4 *pW4, *pP4, *pQ4, *pH4;
    cudaGetSymbolAddress((void**)&pU,   g_U);
    cudaGetSymbolAddress((void**)&pS,   g_S);
    cudaGetSymbolAddress((void**)&pDel, g_DELTA);
    cudaGetSymbolAddress((void**)&pBM,  g_BM);
    cudaGetSymbolAddress((void**)&pCM,  g_CM);
    cudaGetSymbolAddress((void**)&pUh,  g_Uh);
    cudaGetSymbolAddress((void**)&pUl,  g_Ul);
    cudaGetSymbolAddress((void**)&pYh,  g_Yh);
    cudaGetSymbolAddress((void**)&pYl,  g_Yl);
    cudaGetSymbolAddress((void**)&pxh,  g_xh);
    cudaGetSymbolAddress((void**)&pWi,  g_WinT);
    cudaGetSymbolAddress((void**)&pWd,  g_WdT);
    cudaGetSymbolAddress((void**)&pWo,  g_WoT);
    cudaGetSymbolAddress((void**)&pW4,  g_W4);
    cudaGetSymbolAddress((void**)&pP4,  g_P4);
    cudaGetSymbolAddress((void**)&pQ4,  g_Q4);
    cudaGetSymbolAddress((void**)&pH4,  g_H4);

    cudaFuncSetAttribute((const void*)tgemm<0, false>, cudaFuncAttributeMaxDynamicSharedMemorySize, SMEM_TOT);
    cudaFuncSetAttribute((const void*)tgemm<1, true>,  cudaFuncAttributeMaxDynamicSharedMemorySize, SMEM_TOT);
    cudaFuncSetAttribute((const void*)tgemm<2, true>,  cudaFuncAttributeMaxDynamicSharedMemorySize, SMEM_TOT);

    // Launch order keeps tgemm<1> on ncu's capture slot (my 4th launch):
    // prep(1) conv(2) tgemm0(3) tgemm1(4) bc(5) scanA(6) scanB(7) scanC(8) tgemm2(9)
    prep_all<<<10256, 256>>>(W_in, W_delta, W_out, W_B, W_C, pWi, pWd, pWo, pW4);
    conv_x_k<<<Mrows * DM / 1024, 256>>>(x, pxh);

    // 1) x @ W_in -> U (silu, fp32+fp16split) | S (silu)
    tgemm<0, false><<<dim3(2 * DI / 128, Mrows / 128), 256, SMEM_TOT>>>(
        pxh, pxh, pWi, DM, 2048, nullptr, pU, pS, pUh, pUl);

    // 3) DELTA = softplus(U @ W_delta + b)
    tgemm<1, true><<<dim3(DI / 128, Mrows / 128), 256, SMEM_TOT>>>(
        pUh, pUl, pWd, DI, DI, b_delta, pDel, nullptr, nullptr, nullptr);

    // 2) Bm, Cm (vectorized)
    bc_k<<<Mrows / 8, 256>>>(pU, pW4, pBM, pCM);

    // 4) chunked selective scan -> Y (fp16 hi/lo)
    scanA<<<dim3(256, CH), 64>>>(pDel, pU, pBM, A_log, pP4, pQ4);
    scanB<<<64, 256>>>(pP4, pQ4, pH4);
    scanC<<<dim3(256, CH), 64>>>(pDel, pU, pS, pBM, pCM, A_log, D_param,
                                 pH4, pYh, pYl);

    // 5) out = Y @ W_out
    tgemm<2, true><<<dim3(DM / 128, Mrows / 128), 256, SMEM_TOT>>>(
        pYh, pYl, pWo, DI, DM, nullptr, out, nullptr, nullptr, nullptr);
}

// round 11
// speedup vs baseline: 2.1339x; 1.0340x over previous
#include <cuda_runtime.h>
#include <cuda_fp16.h>
#include <cstdint>

#define DM 1024
#define DI 2048
#define DS 16
#define Mrows 4096
#define Lseq 2048
#define CH 16      // chunks
#define TL 128     // timesteps per chunk

// ---------------- scratch (device globals; allocation-free) ----------------
__device__ float g_S[Mrows * DI];
__device__ float g_DELTA[Mrows * DI];
__device__ float g_BM[Mrows * DS];
__device__ float g_CM[Mrows * DS];
__device__ __half g_Uh[Mrows * DI], g_Ul[Mrows * DI];
__device__ __half g_Yh[Mrows * DI];
__device__ __half g_xh[Mrows * DM];
__device__ __half g_WinT[2 * DI * DM];
__device__ __half g_WdT[DI * DI];
__device__ __half g_WoT[DM * DI];
__device__ float4 g_W4[512 * 32];          // packed W_B|W_C: [k/4][32] x float4
__device__ float4 g_P4[CH * 2 * DI * 4];   // per-chunk decay products
__device__ float4 g_Q4[CH * 2 * DI * 4];   // per-chunk partial states
__device__ float4 g_H4[CH * 2 * DI * 4];   // chunk entry states

// ---------------- helpers ----------------
__device__ __forceinline__ float siluf(float x) { return x / (1.0f + __expf(-x)); }
__device__ __forceinline__ float softplusf(float x) {
    return (x > 20.0f) ? x : log1pf(__expf(x));
}
__device__ __forceinline__ uint32_t smem_u32(const void* p) {
    uint32_t a;
    asm("{ .reg .u64 t; cvta.to.shared.u64 t, %1; cvt.u32.u64 %0, t; }" : "=r"(a) : "l"(p));
    return a;
}
__device__ __forceinline__ void cpa16(uint32_t s, const void* g) {
    asm volatile("cp.async.cg.shared.global [%0], [%1], 16;" :: "r"(s), "l"(g));
}
__device__ __forceinline__ void cpa_commit() { asm volatile("cp.async.commit_group;"); }

__device__ __forceinline__ void ldsm4(uint32_t* r, uint32_t addr) {
    asm volatile("ldmatrix.sync.aligned.m8n8.x4.shared.b16 {%0,%1,%2,%3}, [%4];"
                 : "=r"(r[0]), "=r"(r[1]), "=r"(r[2]), "=r"(r[3]) : "r"(addr));
}
__device__ __forceinline__ void mma16816h(float* d, const uint32_t* a, const uint32_t* b) {
    asm volatile(
        "mma.sync.aligned.m16n8k16.row.col.f32.f16.f16.f32 "
        "{%0,%1,%2,%3}, {%4,%5,%6,%7}, {%8,%9}, {%0,%1,%2,%3};\n"
        : "+f"(d[0]), "+f"(d[1]), "+f"(d[2]), "+f"(d[3])
        : "r"(a[0]), "r"(a[1]), "r"(a[2]), "r"(a[3]), "r"(b[0]), "r"(b[1]));
}

#define TPAD 144
#define TILE_B (128 * TPAD)
#define STAGE_B (3 * TILE_B)
#define NSTAGE 2
#define SMEM_TOT (NSTAGE * STAGE_B)  // 110592 -> 2 CTAs/SM

template <bool SPLIT2>
__device__ __forceinline__ void load_chunk(
    const __half* __restrict__ Ah, const __half* __restrict__ Al,
    const __half* __restrict__ B,
    int m0, int n0, int kc, int Kdim, uint32_t sb, int tid, bool active)
{
    if (active) {
#pragma unroll
        for (int j = 0; j < 12; ++j) {
            const int g = j * 256 + tid;
            const int tile = g >> 10;
            if (!SPLIT2 && tile == 1) continue;
            const int w = g & 1023;
            const int row = w >> 3;
            const int col16 = w & 7;
            const __half* base = (tile == 0) ? Ah : (tile == 1) ? Al : B;
            const int r0 = (tile == 2) ? n0 : m0;
            const __half* src = base + (size_t)(r0 + row) * Kdim + kc + col16 * 8;
            cpa16(sb + (uint32_t)(tile * TILE_B + row * TPAD + col16 * 16),
                  (const void*)src);
        }
    }
    cpa_commit();
}

// ---------------------------------------------------------------------------
// HMMA fp16 GEMM: C[M,N] = A[M,K] * B[N,K]^T  (fp32 accum)
// SPLIT2: C ~= Ah*B + Al*B ; else C = Ah*B.
// MODE 0: n0<2048 -> U=silu -> (obh,obl) fp16 split; else S=silu -> out1
// MODE 1: softplus(c + bias[n]) -> out0
// MODE 2: plain -> out0
// ---------------------------------------------------------------------------
template <int MODE, bool SPLIT2>
__global__ void __launch_bounds__(256, 2)
tgemm(const __half* __restrict__ Ah, const __half* __restrict__ Al,
      const __half* __restrict__ B,
      int Kdim, int ostride,
      const float* __restrict__ bias,
      float* __restrict__ out0, float* __restrict__ out1,
      __half* __restrict__ obh, __half* __restrict__ obl)
{
    extern __shared__ char smem[];
    const uint32_t sb = smem_u32(smem);

    const int tid  = threadIdx.x;
    const int lane = tid & 31;
    const int wid  = tid >> 5;
    const int wm   = wid & 3;
    const int wn   = wid >> 2;
    const int m0 = blockIdx.y * 128;
    const int n0 = blockIdx.x * 128;

    const uint32_t a_off =
        (uint32_t)(wm * 32 + (lane & 15)) * TPAD + (uint32_t)((lane >> 4) * 16);
    const int p = lane >> 3;
    const uint32_t b_off =
        (uint32_t)(wn * 64 + (p >> 1) * 8 + (lane & 7)) * TPAD + (uint32_t)((p & 1) * 16);

    float acc[2][8][4];
#pragma unroll
    for (int i = 0; i < 2; ++i)
#pragma unroll
        for (int j = 0; j < 8; ++j)
#pragma unroll
            for (int q = 0; q < 4; ++q) acc[i][j][q] = 0.0f;

    const int NC = Kdim >> 6;

    load_chunk<SPLIT2>(Ah, Al, B, m0, n0, 0, Kdim, sb, tid, 0 < NC);

    for (int c = 0; c < NC; ++c) {
        asm volatile("cp.async.wait_group 0;" ::: "memory");
        __syncthreads();

        load_chunk<SPLIT2>(Ah, Al, B, m0, n0, (c + 1) * 64, Kdim,
                           sb + (uint32_t)((c + 1) & 1) * STAGE_B, tid, (c + 1) < NC);

        const uint32_t st = sb + (uint32_t)(c & 1) * STAGE_B;
        const uint32_t smAh = st;
        const uint32_t smAl = st + TILE_B;
        const uint32_t smB  = st + 2 * TILE_B;

#pragma unroll
        for (int k16 = 0; k16 < 4; ++k16) {
            const uint32_t kb = (uint32_t)(k16 * 32);
            uint32_t ah[2][4], al[2][4], bf[4][4];
#pragma unroll
            for (int mt = 0; mt < 2; ++mt) {
                ldsm4(ah[mt], smAh + kb + a_off + (uint32_t)(mt * 16 * TPAD));
                if (SPLIT2)
                    ldsm4(al[mt], smAl + kb + a_off + (uint32_t)(mt * 16 * TPAD));
            }
#pragma unroll
            for (int p2 = 0; p2 < 4; ++p2)
                ldsm4(bf[p2], smB + kb + b_off + (uint32_t)(p2 * 16 * TPAD));
#pragma unroll
            for (int mt = 0; mt < 2; ++mt)
#pragma unroll
                for (int nt = 0; nt < 8; ++nt)
                    mma16816h(acc[mt][nt], ah[mt], &bf[nt >> 1][(nt & 1) * 2]);
            if (SPLIT2) {
#pragma unroll
                for (int mt = 0; mt < 2; ++mt)
#pragma unroll
                    for (int nt = 0; nt < 8; ++nt)
                        mma16816h(acc[mt][nt], al[mt], &bf[nt >> 1][(nt & 1) * 2]);
            }
        }
    }

    __syncthreads();

    const int g2 = lane >> 2;
    const int c2 = (lane & 3) * 2;
#pragma unroll
    for (int mt = 0; mt < 2; ++mt) {
        const int r0 = m0 + wm * 32 + mt * 16 + g2;
#pragma unroll
        for (int nt = 0; nt < 8; ++nt) {
            const int col = n0 + wn * 64 + nt * 8 + c2;
            float v0 = acc[mt][nt][0], v1 = acc[mt][nt][1];
            float v2 = acc[mt][nt][2], v3 = acc[mt][nt][3];

            if (MODE == 0) {
                v0 = siluf(v0); v1 = siluf(v1); v2 = siluf(v2); v3 = siluf(v3);
                if (n0 < 2048) {
                    __half2 h0, l0, h1, l1;
                    h0.x = __float2half(v0); h0.y = __float2half(v1);
                    l0.x = __float2half(v0 - __half2float(h0.x));
                    l0.y = __float2half(v1 - __half2float(h0.y));
                    h1.x = __float2half(v2); h1.y = __float2half(v3);
                    l1.x = __float2half(v2 - __half2float(h1.x));
                    l1.y = __float2half(v3 - __half2float(h1.y));
                    *(__half2*)(obh + (size_t)r0 * 2048 + col)       = h0;
                    *(__half2*)(obl + (size_t)r0 * 2048 + col)       = l0;
                    *(__half2*)(obh + (size_t)(r0 + 8) * 2048 + col) = h1;
                    *(__half2*)(obl + (size_t)(r0 + 8) * 2048 + col) = l1;
                } else {
                    const int cs = col - 2048;
                    *(float2*)(out1 + (size_t)r0 * 2048 + cs)       = make_float2(v0, v1);
                    *(float2*)(out1 + (size_t)(r0 + 8) * 2048 + cs) = make_float2(v2, v3);
                }
            } else if (MODE == 1) {
                const float b0 = bias[col], b1 = bias[col + 1];
                *(float2*)(out0 + (size_t)r0 * ostride + col) =
                    make_float2(softplusf(v0 + b0), softplusf(v1 + b1));
                *(float2*)(out0 + (size_t)(r0 + 8) * ostride + col) =
                    make_float2(softplusf(v2 + b0), softplusf(v3 + b1));
            } else {
                *(float2*)(out0 + (size_t)r0 * ostride + col)       = make_float2(v0, v1);
                *(float2*)(out0 + (size_t)(r0 + 8) * ostride + col) = make_float2(v2, v3);
            }
        }
    }
}

// ---------------------------------------------------------------------------
// prep_all: weight transposes (fp32->fp16 [N][K]) + W_B/W_C float4 pack
// ---------------------------------------------------------------------------
__device__ __forceinline__ void transp_tile(
    const float* __restrict__ in, __half* __restrict__ oh,
    int K, int N, int nb, int kb, int tid)
{
    __shared__ float t[32][33];
    const int n0 = nb * 32, k0 = kb * 32;
    const int tx = tid & 31, ty = tid >> 5;
#pragma unroll
    for (int i = 0; i < 32; i += 8)
        t[ty + i][tx] = in[(size_t)(k0 + ty + i) * N + n0 + tx];
    __syncthreads();
#pragma unroll
    for (int i = 0; i < 32; i += 8) {
        const int n = n0 + ty + i, k = k0 + tx;
        oh[(size_t)n * K + k] = __float2half(t[tx][ty + i]);
    }
}

__global__ void __launch_bounds__(256)
prep_all(const float* __restrict__ W_in, const float* __restrict__ W_delta,
         const float* __restrict__ W_out,
         const float* __restrict__ WB, const float* __restrict__ WC,
         __half* __restrict__ Wi, __half* __restrict__ Wd, __half* __restrict__ Wo,
         float4* __restrict__ W4)
{
    const int blk = blockIdx.x;
    const int tid = threadIdx.x;
    if (blk < 4096) {
        transp_tile(W_in, Wi, DM, 2 * DI, blk & 127, blk >> 7, tid);
    } else if (blk < 8192) {
        const int t2 = blk - 4096;
        transp_tile(W_delta, Wd, DI, DI, t2 & 63, t2 >> 6, tid);
    } else if (blk < 10240) {
        const int t3 = blk - 8192;
        transp_tile(W_out, Wo, DI, DM, t3 & 31, t3 >> 5, tid);
    } else {
        const int base = (blk - 10240) * 256 + tid;
#pragma unroll
        for (int i = 0; i < 4; ++i) {
            const int id = base + i * 4096;
            const int k4 = id >> 5;
            const int n = id & 31;
            float4 v;
            if (n < DS) {
                v.x = WB[(k4 * 4 + 0) * DS + n];
                v.y = WB[(k4 * 4 + 1) * DS + n];
                v.z = WB[(k4 * 4 + 2) * DS + n];
                v.w = WB[(k4 * 4 + 3) * DS + n];
            } else {
                v.x = WC[(k4 * 4 + 0) * DS + n - DS];
                v.y = WC[(k4 * 4 + 1) * DS + n - DS];
                v.z = WC[(k4 * 4 + 2) * DS + n - DS];
                v.w = WC[(k4 * 4 + 3) * DS + n - DS];
            }
            W4[id] = v;
        }
    }
}

// x -> fp16
__global__ void __launch_bounds__(256)
conv_x_k(const float* __restrict__ x, __half* __restrict__ xh)
{
    const int i = blockIdx.x * 256 + threadIdx.x;
    float4 v = ((const float4*)x)[i];
    __half2 hh0, hh1;
    hh0.x = __float2half(v.x); hh0.y = __float2half(v.y);
    hh1.x = __float2half(v.z); hh1.y = __float2half(v.w);
    ((__half2*)xh)[2*i]   = hh0;
    ((__half2*)xh)[2*i+1] = hh1;
}

// ---------------------------------------------------------------------------
// Bm|Cm = U @ [W_B|W_C]; U reconstructed from fp16 hi+lo.
// ---------------------------------------------------------------------------
__global__ void __launch_bounds__(256)
bc_k(const __half* __restrict__ Uh, const __half* __restrict__ Ul,
     const float4* __restrict__ W4,
     float* __restrict__ BMo, float* __restrict__ CMo)
{
    const int tid = threadIdx.x;
    const int n = tid & 31;
    const int r = tid >> 5;
    const int m = blockIdx.x * 8 + r;

    const uint4* UH = (const uint4*)(Uh + (size_t)m * DI);
    const uint4* UL = (const uint4*)(Ul + (size_t)m * DI);
    float a0 = 0.f, a1 = 0.f, a2 = 0.f, a3 = 0.f;
#pragma unroll 4
    for (int k8 = 0; k8 < DI / 8; ++k8) {
        const uint4 hv = UH[k8];
        const uint4 lv = UL[k8];
        float2 f0 = __half22float2(*(const __half2*)&hv.x);
        float2 f1 = __half22float2(*(const __half2*)&hv.y);
        float2 f2 = __half22float2(*(const __half2*)&hv.z);
        float2 f3 = __half22float2(*(const __half2*)&hv.w);
        float2 e0 = __half22float2(*(const __half2*)&lv.x);
        float2 e1 = __half22float2(*(const __half2*)&lv.y);
        float2 e2 = __half22float2(*(const __half2*)&lv.z);
        float2 e3 = __half22float2(*(const __half2*)&lv.w);
        const float4 w0 = W4[(k8 * 2) * 32 + n];
        const float4 w1 = W4[(k8 * 2 + 1) * 32 + n];
        a0 = fmaf(f0.x + e0.x, w0.x, a0);
        a1 = fmaf(f0.y + e0.y, w0.y, a1);
        a2 = fmaf(f1.x + e1.x, w0.z, a2);
        a3 = fmaf(f1.y + e1.y, w0.w, a3);
        a0 = fmaf(f2.x + e2.x, w1.x, a0);
        a1 = fmaf(f2.y + e2.y, w1.y, a1);
        a2 = fmaf(f3.x + e3.x, w1.z, a2);
        a3 = fmaf(f3.y + e3.y, w1.w, a3);
    }
    const float acc = (a0 + a1) + (a2 + a3);
    if (n < DS) BMo[(size_t)m * DS + n] = acc;
    else        CMo[(size_t)m * DS + (n - DS)] = acc;
}

// ---------------------------------------------------------------------------
// Chunked scan (phases A/B/C). u reconstructed from Uh+Ul.
// ---------------------------------------------------------------------------
__device__ __forceinline__ float loadU(const __half* Uh, const __half* Ul, size_t i) {
    return __half2float(Uh[i]) + __half2float(Ul[i]);
}

__global__ void __launch_bounds__(64)
scanA(const float* __restrict__ DEL,
      const __half* __restrict__ Uh, const __half* __restrict__ Ul,
      const float* __restrict__ BMi, const float* __restrict__ Alog,
      float4* __restrict__ P4, float4* __restrict__ Q4)
{
    const int c = blockIdx.y;
    const int tid = threadIdx.x;
    const int g = blockIdx.x * 16 + (tid >> 2);
    const int b = g >> 11;
    const int d = g & (DI - 1);
    const int sub = tid & 3;

    const float A0 = -__expf(Alog[d * DS + sub * 4 + 0]);
    const float A1 = -__expf(Alog[d * DS + sub * 4 + 1]);
    const float A2 = -__expf(Alog[d * DS + sub * 4 + 2]);
    const float A3 = -__expf(Alog[d * DS + sub * 4 + 3]);
    const float d10 = A1 - A0;
    const bool uni = (fabsf((A2 - A1) - d10) <= 1e-4f * fabsf(d10) + 1e-20f) &&
                     (fabsf((A3 - A2) - d10) <= 1e-4f * fabsf(d10) + 1e-20f);

    float4 P = make_float4(1.f, 1.f, 1.f, 1.f);
    float4 q = make_float4(0.f, 0.f, 0.f, 0.f);

    size_t xbase = ((size_t)b * Lseq + (size_t)c * TL) * DI + d;
    size_t rbase = ((size_t)b * Lseq + (size_t)c * TL) * DS + sub * 4;

#pragma unroll 4
    for (int t = 0; t < TL; ++t) {
        const float delta = DEL[xbase];
        const float uu    = loadU(Uh, Ul, xbase);
        const float4 Bv = *(const float4*)(BMi + rbase);

        float a0, a1, a2, a3;
        if (uni) {
            a0 = __expf(delta * A0);
            const float rr = __expf(delta * d10);
            a1 = a0 * rr; a2 = a1 * rr; a3 = a2 * rr;
        } else {
            a0 = __expf(delta * A0); a1 = __expf(delta * A1);
            a2 = __expf(delta * A2); a3 = __expf(delta * A3);
        }
        const float db = delta * uu;
        q.x = fmaf(a0, q.x, db * Bv.x);
        q.y = fmaf(a1, q.y, db * Bv.y);
        q.z = fmaf(a2, q.z, db * Bv.z);
        q.w = fmaf(a3, q.w, db * Bv.w);
        P.x *= a0; P.y *= a1; P.z *= a2; P.w *= a3;

        xbase += DI;
        rbase += DS;
    }
    const int idx = (((c * 2 + b) * DI) + d) * 4 + sub;
    P4[idx] = P;
    Q4[idx] = q;
}

__global__ void __launch_bounds__(256)
scanB(const float4* __restrict__ P4, const float4* __restrict__ Q4,
      float4* __restrict__ H4)
{
    const int gs = blockIdx.x * 256 + threadIdx.x;
    const int g = gs >> 2;
    const int sub = gs & 3;
    const int b = g >> 11;
    const int d = g & (DI - 1);

    float4 h = make_float4(0.f, 0.f, 0.f, 0.f);
#pragma unroll
    for (int c = 0; c < CH; ++c) {
        const int idx = (((c * 2 + b) * DI) + d) * 4 + sub;
        H4[idx] = h;
        const float4 P = P4[idx];
        const float4 q = Q4[idx];
        h.x = fmaf(P.x, h.x, q.x);
        h.y = fmaf(P.y, h.y, q.y);
        h.z = fmaf(P.z, h.z, q.z);
        h.w = fmaf(P.w, h.w, q.w);
    }
}

__global__ void __launch_bounds__(64)
scanC(const float* __restrict__ DEL,
      const __half* __restrict__ Uh, const __half* __restrict__ Ul,
      const float* __restrict__ S,
      const float* __restrict__ BMi, const float* __restrict__ CMi,
      const float* __restrict__ Alog, const float* __restrict__ Dp,
      const float4* __restrict__ H4,
      __half* __restrict__ Yh)
{
    const int c = blockIdx.y;
    const int tid = threadIdx.x;
    const int g = blockIdx.x * 16 + (tid >> 2);
    const int b = g >> 11;
    const int d = g & (DI - 1);
    const int sub = tid & 3;

    const float A0 = -__expf(Alog[d * DS + sub * 4 + 0]);
    const float A1 = -__expf(Alog[d * DS + sub * 4 + 1]);
    const float A2 = -__expf(Alog[d * DS + sub * 4 + 2]);
    const float A3 = -__expf(Alog[d * DS + sub * 4 + 3]);
    const float d10 = A1 - A0;
    const bool uni = (fabsf((A2 - A1) - d10) <= 1e-4f * fabsf(d10) + 1e-20f) &&
                     (fabsf((A3 - A2) - d10) <= 1e-4f * fabsf(d10) + 1e-20f);
    const float Dd = Dp[d];

    const int idx = (((c * 2 + b) * DI) + d) * 4 + sub;
    float4 h = H4[idx];

    size_t xbase = ((size_t)b * Lseq + (size_t)c * TL) * DI + d;
    size_t rbase = ((size_t)b * Lseq + (size_t)c * TL) * DS + sub * 4;

#pragma unroll 4
    for (int t = 0; t < TL; ++t) {
        const float delta = DEL[xbase];
        const float uu    = loadU(Uh, Ul, xbase);
        const float4 Bv = *(const float4*)(BMi + rbase);
        const float4 Cv = *(const float4*)(CMi + rbase);

        float a0, a1, a2, a3;
        if (uni) {
            a0 = __expf(delta * A0);
            const float rr = __expf(delta * d10);
            a1 = a0 * rr; a2 = a1 * rr; a3 = a2 * rr;
        } else {
            a0 = __expf(delta * A0); a1 = __expf(delta * A1);
            a2 = __expf(delta * A2); a3 = __expf(delta * A3);
        }
        const float db = delta * uu;
        h.x = fmaf(a0, h.x, db * Bv.x);
        h.y = fmaf(a1, h.y, db * Bv.y);
        h.z = fmaf(a2, h.z, db * Bv.z);
        h.w = fmaf(a3, h.w, db * Bv.w);

        float ps = h.x * Cv.x;
        ps = fmaf(h.y, Cv.y, ps);
        ps = fmaf(h.z, Cv.z, ps);
        ps = fmaf(h.w, Cv.w, ps);
        ps += __shfl_xor_sync(0xffffffffu, ps, 1);
        ps += __shfl_xor_sync(0xffffffffu, ps, 2);

        if (sub == 0) {
            const float yv = (ps + uu * Dd) * S[xbase];
            Yh[xbase] = __float2half(yv);
        }
        xbase += DI;
        rbase += DS;
    }
}

// ---------------------------------------------------------------------------
extern "C" void kernel_launch(void* const* d_in, const int* in_sizes, int n_in,
                              void* d_out, int out_size)
{
    const float* x       = (const float*)d_in[0];
    const float* W_in    = (const float*)d_in[1];
    const float* W_delta = (const float*)d_in[2];
    const float* b_delta = (const float*)d_in[3];
    const float* W_B     = (const float*)d_in[4];
    const float* W_C     = (const float*)d_in[5];
    const float* A_log   = (const float*)d_in[6];
    const float* D_param = (const float*)d_in[7];
    const float* W_out   = (const float*)d_in[8];
    float* out = (float*)d_out;

    float *pS, *pDel, *pBM, *pCM;
    __half *pUh, *pUl, *pYh, *pxh, *pWi, *pWd, *pWo;
    float4 *pW4, *pP4, *pQ4, *pH4;
    cudaGetSymbolAddress((void**)&pS,   g_S);
    cudaGetSymbolAddress((void**)&pDel, g_DELTA);
    cudaGetSymbolAddress((void**)&pBM,  g_BM);
    cudaGetSymbolAddress((void**)&pCM,  g_CM);
    cudaGetSymbolAddress((void**)&pUh,  g_Uh);
    cudaGetSymbolAddress((void**)&pUl,  g_Ul);
    cudaGetSymbolAddress((void**)&pYh,  g_Yh);
    cudaGetSymbolAddress((void**)&pxh,  g_xh);
    cudaGetSymbolAddress((void**)&pWi,  g_WinT);
    cudaGetSymbolAddress((void**)&pWd,  g_WdT);
    cudaGetSymbolAddress((void**)&pWo,  g_WoT);
    cudaGetSymbolAddress((void**)&pW4,  g_W4);
    cudaGetSymbolAddress((void**)&pP4,  g_P4);
    cudaGetSymbolAddress((void**)&pQ4,  g_Q4);
    cudaGetSymbolAddress((void**)&pH4,  g_H4);

    cudaFuncSetAttribute((const void*)tgemm<0, false>, cudaFuncAttributeMaxDynamicSharedMemorySize, SMEM_TOT);
    cudaFuncSetAttribute((const void*)tgemm<1, true>,  cudaFuncAttributeMaxDynamicSharedMemorySize, SMEM_TOT);
    cudaFuncSetAttribute((const void*)tgemm<2, false>, cudaFuncAttributeMaxDynamicSharedMemorySize, SMEM_TOT);

    // Order: prep(1) conv(2) tgemm0(3) bc(4 <- ncu slot) tgemm1(5)
    //        scanA(6) scanB(7) scanC(8) tgemm2(9)
    prep_all<<<10256, 256>>>(W_in, W_delta, W_out, W_B, W_C, pWi, pWd, pWo, pW4);
    conv_x_k<<<Mrows * DM / 1024, 256>>>(x, pxh);

    // 1) x @ W_in -> U (silu, fp16 hi/lo) | S (silu)
    tgemm<0, false><<<dim3(2 * DI / 128, Mrows / 128), 256, SMEM_TOT>>>(
        pxh, pxh, pWi, DM, 2048, nullptr, nullptr, pS, pUh, pUl);

    // 2) Bm, Cm (profiled this round)
    bc_k<<<Mrows / 8, 256>>>(pUh, pUl, pW4, pBM, pCM);

    // 3) DELTA = softplus(U @ W_delta + b)   [2-term U]
    tgemm<1, true><<<dim3(DI / 128, Mrows / 128), 256, SMEM_TOT>>>(
        pUh, pUl, pWd, DI, DI, b_delta, pDel, nullptr, nullptr, nullptr);

    // 4) chunked selective scan -> Y (fp16, single term)
    scanA<<<dim3(256, CH), 64>>>(pDel, pUh, pUl, pBM, A_log, pP4, pQ4);
    scanB<<<64, 256>>>(pP4, pQ4, pH4);
    scanC<<<dim3(256, CH), 64>>>(pDel, pUh, pUl, pS, pBM, pCM, A_log, D_param,
                                 pH4, pYh);

    // 5) out = Y @ W_out   [single-term Y]
    tgemm<2, false><<<dim3(DM / 128, Mrows / 128), 256, SMEM_TOT>>>(
        pYh, pYh, pWo, DI, DM, nullptr, out, nullptr, nullptr, nullptr);
}

// round 12
// speedup vs baseline: 2.3664x; 1.1089x over previous
#include <cuda_runtime.h>
#include <cuda_fp16.h>
#include <cstdint>

#define DM 1024
#define DI 2048
#define DS 16
#define Mrows 4096
#define Lseq 2048
#define CH 16      // chunks
#define TL 128     // timesteps per chunk
#define ND 2176    // padded N for fused delta+B+C GEMM (17 tiles of 128)

// ---------------- scratch (device globals; allocation-free) ----------------
__device__ float g_S[Mrows * DI];
__device__ float g_DELTA[Mrows * DI];
__device__ float g_BC[Mrows * 32];         // [m][0..15]=Bm, [16..31]=Cm
__device__ __half g_Uh[Mrows * DI], g_Ul[Mrows * DI];
__device__ __half g_Yh[Mrows * DI];
__device__ __half g_xh[Mrows * DM];
__device__ __half g_WinT[2 * DI * DM];
__device__ __half g_WdT[ND * DI];          // rows: 0..2047 Wd^T, 2048..2079 WB^T|WC^T, rest 0
__device__ __half g_WoT[DM * DI];
__device__ float4 g_P4[CH * 2 * DI * 4];   // per-chunk decay products
__device__ float4 g_Q4[CH * 2 * DI * 4];   // per-chunk partial states
__device__ float4 g_H4[CH * 2 * DI * 4];   // chunk entry states

// ---------------- helpers ----------------
__device__ __forceinline__ float siluf(float x) { return x / (1.0f + __expf(-x)); }
__device__ __forceinline__ float softplusf(float x) {
    return (x > 20.0f) ? x : log1pf(__expf(x));
}
__device__ __forceinline__ uint32_t smem_u32(const void* p) {
    uint32_t a;
    asm("{ .reg .u64 t; cvta.to.shared.u64 t, %1; cvt.u32.u64 %0, t; }" : "=r"(a) : "l"(p));
    return a;
}
__device__ __forceinline__ void cpa16(uint32_t s, const void* g) {
    asm volatile("cp.async.cg.shared.global [%0], [%1], 16;" :: "r"(s), "l"(g));
}
__device__ __forceinline__ void cpa_commit() { asm volatile("cp.async.commit_group;"); }

__device__ __forceinline__ void ldsm4(uint32_t* r, uint32_t addr) {
    asm volatile("ldmatrix.sync.aligned.m8n8.x4.shared.b16 {%0,%1,%2,%3}, [%4];"
                 : "=r"(r[0]), "=r"(r[1]), "=r"(r[2]), "=r"(r[3]) : "r"(addr));
}
__device__ __forceinline__ void mma16816h(float* d, const uint32_t* a, const uint32_t* b) {
    asm volatile(
        "mma.sync.aligned.m16n8k16.row.col.f32.f16.f16.f32 "
        "{%0,%1,%2,%3}, {%4,%5,%6,%7}, {%8,%9}, {%0,%1,%2,%3};\n"
        : "+f"(d[0]), "+f"(d[1]), "+f"(d[2]), "+f"(d[3])
        : "r"(a[0]), "r"(a[1]), "r"(a[2]), "r"(a[3]), "r"(b[0]), "r"(b[1]));
}

#define TPAD 144
#define TILE_B (128 * TPAD)
#define STAGE_B (3 * TILE_B)
#define NSTAGE 2
#define SMEM_TOT (NSTAGE * STAGE_B)  // 110592 -> 2 CTAs/SM

template <bool SPLIT2>
__device__ __forceinline__ void load_chunk(
    const __half* __restrict__ Ah, const __half* __restrict__ Al,
    const __half* __restrict__ B,
    int m0, int n0, int kc, int Kdim, uint32_t sb, int tid, bool active)
{
    if (active) {
#pragma unroll
        for (int j = 0; j < 12; ++j) {
            const int g = j * 256 + tid;
            const int tile = g >> 10;
            if (!SPLIT2 && tile == 1) continue;
            const int w = g & 1023;
            const int row = w >> 3;
            const int col16 = w & 7;
            const __half* base = (tile == 0) ? Ah : (tile == 1) ? Al : B;
            const int r0 = (tile == 2) ? n0 : m0;
            const __half* src = base + (size_t)(r0 + row) * Kdim + kc + col16 * 8;
            cpa16(sb + (uint32_t)(tile * TILE_B + row * TPAD + col16 * 16),
                  (const void*)src);
        }
    }
    cpa_commit();
}

// ---------------------------------------------------------------------------
// HMMA fp16 GEMM: C[M,N] = A[M,K] * B[N,K]^T  (fp32 accum)
// SPLIT2: C ~= Ah*B + Al*B ; else C = Ah*B.
// MODE 0: n0<2048 -> U=silu -> (obh,obl) fp16 split; else S=silu -> out1
// MODE 1: col<2048 -> softplus(c+bias[col]) -> out0(DELTA);
//         2048<=col<2080 -> plain -> out1 (BC, stride 32)
// MODE 2: plain -> out0
// ---------------------------------------------------------------------------
template <int MODE, bool SPLIT2>
__global__ void __launch_bounds__(256, 2)
tgemm(const __half* __restrict__ Ah, const __half* __restrict__ Al,
      const __half* __restrict__ B,
      int Kdim, int ostride,
      const float* __restrict__ bias,
      float* __restrict__ out0, float* __restrict__ out1,
      __half* __restrict__ obh, __half* __restrict__ obl)
{
    extern __shared__ char smem[];
    const uint32_t sb = smem_u32(smem);

    const int tid  = threadIdx.x;
    const int lane = tid & 31;
    const int wid  = tid >> 5;
    const int wm   = wid & 3;
    const int wn   = wid >> 2;
    const int m0 = blockIdx.y * 128;
    const int n0 = blockIdx.x * 128;

    const uint32_t a_off =
        (uint32_t)(wm * 32 + (lane & 15)) * TPAD + (uint32_t)((lane >> 4) * 16);
    const int p = lane >> 3;
    const uint32_t b_off =
        (uint32_t)(wn * 64 + (p >> 1) * 8 + (lane & 7)) * TPAD + (uint32_t)((p & 1) * 16);

    float acc[2][8][4];
#pragma unroll
    for (int i = 0; i < 2; ++i)
#pragma unroll
        for (int j = 0; j < 8; ++j)
#pragma unroll
            for (int q = 0; q < 4; ++q) acc[i][j][q] = 0.0f;

    const int NC = Kdim >> 6;

    load_chunk<SPLIT2>(Ah, Al, B, m0, n0, 0, Kdim, sb, tid, 0 < NC);

    for (int c = 0; c < NC; ++c) {
        asm volatile("cp.async.wait_group 0;" ::: "memory");
        __syncthreads();

        load_chunk<SPLIT2>(Ah, Al, B, m0, n0, (c + 1) * 64, Kdim,
                           sb + (uint32_t)((c + 1) & 1) * STAGE_B, tid, (c + 1) < NC);

        const uint32_t st = sb + (uint32_t)(c & 1) * STAGE_B;
        const uint32_t smAh = st;
        const uint32_t smAl = st + TILE_B;
        const uint32_t smB  = st + 2 * TILE_B;

#pragma unroll
        for (int k16 = 0; k16 < 4; ++k16) {
            const uint32_t kb = (uint32_t)(k16 * 32);
            uint32_t ah[2][4], al[2][4], bf[4][4];
#pragma unroll
            for (int mt = 0; mt < 2; ++mt) {
                ldsm4(ah[mt], smAh + kb + a_off + (uint32_t)(mt * 16 * TPAD));
                if (SPLIT2)
                    ldsm4(al[mt], smAl + kb + a_off + (uint32_t)(mt * 16 * TPAD));
            }
#pragma unroll
            for (int p2 = 0; p2 < 4; ++p2)
                ldsm4(bf[p2], smB + kb + b_off + (uint32_t)(p2 * 16 * TPAD));
#pragma unroll
            for (int mt = 0; mt < 2; ++mt)
#pragma unroll
                for (int nt = 0; nt < 8; ++nt)
                    mma16816h(acc[mt][nt], ah[mt], &bf[nt >> 1][(nt & 1) * 2]);
            if (SPLIT2) {
#pragma unroll
                for (int mt = 0; mt < 2; ++mt)
#pragma unroll
                    for (int nt = 0; nt < 8; ++nt)
                        mma16816h(acc[mt][nt], al[mt], &bf[nt >> 1][(nt & 1) * 2]);
            }
        }
    }

    __syncthreads();

    const int g2 = lane >> 2;
    const int c2 = (lane & 3) * 2;
#pragma unroll
    for (int mt = 0; mt < 2; ++mt) {
        const int r0 = m0 + wm * 32 + mt * 16 + g2;
#pragma unroll
        for (int nt = 0; nt < 8; ++nt) {
            const int col = n0 + wn * 64 + nt * 8 + c2;
            float v0 = acc[mt][nt][0], v1 = acc[mt][nt][1];
            float v2 = acc[mt][nt][2], v3 = acc[mt][nt][3];

            if (MODE == 0) {
                v0 = siluf(v0); v1 = siluf(v1); v2 = siluf(v2); v3 = siluf(v3);
                if (n0 < 2048) {
                    __half2 h0, l0, h1, l1;
                    h0.x = __float2half(v0); h0.y = __float2half(v1);
                    l0.x = __float2half(v0 - __half2float(h0.x));
                    l0.y = __float2half(v1 - __half2float(h0.y));
                    h1.x = __float2half(v2); h1.y = __float2half(v3);
                    l1.x = __float2half(v2 - __half2float(h1.x));
                    l1.y = __float2half(v3 - __half2float(h1.y));
                    *(__half2*)(obh + (size_t)r0 * 2048 + col)       = h0;
                    *(__half2*)(obl + (size_t)r0 * 2048 + col)       = l0;
                    *(__half2*)(obh + (size_t)(r0 + 8) * 2048 + col) = h1;
                    *(__half2*)(obl + (size_t)(r0 + 8) * 2048 + col) = l1;
                } else {
                    const int cs = col - 2048;
                    *(float2*)(out1 + (size_t)r0 * 2048 + cs)       = make_float2(v0, v1);
                    *(float2*)(out1 + (size_t)(r0 + 8) * 2048 + cs) = make_float2(v2, v3);
                }
            } else if (MODE == 1) {
                if (col < 2048) {
                    const float b0 = bias[col], b1 = bias[col + 1];
                    *(float2*)(out0 + (size_t)r0 * ostride + col) =
                        make_float2(softplusf(v0 + b0), softplusf(v1 + b1));
                    *(float2*)(out0 + (size_t)(r0 + 8) * ostride + col) =
                        make_float2(softplusf(v2 + b0), softplusf(v3 + b1));
                } else if (col < 2080) {
                    const int n = col - 2048;
                    *(float2*)(out1 + (size_t)r0 * 32 + n)       = make_float2(v0, v1);
                    *(float2*)(out1 + (size_t)(r0 + 8) * 32 + n) = make_float2(v2, v3);
                }
            } else {
                *(float2*)(out0 + (size_t)r0 * ostride + col)       = make_float2(v0, v1);
                *(float2*)(out0 + (size_t)(r0 + 8) * ostride + col) = make_float2(v2, v3);
            }
        }
    }
}

// ---------------------------------------------------------------------------
// prep_all: weight transposes (fp32->fp16 [N][K]) + W_B/W_C rows + zero pad
// blocks: [0,4096) Win ; [4096,8192) Wd ; [8192,10240) Wo ;
//         [10240,10304) WB/WC rows ; [10304,10496) zero pad rows
// ---------------------------------------------------------------------------
__device__ __forceinline__ void transp_tile(
    const float* __restrict__ in, __half* __restrict__ oh,
    int K, int N, int nb, int kb, int tid)
{
    __shared__ float t[32][33];
    const int n0 = nb * 32, k0 = kb * 32;
    const int tx = tid & 31, ty = tid >> 5;
#pragma unroll
    for (int i = 0; i < 32; i += 8)
        t[ty + i][tx] = in[(size_t)(k0 + ty + i) * N + n0 + tx];
    __syncthreads();
#pragma unroll
    for (int i = 0; i < 32; i += 8) {
        const int n = n0 + ty + i, k = k0 + tx;
        oh[(size_t)n * K + k] = __float2half(t[tx][ty + i]);
    }
}

__global__ void __launch_bounds__(256)
prep_all(const float* __restrict__ W_in, const float* __restrict__ W_delta,
         const float* __restrict__ W_out,
         const float* __restrict__ WB, const float* __restrict__ WC,
         __half* __restrict__ Wi, __half* __restrict__ Wd, __half* __restrict__ Wo)
{
    const int blk = blockIdx.x;
    const int tid = threadIdx.x;
    if (blk < 4096) {
        transp_tile(W_in, Wi, DM, 2 * DI, blk & 127, blk >> 7, tid);
    } else if (blk < 8192) {
        const int t2 = blk - 4096;
        transp_tile(W_delta, Wd, DI, DI, t2 & 63, t2 >> 6, tid);
    } else if (blk < 10240) {
        const int t3 = blk - 8192;
        transp_tile(W_out, Wo, DI, DM, t3 & 31, t3 >> 5, tid);
    } else if (blk < 10304) {
        // WB^T|WC^T into rows 2048..2079 of Wd: 32 rows x 2048 cols
        const int base = (blk - 10240) * 1024 + tid * 4;   // 0..65535 step 4
#pragma unroll
        for (int i = 0; i < 4; ++i) {
            const int id = base + i;                        // row-major [n][k]
            const int n = id >> 11;                         // 0..31
            const int k = id & 2047;
            const float v = (n < DS) ? WB[(size_t)k * DS + n]
                                     : WC[(size_t)k * DS + (n - DS)];
            Wd[(size_t)(2048 + n) * DI + k] = __float2half(v);
        }
    } else {
        // zero rows 2080..2175 (96 x 2048)
        const int base = (blk - 10304) * 1024 + tid * 4;    // 0..196607 step 4
        __half2 z; z.x = __float2half(0.f); z.y = __float2half(0.f);
        *(__half2*)(Wd + (size_t)2080 * DI + base)     = z;
        *(__half2*)(Wd + (size_t)2080 * DI + base + 2) = z;
    }
}

// x -> fp16
__global__ void __launch_bounds__(256)
conv_x_k(const float* __restrict__ x, __half* __restrict__ xh)
{
    const int i = blockIdx.x * 256 + threadIdx.x;
    float4 v = ((const float4*)x)[i];
    __half2 hh0, hh1;
    hh0.x = __float2half(v.x); hh0.y = __float2half(v.y);
    hh1.x = __float2half(v.z); hh1.y = __float2half(v.w);
    ((__half2*)xh)[2*i]   = hh0;
    ((__half2*)xh)[2*i+1] = hh1;
}

// ---------------------------------------------------------------------------
// Chunked scan (phases A/B/C). u reconstructed from Uh+Ul. BC combined [m][32].
// ---------------------------------------------------------------------------
__device__ __forceinline__ float loadU(const __half* Uh, const __half* Ul, size_t i) {
    return __half2float(Uh[i]) + __half2float(Ul[i]);
}

__global__ void __launch_bounds__(64)
scanA(const float* __restrict__ DEL,
      const __half* __restrict__ Uh, const __half* __restrict__ Ul,
      const float* __restrict__ BC, const float* __restrict__ Alog,
      float4* __restrict__ P4, float4* __restrict__ Q4)
{
    const int c = blockIdx.y;
    const int tid = threadIdx.x;
    const int g = blockIdx.x * 16 + (tid >> 2);
    const int b = g >> 11;
    const int d = g & (DI - 1);
    const int sub = tid & 3;

    const float A0 = -__expf(Alog[d * DS + sub * 4 + 0]);
    const float A1 = -__expf(Alog[d * DS + sub * 4 + 1]);
    const float A2 = -__expf(Alog[d * DS + sub * 4 + 2]);
    const float A3 = -__expf(Alog[d * DS + sub * 4 + 3]);
    const float d10 = A1 - A0;
    const bool uni = (fabsf((A2 - A1) - d10) <= 1e-4f * fabsf(d10) + 1e-20f) &&
                     (fabsf((A3 - A2) - d10) <= 1e-4f * fabsf(d10) + 1e-20f);

    float4 P = make_float4(1.f, 1.f, 1.f, 1.f);
    float4 q = make_float4(0.f, 0.f, 0.f, 0.f);

    size_t xbase = ((size_t)b * Lseq + (size_t)c * TL) * DI + d;
    size_t rbase = ((size_t)b * Lseq + (size_t)c * TL) * 32 + sub * 4;

#pragma unroll 4
    for (int t = 0; t < TL; ++t) {
        const float delta = DEL[xbase];
        const float uu    = loadU(Uh, Ul, xbase);
        const float4 Bv = *(const float4*)(BC + rbase);

        float a0, a1, a2, a3;
        if (uni) {
            a0 = __expf(delta * A0);
            const float rr = __expf(delta * d10);
            a1 = a0 * rr; a2 = a1 * rr; a3 = a2 * rr;
        } else {
            a0 = __expf(delta * A0); a1 = __expf(delta * A1);
            a2 = __expf(delta * A2); a3 = __expf(delta * A3);
        }
        const float db = delta * uu;
        q.x = fmaf(a0, q.x, db * Bv.x);
        q.y = fmaf(a1, q.y, db * Bv.y);
        q.z = fmaf(a2, q.z, db * Bv.z);
        q.w = fmaf(a3, q.w, db * Bv.w);
        P.x *= a0; P.y *= a1; P.z *= a2; P.w *= a3;

        xbase += DI;
        rbase += 32;
    }
    const int idx = (((c * 2 + b) * DI) + d) * 4 + sub;
    P4[idx] = P;
    Q4[idx] = q;
}

__global__ void __launch_bounds__(256)
scanB(const float4* __restrict__ P4, const float4* __restrict__ Q4,
      float4* __restrict__ H4)
{
    const int gs = blockIdx.x * 256 + threadIdx.x;
    const int g = gs >> 2;
    const int sub = gs & 3;
    const int b = g >> 11;
    const int d = g & (DI - 1);

    float4 h = make_float4(0.f, 0.f, 0.f, 0.f);
#pragma unroll
    for (int c = 0; c < CH; ++c) {
        const int idx = (((c * 2 + b) * DI) + d) * 4 + sub;
        H4[idx] = h;
        const float4 P = P4[idx];
        const float4 q = Q4[idx];
        h.x = fmaf(P.x, h.x, q.x);
        h.y = fmaf(P.y, h.y, q.y);
        h.z = fmaf(P.z, h.z, q.z);
        h.w = fmaf(P.w, h.w, q.w);
    }
}

__global__ void __launch_bounds__(64)
scanC(const float* __restrict__ DEL,
      const __half* __restrict__ Uh, const __half* __restrict__ Ul,
      const float* __restrict__ S,
      const float* __restrict__ BC,
      const float* __restrict__ Alog, const float* __restrict__ Dp,
      const float4* __restrict__ H4,
      __half* __restrict__ Yh)
{
    const int c = blockIdx.y;
    const int tid = threadIdx.x;
    const int g = blockIdx.x * 16 + (tid >> 2);
    const int b = g >> 11;
    const int d = g & (DI - 1);
    const int sub = tid & 3;

    const float A0 = -__expf(Alog[d * DS + sub * 4 + 0]);
    const float A1 = -__expf(Alog[d * DS + sub * 4 + 1]);
    const float A2 = -__expf(Alog[d * DS + sub * 4 + 2]);
    const float A3 = -__expf(Alog[d * DS + sub * 4 + 3]);
    const float d10 = A1 - A0;
    const bool uni = (fabsf((A2 - A1) - d10) <= 1e-4f * fabsf(d10) + 1e-20f) &&
                     (fabsf((A3 - A2) - d10) <= 1e-4f * fabsf(d10) + 1e-20f);
    const float Dd = Dp[d];

    const int idx = (((c * 2 + b) * DI) + d) * 4 + sub;
    float4 h = H4[idx];

    size_t xbase = ((size_t)b * Lseq + (size_t)c * TL) * DI + d;
    size_t rbase = ((size_t)b * Lseq + (size_t)c * TL) * 32 + sub * 4;

#pragma unroll 4
    for (int t = 0; t < TL; ++t) {
        const float delta = DEL[xbase];
        const float uu    = loadU(Uh, Ul, xbase);
        const float4 Bv = *(const float4*)(BC + rbase);
        const float4 Cv = *(const float4*)(BC + rbase + 16);

        float a0, a1, a2, a3;
        if (uni) {
            a0 = __expf(delta * A0);
            const float rr = __expf(delta * d10);
            a1 = a0 * rr; a2 = a1 * rr; a3 = a2 * rr;
        } else {
            a0 = __expf(delta * A0); a1 = __expf(delta * A1);
            a2 = __expf(delta * A2); a3 = __expf(delta * A3);
        }
        const float db = delta * uu;
        h.x = fmaf(a0, h.x, db * Bv.x);
        h.y = fmaf(a1, h.y, db * Bv.y);
        h.z = fmaf(a2, h.z, db * Bv.z);
        h.w = fmaf(a3, h.w, db * Bv.w);

        float ps = h.x * Cv.x;
        ps = fmaf(h.y, Cv.y, ps);
        ps = fmaf(h.z, Cv.z, ps);
        ps = fmaf(h.w, Cv.w, ps);
        ps += __shfl_xor_sync(0xffffffffu, ps, 1);
        ps += __shfl_xor_sync(0xffffffffu, ps, 2);

        if (sub == 0) {
            const float yv = (ps + uu * Dd) * S[xbase];
            Yh[xbase] = __float2half(yv);
        }
        xbase += DI;
        rbase += 32;
    }
}

// ---------------------------------------------------------------------------
extern "C" void kernel_launch(void* const* d_in, const int* in_sizes, int n_in,
                              void* d_out, int out_size)
{
    const float* x       = (const float*)d_in[0];
    const float* W_in    = (const float*)d_in[1];
    const float* W_delta = (const float*)d_in[2];
    const float* b_delta = (const float*)d_in[3];
    const float* W_B     = (const float*)d_in[4];
    const float* W_C     = (const float*)d_in[5];
    const float* A_log   = (const float*)d_in[6];
    const float* D_param = (const float*)d_in[7];
    const float* W_out   = (const float*)d_in[8];
    float* out = (float*)d_out;

    float *pS, *pDel, *pBC;
    __half *pUh, *pUl, *pYh, *pxh, *pWi, *pWd, *pWo;
    float4 *pP4, *pQ4, *pH4;
    cudaGetSymbolAddress((void**)&pS,   g_S);
    cudaGetSymbolAddress((void**)&pDel, g_DELTA);
    cudaGetSymbolAddress((void**)&pBC,  g_BC);
    cudaGetSymbolAddress((void**)&pUh,  g_Uh);
    cudaGetSymbolAddress((void**)&pUl,  g_Ul);
    cudaGetSymbolAddress((void**)&pYh,  g_Yh);
    cudaGetSymbolAddress((void**)&pxh,  g_xh);
    cudaGetSymbolAddress((void**)&pWi,  g_WinT);
    cudaGetSymbolAddress((void**)&pWd,  g_WdT);
    cudaGetSymbolAddress((void**)&pWo,  g_WoT);
    cudaGetSymbolAddress((void**)&pP4,  g_P4);
    cudaGetSymbolAddress((void**)&pQ4,  g_Q4);
    cudaGetSymbolAddress((void**)&pH4,  g_H4);

    cudaFuncSetAttribute((const void*)tgemm<0, false>, cudaFuncAttributeMaxDynamicSharedMemorySize, SMEM_TOT);
    cudaFuncSetAttribute((const void*)tgemm<1, true>,  cudaFuncAttributeMaxDynamicSharedMemorySize, SMEM_TOT);
    cudaFuncSetAttribute((const void*)tgemm<2, false>, cudaFuncAttributeMaxDynamicSharedMemorySize, SMEM_TOT);

    // Order: prep(1) conv(2) tgemm0(3) tgemm1(4 <- ncu slot)
    //        scanA(5) scanB(6) scanC(7) tgemm2(8)
    prep_all<<<10496, 256>>>(W_in, W_delta, W_out, W_B, W_C, pWi, pWd, pWo);
    conv_x_k<<<Mrows * DM / 1024, 256>>>(x, pxh);

    // 1) x @ W_in -> U (silu, fp16 hi/lo) | S (silu)
    tgemm<0, false><<<dim3(2 * DI / 128, Mrows / 128), 256, SMEM_TOT>>>(
        pxh, pxh, pWi, DM, 2048, nullptr, nullptr, pS, pUh, pUl);

    // 2+3) DELTA = softplus(U @ W_delta + b) fused with Bm|Cm = U @ [WB|WC]
    tgemm<1, true><<<dim3(ND / 128, Mrows / 128), 256, SMEM_TOT>>>(
        pUh, pUl, pWd, DI, DI, b_delta, pDel, pBC, nullptr, nullptr);

    // 4) chunked selective scan -> Y (fp16, single term)
    scanA<<<dim3(256, CH), 64>>>(pDel, pUh, pUl, pBC, A_log, pP4, pQ4);
    scanB<<<64, 256>>>(pP4, pQ4, pH4);
    scanC<<<dim3(256, CH), 64>>>(pDel, pUh, pUl, pS, pBC, A_log, D_param,
                                 pH4, pYh);

    // 5) out = Y @ W_out   [single-term Y]
    tgemm<2, false><<<dim3(DM / 128, Mrows / 128), 256, SMEM_TOT>>>(
        pYh, pYh, pWo, DI, DM, nullptr, out, nullptr, nullptr, nullptr);
}

// round 13
// speedup vs baseline: 2.5518x; 1.0784x over previous
#include <cuda_runtime.h>
#include <cuda_fp16.h>
#include <cstdint>

#define DM 1024
#define DI 2048
#define DS 16
#define Mrows 4096
#define Lseq 2048
#define CH 32      // chunks
#define TL 64      // timesteps per chunk
#define ND 2176    // padded N for fused delta+B+C GEMM (17 tiles of 128)

// ---------------- scratch (device globals; allocation-free) ----------------
__device__ __half g_Sh[Mrows * DI];
__device__ float g_DELTA[Mrows * DI];
__device__ float g_BC[Mrows * 32];         // [m][0..15]=Bm, [16..31]=Cm
__device__ __half g_Uh[Mrows * DI], g_Ul[Mrows * DI];
__device__ __half g_Yh[Mrows * DI];
__device__ __half g_xh[Mrows * DM];
__device__ __half g_WinT[2 * DI * DM];
__device__ __half g_WdT[ND * DI];          // rows: 0..2047 Wd^T, 2048..2079 WB^T|WC^T, rest 0
__device__ __half g_WoT[DM * DI];
__device__ float4 g_P4[CH * 2 * DI * 4];   // per-chunk decay products
__device__ float4 g_Q4[CH * 2 * DI * 4];   // per-chunk partial states
__device__ float4 g_H4[CH * 2 * DI * 4];   // chunk entry states

// ---------------- helpers ----------------
__device__ __forceinline__ float siluf(float x) { return x / (1.0f + __expf(-x)); }
__device__ __forceinline__ float softplusf(float x) {
    return (x > 20.0f) ? x : log1pf(__expf(x));
}
__device__ __forceinline__ uint32_t smem_u32(const void* p) {
    uint32_t a;
    asm("{ .reg .u64 t; cvta.to.shared.u64 t, %1; cvt.u32.u64 %0, t; }" : "=r"(a) : "l"(p));
    return a;
}
__device__ __forceinline__ void cpa16(uint32_t s, const void* g) {
    asm volatile("cp.async.cg.shared.global [%0], [%1], 16;" :: "r"(s), "l"(g));
}
__device__ __forceinline__ void cpa_commit() { asm volatile("cp.async.commit_group;"); }

__device__ __forceinline__ void ldsm4(uint32_t* r, uint32_t addr) {
    asm volatile("ldmatrix.sync.aligned.m8n8.x4.shared.b16 {%0,%1,%2,%3}, [%4];"
                 : "=r"(r[0]), "=r"(r[1]), "=r"(r[2]), "=r"(r[3]) : "r"(addr));
}
__device__ __forceinline__ void mma16816h(float* d, const uint32_t* a, const uint32_t* b) {
    asm volatile(
        "mma.sync.aligned.m16n8k16.row.col.f32.f16.f16.f32 "
        "{%0,%1,%2,%3}, {%4,%5,%6,%7}, {%8,%9}, {%0,%1,%2,%3};\n"
        : "+f"(d[0]), "+f"(d[1]), "+f"(d[2]), "+f"(d[3])
        : "r"(a[0]), "r"(a[1]), "r"(a[2]), "r"(a[3]), "r"(b[0]), "r"(b[1]));
}

#define TPAD 144
#define TILE_B (128 * TPAD)
#define STAGE_B (3 * TILE_B)
#define NSTAGE 2
#define SMEM_TOT (NSTAGE * STAGE_B)  // 110592 -> 2 CTAs/SM

template <bool SPLIT2>
__device__ __forceinline__ void load_chunk(
    const __half* __restrict__ Ah, const __half* __restrict__ Al,
    const __half* __restrict__ B,
    int m0, int n0, int kc, int Kdim, uint32_t sb, int tid, bool active)
{
    if (active) {
#pragma unroll
        for (int j = 0; j < 12; ++j) {
            const int g = j * 256 + tid;
            const int tile = g >> 10;
            if (!SPLIT2 && tile == 1) continue;
            const int w = g & 1023;
            const int row = w >> 3;
            const int col16 = w & 7;
            const __half* base = (tile == 0) ? Ah : (tile == 1) ? Al : B;
            const int r0 = (tile == 2) ? n0 : m0;
            const __half* src = base + (size_t)(r0 + row) * Kdim + kc + col16 * 8;
            cpa16(sb + (uint32_t)(tile * TILE_B + row * TPAD + col16 * 16),
                  (const void*)src);
        }
    }
    cpa_commit();
}

// ---------------------------------------------------------------------------
// HMMA fp16 GEMM: C[M,N] = A[M,K] * B[N,K]^T  (fp32 accum)
// SPLIT2: C ~= Ah*B + Al*B ; else C = Ah*B.
// MODE 0: n0<2048 -> U=silu -> (obh,obl) fp16 split; else S=silu -> obs (fp16)
// MODE 1: col<2048 -> softplus(c+bias) -> out0(DELTA); col in [2048,2080) -> BC
// MODE 2: plain -> out0
// ---------------------------------------------------------------------------
template <int MODE, bool SPLIT2>
__global__ void __launch_bounds__(256, 2)
tgemm(const __half* __restrict__ Ah, const __half* __restrict__ Al,
      const __half* __restrict__ B,
      int Kdim, int ostride,
      const float* __restrict__ bias,
      float* __restrict__ out0, float* __restrict__ out1,
      __half* __restrict__ obh, __half* __restrict__ obl,
      __half* __restrict__ obs)
{
    extern __shared__ char smem[];
    const uint32_t sb = smem_u32(smem);

    const int tid  = threadIdx.x;
    const int lane = tid & 31;
    const int wid  = tid >> 5;
    const int wm   = wid & 3;
    const int wn   = wid >> 2;
    const int m0 = blockIdx.y * 128;
    const int n0 = blockIdx.x * 128;

    const uint32_t a_off =
        (uint32_t)(wm * 32 + (lane & 15)) * TPAD + (uint32_t)((lane >> 4) * 16);
    const int p = lane >> 3;
    const uint32_t b_off =
        (uint32_t)(wn * 64 + (p >> 1) * 8 + (lane & 7)) * TPAD + (uint32_t)((p & 1) * 16);

    float acc[2][8][4];
#pragma unroll
    for (int i = 0; i < 2; ++i)
#pragma unroll
        for (int j = 0; j < 8; ++j)
#pragma unroll
            for (int q = 0; q < 4; ++q) acc[i][j][q] = 0.0f;

    const int NC = Kdim >> 6;

    load_chunk<SPLIT2>(Ah, Al, B, m0, n0, 0, Kdim, sb, tid, 0 < NC);

    for (int c = 0; c < NC; ++c) {
        asm volatile("cp.async.wait_group 0;" ::: "memory");
        __syncthreads();

        load_chunk<SPLIT2>(Ah, Al, B, m0, n0, (c + 1) * 64, Kdim,
                           sb + (uint32_t)((c + 1) & 1) * STAGE_B, tid, (c + 1) < NC);

        const uint32_t st = sb + (uint32_t)(c & 1) * STAGE_B;
        const uint32_t smAh = st;
        const uint32_t smAl = st + TILE_B;
        const uint32_t smB  = st + 2 * TILE_B;

#pragma unroll
        for (int k16 = 0; k16 < 4; ++k16) {
            const uint32_t kb = (uint32_t)(k16 * 32);
            uint32_t ah[2][4], al[2][4], bf[4][4];
#pragma unroll
            for (int mt = 0; mt < 2; ++mt) {
                ldsm4(ah[mt], smAh + kb + a_off + (uint32_t)(mt * 16 * TPAD));
                if (SPLIT2)
                    ldsm4(al[mt], smAl + kb + a_off + (uint32_t)(mt * 16 * TPAD));
            }
#pragma unroll
            for (int p2 = 0; p2 < 4; ++p2)
                ldsm4(bf[p2], smB + kb + b_off + (uint32_t)(p2 * 16 * TPAD));
#pragma unroll
            for (int mt = 0; mt < 2; ++mt)
#pragma unroll
                for (int nt = 0; nt < 8; ++nt)
                    mma16816h(acc[mt][nt], ah[mt], &bf[nt >> 1][(nt & 1) * 2]);
            if (SPLIT2) {
#pragma unroll
                for (int mt = 0; mt < 2; ++mt)
#pragma unroll
                    for (int nt = 0; nt < 8; ++nt)
                        mma16816h(acc[mt][nt], al[mt], &bf[nt >> 1][(nt & 1) * 2]);
            }
        }
    }

    __syncthreads();

    const int g2 = lane >> 2;
    const int c2 = (lane & 3) * 2;
#pragma unroll
    for (int mt = 0; mt < 2; ++mt) {
        const int r0 = m0 + wm * 32 + mt * 16 + g2;
#pragma unroll
        for (int nt = 0; nt < 8; ++nt) {
            const int col = n0 + wn * 64 + nt * 8 + c2;
            float v0 = acc[mt][nt][0], v1 = acc[mt][nt][1];
            float v2 = acc[mt][nt][2], v3 = acc[mt][nt][3];

            if (MODE == 0) {
                v0 = siluf(v0); v1 = siluf(v1); v2 = siluf(v2); v3 = siluf(v3);
                if (n0 < 2048) {
                    __half2 h0, l0, h1, l1;
                    h0.x = __float2half(v0); h0.y = __float2half(v1);
                    l0.x = __float2half(v0 - __half2float(h0.x));
                    l0.y = __float2half(v1 - __half2float(h0.y));
                    h1.x = __float2half(v2); h1.y = __float2half(v3);
                    l1.x = __float2half(v2 - __half2float(h1.x));
                    l1.y = __float2half(v3 - __half2float(h1.y));
                    *(__half2*)(obh + (size_t)r0 * 2048 + col)       = h0;
                    *(__half2*)(obl + (size_t)r0 * 2048 + col)       = l0;
                    *(__half2*)(obh + (size_t)(r0 + 8) * 2048 + col) = h1;
                    *(__half2*)(obl + (size_t)(r0 + 8) * 2048 + col) = l1;
                } else {
                    const int cs = col - 2048;
                    __half2 s0, s1;
                    s0.x = __float2half(v0); s0.y = __float2half(v1);
                    s1.x = __float2half(v2); s1.y = __float2half(v3);
                    *(__half2*)(obs + (size_t)r0 * 2048 + cs)       = s0;
                    *(__half2*)(obs + (size_t)(r0 + 8) * 2048 + cs) = s1;
                }
            } else if (MODE == 1) {
                if (col < 2048) {
                    const float b0 = bias[col], b1 = bias[col + 1];
                    *(float2*)(out0 + (size_t)r0 * ostride + col) =
                        make_float2(softplusf(v0 + b0), softplusf(v1 + b1));
                    *(float2*)(out0 + (size_t)(r0 + 8) * ostride + col) =
                        make_float2(softplusf(v2 + b0), softplusf(v3 + b1));
                } else if (col < 2080) {
                    const int n = col - 2048;
                    *(float2*)(out1 + (size_t)r0 * 32 + n)       = make_float2(v0, v1);
                    *(float2*)(out1 + (size_t)(r0 + 8) * 32 + n) = make_float2(v2, v3);
                }
            } else {
                *(float2*)(out0 + (size_t)r0 * ostride + col)       = make_float2(v0, v1);
                *(float2*)(out0 + (size_t)(r0 + 8) * ostride + col) = make_float2(v2, v3);
            }
        }
    }
}

// ---------------------------------------------------------------------------
// prep_all: weight transposes + WB/WC rows + zero pad + x->fp16 conversion
// blocks: [0,4096) Win ; [4096,8192) Wd ; [8192,10240) Wo ;
//         [10240,10304) WB/WC rows ; [10304,10496) zero pad ; [10496,14592) x
// ---------------------------------------------------------------------------
__device__ __forceinline__ void transp_tile(
    const float* __restrict__ in, __half* __restrict__ oh,
    int K, int N, int nb, int kb, int tid)
{
    __shared__ float t[32][33];
    const int n0 = nb * 32, k0 = kb * 32;
    const int tx = tid & 31, ty = tid >> 5;
#pragma unroll
    for (int i = 0; i < 32; i += 8)
        t[ty + i][tx] = in[(size_t)(k0 + ty + i) * N + n0 + tx];
    __syncthreads();
#pragma unroll
    for (int i = 0; i < 32; i += 8) {
        const int n = n0 + ty + i, k = k0 + tx;
        oh[(size_t)n * K + k] = __float2half(t[tx][ty + i]);
    }
}

__global__ void __launch_bounds__(256)
prep_all(const float* __restrict__ W_in, const float* __restrict__ W_delta,
         const float* __restrict__ W_out,
         const float* __restrict__ WB, const float* __restrict__ WC,
         const float* __restrict__ x,
         __half* __restrict__ Wi, __half* __restrict__ Wd, __half* __restrict__ Wo,
         __half* __restrict__ xh)
{
    const int blk = blockIdx.x;
    const int tid = threadIdx.x;
    if (blk < 4096) {
        transp_tile(W_in, Wi, DM, 2 * DI, blk & 127, blk >> 7, tid);
    } else if (blk < 8192) {
        const int t2 = blk - 4096;
        transp_tile(W_delta, Wd, DI, DI, t2 & 63, t2 >> 6, tid);
    } else if (blk < 10240) {
        const int t3 = blk - 8192;
        transp_tile(W_out, Wo, DI, DM, t3 & 31, t3 >> 5, tid);
    } else if (blk < 10304) {
        const int base = (blk - 10240) * 1024 + tid * 4;
#pragma unroll
        for (int i = 0; i < 4; ++i) {
            const int id = base + i;
            const int n = id >> 11;
            const int k = id & 2047;
            const float v = (n < DS) ? WB[(size_t)k * DS + n]
                                     : WC[(size_t)k * DS + (n - DS)];
            Wd[(size_t)(2048 + n) * DI + k] = __float2half(v);
        }
    } else if (blk < 10496) {
        const int base = (blk - 10304) * 1024 + tid * 4;
        __half2 z; z.x = __float2half(0.f); z.y = __float2half(0.f);
        *(__half2*)(Wd + (size_t)2080 * DI + base)     = z;
        *(__half2*)(Wd + (size_t)2080 * DI + base + 2) = z;
    } else {
        const int i = (blk - 10496) * 256 + tid;
        float4 v = ((const float4*)x)[i];
        __half2 hh0, hh1;
        hh0.x = __float2half(v.x); hh0.y = __float2half(v.y);
        hh1.x = __float2half(v.z); hh1.y = __float2half(v.w);
        ((__half2*)xh)[2*i]   = hh0;
        ((__half2*)xh)[2*i+1] = hh1;
    }
}

// ---------------------------------------------------------------------------
// Chunked scan (phases A/B/C). u from Uh+Ul; BC combined [m][32]; S fp16.
// ---------------------------------------------------------------------------
__device__ __forceinline__ float loadU(const __half* Uh, const __half* Ul, size_t i) {
    return __half2float(Uh[i]) + __half2float(Ul[i]);
}

__global__ void __launch_bounds__(64)
scanA(const float* __restrict__ DEL,
      const __half* __restrict__ Uh, const __half* __restrict__ Ul,
      const float* __restrict__ BC, const float* __restrict__ Alog,
      float4* __restrict__ P4, float4* __restrict__ Q4)
{
    const int c = blockIdx.y;
    const int tid = threadIdx.x;
    const int g = blockIdx.x * 16 + (tid >> 2);
    const int b = g >> 11;
    const int d = g & (DI - 1);
    const int sub = tid & 3;

    const float A0 = -__expf(Alog[d * DS + sub * 4 + 0]);
    const float A1 = -__expf(Alog[d * DS + sub * 4 + 1]);
    const float A2 = -__expf(Alog[d * DS + sub * 4 + 2]);
    const float A3 = -__expf(Alog[d * DS + sub * 4 + 3]);
    const float d10 = A1 - A0;
    const bool uni = (fabsf((A2 - A1) - d10) <= 1e-4f * fabsf(d10) + 1e-20f) &&
                     (fabsf((A3 - A2) - d10) <= 1e-4f * fabsf(d10) + 1e-20f);

    float4 P = make_float4(1.f, 1.f, 1.f, 1.f);
    float4 q = make_float4(0.f, 0.f, 0.f, 0.f);

    size_t xbase = ((size_t)b * Lseq + (size_t)c * TL) * DI + d;
    size_t rbase = ((size_t)b * Lseq + (size_t)c * TL) * 32 + sub * 4;

#pragma unroll 4
    for (int t = 0; t < TL; ++t) {
        const float delta = DEL[xbase];
        const float uu    = loadU(Uh, Ul, xbase);
        const float4 Bv = *(const float4*)(BC + rbase);

        float a0, a1, a2, a3;
        if (uni) {
            a0 = __expf(delta * A0);
            const float rr = __expf(delta * d10);
            a1 = a0 * rr; a2 = a1 * rr; a3 = a2 * rr;
        } else {
            a0 = __expf(delta * A0); a1 = __expf(delta * A1);
            a2 = __expf(delta * A2); a3 = __expf(delta * A3);
        }
        const float db = delta * uu;
        q.x = fmaf(a0, q.x, db * Bv.x);
        q.y = fmaf(a1, q.y, db * Bv.y);
        q.z = fmaf(a2, q.z, db * Bv.z);
        q.w = fmaf(a3, q.w, db * Bv.w);
        P.x *= a0; P.y *= a1; P.z *= a2; P.w *= a3;

        xbase += DI;
        rbase += 32;
    }
    const int idx = (((c * 2 + b) * DI) + d) * 4 + sub;
    P4[idx] = P;
    Q4[idx] = q;
}

__global__ void __launch_bounds__(256)
scanB(const float4* __restrict__ P4, const float4* __restrict__ Q4,
      float4* __restrict__ H4)
{
    const int gs = blockIdx.x * 256 + threadIdx.x;
    const int g = gs >> 2;
    const int sub = gs & 3;
    const int b = g >> 11;
    const int d = g & (DI - 1);

    float4 h = make_float4(0.f, 0.f, 0.f, 0.f);
#pragma unroll
    for (int c = 0; c < CH; ++c) {
        const int idx = (((c * 2 + b) * DI) + d) * 4 + sub;
        H4[idx] = h;
        const float4 P = P4[idx];
        const float4 q = Q4[idx];
        h.x = fmaf(P.x, h.x, q.x);
        h.y = fmaf(P.y, h.y, q.y);
        h.z = fmaf(P.z, h.z, q.z);
        h.w = fmaf(P.w, h.w, q.w);
    }
}

__global__ void __launch_bounds__(64)
scanC(const float* __restrict__ DEL,
      const __half* __restrict__ Uh, const __half* __restrict__ Ul,
      const __half* __restrict__ Sh,
      const float* __restrict__ BC,
      const float* __restrict__ Alog, const float* __restrict__ Dp,
      const float4* __restrict__ H4,
      __half* __restrict__ Yh)
{
    const int c = blockIdx.y;
    const int tid = threadIdx.x;
    const int g = blockIdx.x * 16 + (tid >> 2);
    const int b = g >> 11;
    const int d = g & (DI - 1);
    const int sub = tid & 3;

    const float A0 = -__expf(Alog[d * DS + sub * 4 + 0]);
    const float A1 = -__expf(Alog[d * DS + sub * 4 + 1]);
    const float A2 = -__expf(Alog[d * DS + sub * 4 + 2]);
    const float A3 = -__expf(Alog[d * DS + sub * 4 + 3]);
    const float d10 = A1 - A0;
    const bool uni = (fabsf((A2 - A1) - d10) <= 1e-4f * fabsf(d10) + 1e-20f) &&
                     (fabsf((A3 - A2) - d10) <= 1e-4f * fabsf(d10) + 1e-20f);
    const float Dd = Dp[d];

    const int idx = (((c * 2 + b) * DI) + d) * 4 + sub;
    float4 h = H4[idx];

    size_t xbase = ((size_t)b * Lseq + (size_t)c * TL) * DI + d;
    size_t rbase = ((size_t)b * Lseq + (size_t)c * TL) * 32 + sub * 4;

#pragma unroll 4
    for (int t = 0; t < TL; ++t) {
        const float delta = DEL[xbase];
        const float uu    = loadU(Uh, Ul, xbase);
        const float4 Bv = *(const float4*)(BC + rbase);
        const float4 Cv = *(const float4*)(BC + rbase + 16);

        float a0, a1, a2, a3;
        if (uni) {
            a0 = __expf(delta * A0);
            const float rr = __expf(delta * d10);
            a1 = a0 * rr; a2 = a1 * rr; a3 = a2 * rr;
        } else {
            a0 = __expf(delta * A0); a1 = __expf(delta * A1);
            a2 = __expf(delta * A2); a3 = __expf(delta * A3);
        }
        const float db = delta * uu;
        h.x = fmaf(a0, h.x, db * Bv.x);
        h.y = fmaf(a1, h.y, db * Bv.y);
        h.z = fmaf(a2, h.z, db * Bv.z);
        h.w = fmaf(a3, h.w, db * Bv.w);

        float ps = h.x * Cv.x;
        ps = fmaf(h.y, Cv.y, ps);
        ps = fmaf(h.z, Cv.z, ps);
        ps = fmaf(h.w, Cv.w, ps);
        ps += __shfl_xor_sync(0xffffffffu, ps, 1);
        ps += __shfl_xor_sync(0xffffffffu, ps, 2);

        if (sub == 0) {
            const float yv = (ps + uu * Dd) * __half2float(Sh[xbase]);
            Yh[xbase] = __float2half(yv);
        }
        xbase += DI;
        rbase += 32;
    }
}

// ---------------------------------------------------------------------------
extern "C" void kernel_launch(void* const* d_in, const int* in_sizes, int n_in,
                              void* d_out, int out_size)
{
    const float* x       = (const float*)d_in[0];
    const float* W_in    = (const float*)d_in[1];
    const float* W_delta = (const float*)d_in[2];
    const float* b_delta = (const float*)d_in[3];
    const float* W_B     = (const float*)d_in[4];
    const float* W_C     = (const float*)d_in[5];
    const float* A_log   = (const float*)d_in[6];
    const float* D_param = (const float*)d_in[7];
    const float* W_out   = (const float*)d_in[8];
    float* out = (float*)d_out;

    float *pDel, *pBC;
    __half *pSh, *pUh, *pUl, *pYh, *pxh, *pWi, *pWd, *pWo;
    float4 *pP4, *pQ4, *pH4;
    cudaGetSymbolAddress((void**)&pSh,  g_Sh);
    cudaGetSymbolAddress((void**)&pDel, g_DELTA);
    cudaGetSymbolAddress((void**)&pBC,  g_BC);
    cudaGetSymbolAddress((void**)&pUh,  g_Uh);
    cudaGetSymbolAddress((void**)&pUl,  g_Ul);
    cudaGetSymbolAddress((void**)&pYh,  g_Yh);
    cudaGetSymbolAddress((void**)&pxh,  g_xh);
    cudaGetSymbolAddress((void**)&pWi,  g_WinT);
    cudaGetSymbolAddress((void**)&pWd,  g_WdT);
    cudaGetSymbolAddress((void**)&pWo,  g_WoT);
    cudaGetSymbolAddress((void**)&pP4,  g_P4);
    cudaGetSymbolAddress((void**)&pQ4,  g_Q4);
    cudaGetSymbolAddress((void**)&pH4,  g_H4);

    cudaFuncSetAttribute((const void*)tgemm<0, false>, cudaFuncAttributeMaxDynamicSharedMemorySize, SMEM_TOT);
    cudaFuncSetAttribute((const void*)tgemm<1, true>,  cudaFuncAttributeMaxDynamicSharedMemorySize, SMEM_TOT);
    cudaFuncSetAttribute((const void*)tgemm<2, false>, cudaFuncAttributeMaxDynamicSharedMemorySize, SMEM_TOT);

    // Order: prep(1) tgemm0(2) tgemm1(3) scanA(4 <- ncu slot)
    //        scanB(5) scanC(6) tgemm2(7)
    prep_all<<<14592, 256>>>(W_in, W_delta, W_out, W_B, W_C, x,
                             pWi, pWd, pWo, pxh);

    // 1) x @ W_in -> U (silu, fp16 hi/lo) | S (silu, fp16)
    tgemm<0, false><<<dim3(2 * DI / 128, Mrows / 128), 256, SMEM_TOT>>>(
        pxh, pxh, pWi, DM, 2048, nullptr, nullptr, nullptr, pUh, pUl, pSh);

    // 2+3) DELTA = softplus(U @ W_delta + b) fused with Bm|Cm
    tgemm<1, true><<<dim3(ND / 128, Mrows / 128), 256, SMEM_TOT>>>(
        pUh, pUl, pWd, DI, DI, b_delta, pDel, pBC, nullptr, nullptr, nullptr);

    // 4) chunked selective scan -> Y (fp16)
    scanA<<<dim3(256, CH), 64>>>(pDel, pUh, pUl, pBC, A_log, pP4, pQ4);
    scanB<<<64, 256>>>(pP4, pQ4, pH4);
    scanC<<<dim3(256, CH), 64>>>(pDel, pUh, pUl, pSh, pBC, A_log, D_param,
                                 pH4, pYh);

    // 5) out = Y @ W_out   [single-term Y]
    tgemm<2, false><<<dim3(DM / 128, Mrows / 128), 256, SMEM_TOT>>>(
        pYh, pYh, pWo, DI, DM, nullptr, out, nullptr, nullptr, nullptr, nullptr);
}

// round 14
// speedup vs baseline: 2.8395x; 1.1127x over previous
#include <cuda_runtime.h>
#include <cuda_fp16.h>
#include <cstdint>

#define DM 1024
#define DI 2048
#define DS 16
#define Mrows 4096
#define Lseq 2048
#define CH 32      // chunks
#define TL 64      // timesteps per chunk
#define ND 2176    // padded N for fused delta+B+C GEMM (17 tiles of 128)

// ---------------- scratch (device globals; allocation-free) ----------------
__device__ __half g_Sh[Mrows * DI];
__device__ float g_DELTA[Mrows * DI];
__device__ float g_BC[Mrows * 32];         // [m][0..15]=Bm, [16..31]=Cm
__device__ __half g_Uh[Mrows * DI], g_Ul[Mrows * DI];
__device__ __half g_Yh[Mrows * DI];
__device__ __half g_xh[Mrows * DM];
__device__ __half g_WinT[2 * DI * DM];
__device__ __half g_WdT[ND * DI];          // rows: 0..2047 Wd^T, 2048..2079 WB^T|WC^T, rest 0
__device__ __half g_WoT[DM * DI];
__device__ float4 g_P4[CH * 2 * DI * 4];   // per-chunk decay products
__device__ float4 g_Q4[CH * 2 * DI * 4];   // per-chunk partial states
__device__ float4 g_H4[CH * 2 * DI * 4];   // chunk entry states

// ---------------- helpers ----------------
__device__ __forceinline__ float siluf(float x) { return x / (1.0f + __expf(-x)); }
__device__ __forceinline__ float softplusf(float x) {
    return (x > 20.0f) ? x : log1pf(__expf(x));
}
__device__ __forceinline__ uint32_t smem_u32(const void* p) {
    uint32_t a;
    asm("{ .reg .u64 t; cvta.to.shared.u64 t, %1; cvt.u32.u64 %0, t; }" : "=r"(a) : "l"(p));
    return a;
}
__device__ __forceinline__ void cpa16(uint32_t s, const void* g) {
    asm volatile("cp.async.cg.shared.global [%0], [%1], 16;" :: "r"(s), "l"(g));
}
__device__ __forceinline__ void cpa_commit() { asm volatile("cp.async.commit_group;"); }

__device__ __forceinline__ void ldsm4(uint32_t* r, uint32_t addr) {
    asm volatile("ldmatrix.sync.aligned.m8n8.x4.shared.b16 {%0,%1,%2,%3}, [%4];"
                 : "=r"(r[0]), "=r"(r[1]), "=r"(r[2]), "=r"(r[3]) : "r"(addr));
}
__device__ __forceinline__ void mma16816h(float* d, const uint32_t* a, const uint32_t* b) {
    asm volatile(
        "mma.sync.aligned.m16n8k16.row.col.f32.f16.f16.f32 "
        "{%0,%1,%2,%3}, {%4,%5,%6,%7}, {%8,%9}, {%0,%1,%2,%3};\n"
        : "+f"(d[0]), "+f"(d[1]), "+f"(d[2]), "+f"(d[3])
        : "r"(a[0]), "r"(a[1]), "r"(a[2]), "r"(a[3]), "r"(b[0]), "r"(b[1]));
}

#define TPAD 144
#define TILE_B (128 * TPAD)
#define STAGE_B (3 * TILE_B)
#define NSTAGE 2
#define SMEM_TOT (NSTAGE * STAGE_B)  // 110592 -> 2 CTAs/SM

template <bool SPLIT2>
__device__ __forceinline__ void load_chunk(
    const __half* __restrict__ Ah, const __half* __restrict__ Al,
    const __half* __restrict__ B,
    int m0, int n0, int kc, int Kdim, uint32_t sb, int tid, bool active)
{
    if (active) {
#pragma unroll
        for (int j = 0; j < 12; ++j) {
            const int g = j * 256 + tid;
            const int tile = g >> 10;
            if (!SPLIT2 && tile == 1) continue;
            const int w = g & 1023;
            const int row = w >> 3;
            const int col16 = w & 7;
            const __half* base = (tile == 0) ? Ah : (tile == 1) ? Al : B;
            const int r0 = (tile == 2) ? n0 : m0;
            const __half* src = base + (size_t)(r0 + row) * Kdim + kc + col16 * 8;
            cpa16(sb + (uint32_t)(tile * TILE_B + row * TPAD + col16 * 16),
                  (const void*)src);
        }
    }
    cpa_commit();
}

// ---------------------------------------------------------------------------
// HMMA fp16 GEMM: C[M,N] = A[M,K] * B[N,K]^T  (fp32 accum)
// ---------------------------------------------------------------------------
template <int MODE, bool SPLIT2>
__global__ void __launch_bounds__(256, 2)
tgemm(const __half* __restrict__ Ah, const __half* __restrict__ Al,
      const __half* __restrict__ B,
      int Kdim, int ostride,
      const float* __restrict__ bias,
      float* __restrict__ out0, float* __restrict__ out1,
      __half* __restrict__ obh, __half* __restrict__ obl,
      __half* __restrict__ obs)
{
    extern __shared__ char smem[];
    const uint32_t sb = smem_u32(smem);

    const int tid  = threadIdx.x;
    const int lane = tid & 31;
    const int wid  = tid >> 5;
    const int wm   = wid & 3;
    const int wn   = wid >> 2;
    const int m0 = blockIdx.y * 128;
    const int n0 = blockIdx.x * 128;

    const uint32_t a_off =
        (uint32_t)(wm * 32 + (lane & 15)) * TPAD + (uint32_t)((lane >> 4) * 16);
    const int p = lane >> 3;
    const uint32_t b_off =
        (uint32_t)(wn * 64 + (p >> 1) * 8 + (lane & 7)) * TPAD + (uint32_t)((p & 1) * 16);

    float acc[2][8][4];
#pragma unroll
    for (int i = 0; i < 2; ++i)
#pragma unroll
        for (int j = 0; j < 8; ++j)
#pragma unroll
            for (int q = 0; q < 4; ++q) acc[i][j][q] = 0.0f;

    const int NC = Kdim >> 6;

    load_chunk<SPLIT2>(Ah, Al, B, m0, n0, 0, Kdim, sb, tid, 0 < NC);

    for (int c = 0; c < NC; ++c) {
        asm volatile("cp.async.wait_group 0;" ::: "memory");
        __syncthreads();

        load_chunk<SPLIT2>(Ah, Al, B, m0, n0, (c + 1) * 64, Kdim,
                           sb + (uint32_t)((c + 1) & 1) * STAGE_B, tid, (c + 1) < NC);

        const uint32_t st = sb + (uint32_t)(c & 1) * STAGE_B;
        const uint32_t smAh = st;
        const uint32_t smAl = st + TILE_B;
        const uint32_t smB  = st + 2 * TILE_B;

#pragma unroll
        for (int k16 = 0; k16 < 4; ++k16) {
            const uint32_t kb = (uint32_t)(k16 * 32);
            uint32_t ah[2][4], al[2][4], bf[4][4];
#pragma unroll
            for (int mt = 0; mt < 2; ++mt) {
                ldsm4(ah[mt], smAh + kb + a_off + (uint32_t)(mt * 16 * TPAD));
                if (SPLIT2)
                    ldsm4(al[mt], smAl + kb + a_off + (uint32_t)(mt * 16 * TPAD));
            }
#pragma unroll
            for (int p2 = 0; p2 < 4; ++p2)
                ldsm4(bf[p2], smB + kb + b_off + (uint32_t)(p2 * 16 * TPAD));
#pragma unroll
            for (int mt = 0; mt < 2; ++mt)
#pragma unroll
                for (int nt = 0; nt < 8; ++nt)
                    mma16816h(acc[mt][nt], ah[mt], &bf[nt >> 1][(nt & 1) * 2]);
            if (SPLIT2) {
#pragma unroll
                for (int mt = 0; mt < 2; ++mt)
#pragma unroll
                    for (int nt = 0; nt < 8; ++nt)
                        mma16816h(acc[mt][nt], al[mt], &bf[nt >> 1][(nt & 1) * 2]);
            }
        }
    }

    __syncthreads();

    const int g2 = lane >> 2;
    const int c2 = (lane & 3) * 2;
#pragma unroll
    for (int mt = 0; mt < 2; ++mt) {
        const int r0 = m0 + wm * 32 + mt * 16 + g2;
#pragma unroll
        for (int nt = 0; nt < 8; ++nt) {
            const int col = n0 + wn * 64 + nt * 8 + c2;
            float v0 = acc[mt][nt][0], v1 = acc[mt][nt][1];
            float v2 = acc[mt][nt][2], v3 = acc[mt][nt][3];

            if (MODE == 0) {
                v0 = siluf(v0); v1 = siluf(v1); v2 = siluf(v2); v3 = siluf(v3);
                if (n0 < 2048) {
                    __half2 h0, l0, h1, l1;
                    h0.x = __float2half(v0); h0.y = __float2half(v1);
                    l0.x = __float2half(v0 - __half2float(h0.x));
                    l0.y = __float2half(v1 - __half2float(h0.y));
                    h1.x = __float2half(v2); h1.y = __float2half(v3);
                    l1.x = __float2half(v2 - __half2float(h1.x));
                    l1.y = __float2half(v3 - __half2float(h1.y));
                    *(__half2*)(obh + (size_t)r0 * 2048 + col)       = h0;
                    *(__half2*)(obl + (size_t)r0 * 2048 + col)       = l0;
                    *(__half2*)(obh + (size_t)(r0 + 8) * 2048 + col) = h1;
                    *(__half2*)(obl + (size_t)(r0 + 8) * 2048 + col) = l1;
                } else {
                    const int cs = col - 2048;
                    __half2 s0, s1;
                    s0.x = __float2half(v0); s0.y = __float2half(v1);
                    s1.x = __float2half(v2); s1.y = __float2half(v3);
                    *(__half2*)(obs + (size_t)r0 * 2048 + cs)       = s0;
                    *(__half2*)(obs + (size_t)(r0 + 8) * 2048 + cs) = s1;
                }
            } else if (MODE == 1) {
                if (col < 2048) {
                    const float b0 = bias[col], b1 = bias[col + 1];
                    *(float2*)(out0 + (size_t)r0 * ostride + col) =
                        make_float2(softplusf(v0 + b0), softplusf(v1 + b1));
                    *(float2*)(out0 + (size_t)(r0 + 8) * ostride + col) =
                        make_float2(softplusf(v2 + b0), softplusf(v3 + b1));
                } else if (col < 2080) {
                    const int n = col - 2048;
                    *(float2*)(out1 + (size_t)r0 * 32 + n)       = make_float2(v0, v1);
                    *(float2*)(out1 + (size_t)(r0 + 8) * 32 + n) = make_float2(v2, v3);
                }
            } else {
                *(float2*)(out0 + (size_t)r0 * ostride + col)       = make_float2(v0, v1);
                *(float2*)(out0 + (size_t)(r0 + 8) * ostride + col) = make_float2(v2, v3);
            }
        }
    }
}

// ---------------------------------------------------------------------------
// prep_all: weight transposes + WB/WC rows + zero pad + x->fp16 conversion
// ---------------------------------------------------------------------------
__device__ __forceinline__ void transp_tile(
    const float* __restrict__ in, __half* __restrict__ oh,
    int K, int N, int nb, int kb, int tid)
{
    __shared__ float t[32][33];
    const int n0 = nb * 32, k0 = kb * 32;
    const int tx = tid & 31, ty = tid >> 5;
#pragma unroll
    for (int i = 0; i < 32; i += 8)
        t[ty + i][tx] = in[(size_t)(k0 + ty + i) * N + n0 + tx];
    __syncthreads();
#pragma unroll
    for (int i = 0; i < 32; i += 8) {
        const int n = n0 + ty + i, k = k0 + tx;
        oh[(size_t)n * K + k] = __float2half(t[tx][ty + i]);
    }
}

__global__ void __launch_bounds__(256)
prep_all(const float* __restrict__ W_in, const float* __restrict__ W_delta,
         const float* __restrict__ W_out,
         const float* __restrict__ WB, const float* __restrict__ WC,
         const float* __restrict__ x,
         __half* __restrict__ Wi, __half* __restrict__ Wd, __half* __restrict__ Wo,
         __half* __restrict__ xh)
{
    const int blk = blockIdx.x;
    const int tid = threadIdx.x;
    if (blk < 4096) {
        transp_tile(W_in, Wi, DM, 2 * DI, blk & 127, blk >> 7, tid);
    } else if (blk < 8192) {
        const int t2 = blk - 4096;
        transp_tile(W_delta, Wd, DI, DI, t2 & 63, t2 >> 6, tid);
    } else if (blk < 10240) {
        const int t3 = blk - 8192;
        transp_tile(W_out, Wo, DI, DM, t3 & 31, t3 >> 5, tid);
    } else if (blk < 10304) {
        const int base = (blk - 10240) * 1024 + tid * 4;
#pragma unroll
        for (int i = 0; i < 4; ++i) {
            const int id = base + i;
            const int n = id >> 11;
            const int k = id & 2047;
            const float v = (n < DS) ? WB[(size_t)k * DS + n]
                                     : WC[(size_t)k * DS + (n - DS)];
            Wd[(size_t)(2048 + n) * DI + k] = __float2half(v);
        }
    } else if (blk < 10496) {
        const int base = (blk - 10304) * 1024 + tid * 4;
        __half2 z; z.x = __float2half(0.f); z.y = __float2half(0.f);
        *(__half2*)(Wd + (size_t)2080 * DI + base)     = z;
        *(__half2*)(Wd + (size_t)2080 * DI + base + 2) = z;
    } else {
        const int i = (blk - 10496) * 256 + tid;
        float4 v = ((const float4*)x)[i];
        __half2 hh0, hh1;
        hh0.x = __float2half(v.x); hh0.y = __float2half(v.y);
        hh1.x = __float2half(v.z); hh1.y = __float2half(v.w);
        ((__half2*)xh)[2*i]   = hh0;
        ((__half2*)xh)[2*i+1] = hh1;
    }
}

// ---------------------------------------------------------------------------
// Chunked scan: ONE thread per channel, 16 states in registers.
// exp via power chain (A rows uniformly spaced): a_i = a0 * r^i.
// ---------------------------------------------------------------------------
__device__ __forceinline__ float loadU(const __half* Uh, const __half* Ul, size_t i) {
    return __half2float(Uh[i]) + __half2float(Ul[i]);
}

__device__ __forceinline__ void comp_a(
    bool uni, float delta, const float* A, float d10, float* a)
{
    if (uni) {
        a[0] = __expf(delta * A[0]);
        const float r  = __expf(delta * d10);
        const float r2 = r * r;
        const float r4 = r2 * r2;
        const float r8 = r4 * r4;
        a[1] = a[0] * r;  a[2] = a[0] * r2; a[3] = a[1] * r2;
        a[4] = a[0] * r4; a[5] = a[1] * r4; a[6] = a[2] * r4; a[7] = a[3] * r4;
#pragma unroll
        for (int i = 0; i < 8; ++i) a[8 + i] = a[i] * r8;
    } else {
#pragma unroll
        for (int i = 0; i < DS; ++i) a[i] = __expf(delta * A[i]);
    }
}

__global__ void __launch_bounds__(128)
scanA(const float* __restrict__ DEL,
      const __half* __restrict__ Uh, const __half* __restrict__ Ul,
      const float* __restrict__ BC, const float* __restrict__ Alog,
      float4* __restrict__ P4, float4* __restrict__ Q4)
{
    const int c = blockIdx.y;
    const int g = blockIdx.x * 128 + threadIdx.x;   // channel 0..4095
    const int b = g >> 11;
    const int d = g & (DI - 1);

    float A[DS];
#pragma unroll
    for (int i = 0; i < DS; ++i) A[i] = -__expf(Alog[d * DS + i]);
    const float d10 = A[1] - A[0];
    bool uni = true;
#pragma unroll
    for (int i = 2; i < DS; ++i)
        uni = uni && (fabsf((A[i] - A[i - 1]) - d10) <= 1e-4f * fabsf(d10) + 1e-20f);

    float h[DS], P[DS];
#pragma unroll
    for (int i = 0; i < DS; ++i) { h[i] = 0.f; P[i] = 1.f; }

    size_t xbase = ((size_t)b * Lseq + (size_t)c * TL) * DI + d;
    size_t rbase = ((size_t)b * Lseq + (size_t)c * TL) * 32;

#pragma unroll 2
    for (int t = 0; t < TL; ++t) {
        const float delta = DEL[xbase];
        const float uu    = loadU(Uh, Ul, xbase);
        float Bv[DS];
#pragma unroll
        for (int q = 0; q < 4; ++q)
            *(float4*)&Bv[q * 4] = *(const float4*)(BC + rbase + q * 4);

        float a[DS];
        comp_a(uni, delta, A, d10, a);
        const float db = delta * uu;
#pragma unroll
        for (int i = 0; i < DS; ++i) {
            h[i] = fmaf(a[i], h[i], db * Bv[i]);
            P[i] *= a[i];
        }
        xbase += DI;
        rbase += 32;
    }
    const int idx = (((c * 2 + b) * DI) + d) * 4;
#pragma unroll
    for (int s = 0; s < 4; ++s) {
        P4[idx + s] = make_float4(P[4*s], P[4*s+1], P[4*s+2], P[4*s+3]);
        Q4[idx + s] = make_float4(h[4*s], h[4*s+1], h[4*s+2], h[4*s+3]);
    }
}

__global__ void __launch_bounds__(256)
scanB(const float4* __restrict__ P4, const float4* __restrict__ Q4,
      float4* __restrict__ H4)
{
    const int gs = blockIdx.x * 256 + threadIdx.x;
    const int g = gs >> 2;
    const int sub = gs & 3;
    const int b = g >> 11;
    const int d = g & (DI - 1);

    float4 h = make_float4(0.f, 0.f, 0.f, 0.f);
#pragma unroll
    for (int c = 0; c < CH; ++c) {
        const int idx = (((c * 2 + b) * DI) + d) * 4 + sub;
        H4[idx] = h;
        const float4 P = P4[idx];
        const float4 q = Q4[idx];
        h.x = fmaf(P.x, h.x, q.x);
        h.y = fmaf(P.y, h.y, q.y);
        h.z = fmaf(P.z, h.z, q.z);
        h.w = fmaf(P.w, h.w, q.w);
    }
}

__global__ void __launch_bounds__(128)
scanC(const float* __restrict__ DEL,
      const __half* __restrict__ Uh, const __half* __restrict__ Ul,
      const __half* __restrict__ Sh,
      const float* __restrict__ BC,
      const float* __restrict__ Alog, const float* __restrict__ Dp,
      const float4* __restrict__ H4,
      __half* __restrict__ Yh)
{
    const int c = blockIdx.y;
    const int g = blockIdx.x * 128 + threadIdx.x;   // channel 0..4095
    const int b = g >> 11;
    const int d = g & (DI - 1);

    float A[DS];
#pragma unroll
    for (int i = 0; i < DS; ++i) A[i] = -__expf(Alog[d * DS + i]);
    const float d10 = A[1] - A[0];
    bool uni = true;
#pragma unroll
    for (int i = 2; i < DS; ++i)
        uni = uni && (fabsf((A[i] - A[i - 1]) - d10) <= 1e-4f * fabsf(d10) + 1e-20f);
    const float Dd = Dp[d];

    const int idx = (((c * 2 + b) * DI) + d) * 4;
    float h[DS];
#pragma unroll
    for (int s = 0; s < 4; ++s) {
        const float4 hv = H4[idx + s];
        h[4*s] = hv.x; h[4*s+1] = hv.y; h[4*s+2] = hv.z; h[4*s+3] = hv.w;
    }

    size_t xbase = ((size_t)b * Lseq + (size_t)c * TL) * DI + d;
    size_t rbase = ((size_t)b * Lseq + (size_t)c * TL) * 32;

#pragma unroll 2
    for (int t = 0; t < TL; ++t) {
        const float delta = DEL[xbase];
        const float uu    = loadU(Uh, Ul, xbase);
        float Bv[DS], Cv[DS];
#pragma unroll
        for (int q = 0; q < 4; ++q) {
            *(float4*)&Bv[q * 4] = *(const float4*)(BC + rbase + q * 4);
            *(float4*)&Cv[q * 4] = *(const float4*)(BC + rbase + 16 + q * 4);
        }

        float a[DS];
        comp_a(uni, delta, A, d10, a);
        const float db = delta * uu;
        float y0 = 0.f, y1 = 0.f, y2 = 0.f, y3 = 0.f;
#pragma unroll
        for (int i = 0; i < DS; i += 4) {
            h[i]   = fmaf(a[i],   h[i],   db * Bv[i]);
            h[i+1] = fmaf(a[i+1], h[i+1], db * Bv[i+1]);
            h[i+2] = fmaf(a[i+2], h[i+2], db * Bv[i+2]);
            h[i+3] = fmaf(a[i+3], h[i+3], db * Bv[i+3]);
            y0 = fmaf(h[i],   Cv[i],   y0);
            y1 = fmaf(h[i+1], Cv[i+1], y1);
            y2 = fmaf(h[i+2], Cv[i+2], y2);
            y3 = fmaf(h[i+3], Cv[i+3], y3);
        }
        const float yv = (((y0 + y1) + (y2 + y3)) + uu * Dd) * __half2float(Sh[xbase]);
        Yh[xbase] = __float2half(yv);
        xbase += DI;
        rbase += 32;
    }
}

// ---------------------------------------------------------------------------
extern "C" void kernel_launch(void* const* d_in, const int* in_sizes, int n_in,
                              void* d_out, int out_size)
{
    const float* x       = (const float*)d_in[0];
    const float* W_in    = (const float*)d_in[1];
    const float* W_delta = (const float*)d_in[2];
    const float* b_delta = (const float*)d_in[3];
    const float* W_B     = (const float*)d_in[4];
    const float* W_C     = (const float*)d_in[5];
    const float* A_log   = (const float*)d_in[6];
    const float* D_param = (const float*)d_in[7];
    const float* W_out   = (const float*)d_in[8];
    float* out = (float*)d_out;

    float *pDel, *pBC;
    __half *pSh, *pUh, *pUl, *pYh, *pxh, *pWi, *pWd, *pWo;
    float4 *pP4, *pQ4, *pH4;
    cudaGetSymbolAddress((void**)&pSh,  g_Sh);
    cudaGetSymbolAddress((void**)&pDel, g_DELTA);
    cudaGetSymbolAddress((void**)&pBC,  g_BC);
    cudaGetSymbolAddress((void**)&pUh,  g_Uh);
    cudaGetSymbolAddress((void**)&pUl,  g_Ul);
    cudaGetSymbolAddress((void**)&pYh,  g_Yh);
    cudaGetSymbolAddress((void**)&pxh,  g_xh);
    cudaGetSymbolAddress((void**)&pWi,  g_WinT);
    cudaGetSymbolAddress((void**)&pWd,  g_WdT);
    cudaGetSymbolAddress((void**)&pWo,  g_WoT);
    cudaGetSymbolAddress((void**)&pP4,  g_P4);
    cudaGetSymbolAddress((void**)&pQ4,  g_Q4);
    cudaGetSymbolAddress((void**)&pH4,  g_H4);

    cudaFuncSetAttribute((const void*)tgemm<0, false>, cudaFuncAttributeMaxDynamicSharedMemorySize, SMEM_TOT);
    cudaFuncSetAttribute((const void*)tgemm<1, true>,  cudaFuncAttributeMaxDynamicSharedMemorySize, SMEM_TOT);
    cudaFuncSetAttribute((const void*)tgemm<2, false>, cudaFuncAttributeMaxDynamicSharedMemorySize, SMEM_TOT);

    // Order: prep(1) tgemm0(2) tgemm1(3) scanA(4 <- ncu slot)
    //        scanB(5) scanC(6) tgemm2(7)
    prep_all<<<14592, 256>>>(W_in, W_delta, W_out, W_B, W_C, x,
                             pWi, pWd, pWo, pxh);

    // 1) x @ W_in -> U (silu, fp16 hi/lo) | S (silu, fp16)
    tgemm<0, false><<<dim3(2 * DI / 128, Mrows / 128), 256, SMEM_TOT>>>(
        pxh, pxh, pWi, DM, 2048, nullptr, nullptr, nullptr, pUh, pUl, pSh);

    // 2+3) DELTA = softplus(U @ W_delta + b) fused with Bm|Cm
    tgemm<1, true><<<dim3(ND / 128, Mrows / 128), 256, SMEM_TOT>>>(
        pUh, pUl, pWd, DI, DI, b_delta, pDel, pBC, nullptr, nullptr, nullptr);

    // 4) chunked selective scan -> Y (fp16)
    scanA<<<dim3(Mrows / 128, CH), 128>>>(pDel, pUh, pUl, pBC, A_log, pP4, pQ4);
    scanB<<<64, 256>>>(pP4, pQ4, pH4);
    scanC<<<dim3(Mrows / 128, CH), 128>>>(pDel, pUh, pUl, pSh, pBC, A_log,
                                          D_param, pH4, pYh);

    // 5) out = Y @ W_out   [single-term Y]
    tgemm<2, false><<<dim3(DM / 128, Mrows / 128), 256, SMEM_TOT>>>(
        pYh, pYh, pWo, DI, DM, nullptr, out, nullptr, nullptr, nullptr, nullptr);
}

// round 15
// speedup vs baseline: 3.2610x; 1.1484x over previous
#include <cuda_runtime.h>
#include <cuda_fp16.h>
#include <cstdint>

#define DM 1024
#define DI 2048
#define DS 16
#define Mrows 4096
#define Lseq 2048
#define CH 32      // chunks
#define TL 64      // timesteps per chunk
#define ND 2176    // padded N for fused delta+B+C GEMM (17 tiles of 128)

// ---------------- scratch (device globals; allocation-free) ----------------
__device__ __half g_Sh[Mrows * DI];
__device__ float g_DELTA[Mrows * DI];
__device__ float g_BC[Mrows * 32];         // [m][0..15]=Bm, [16..31]=Cm
__device__ __half g_Uh[Mrows * DI], g_Ul[Mrows * DI];
__device__ __half g_Yh[Mrows * DI];
__device__ __half g_xh[Mrows * DM];
__device__ __half g_WinT[2 * DI * DM];
__device__ __half g_WdT[ND * DI];          // rows: 0..2047 Wd^T, 2048..2079 WB^T|WC^T, rest 0
__device__ __half g_WoT[DM * DI];
__device__ float4 g_P4[CH * 2 * DI * 4];   // per-chunk decay products
__device__ float4 g_Q4[CH * 2 * DI * 4];   // per-chunk partial states
__device__ float4 g_H4[CH * 2 * DI * 4];   // chunk entry states

// ---------------- helpers ----------------
__device__ __forceinline__ float siluf(float x) { return x / (1.0f + __expf(-x)); }
__device__ __forceinline__ float softplusf(float x) {
    return (x > 20.0f) ? x : log1pf(__expf(x));
}
__device__ __forceinline__ uint32_t smem_u32(const void* p) {
    uint32_t a;
    asm("{ .reg .u64 t; cvta.to.shared.u64 t, %1; cvt.u32.u64 %0, t; }" : "=r"(a) : "l"(p));
    return a;
}
__device__ __forceinline__ void cpa16(uint32_t s, const void* g) {
    asm volatile("cp.async.cg.shared.global [%0], [%1], 16;" :: "r"(s), "l"(g));
}
__device__ __forceinline__ void cpa_commit() { asm volatile("cp.async.commit_group;"); }

__device__ __forceinline__ void ldsm4(uint32_t* r, uint32_t addr) {
    asm volatile("ldmatrix.sync.aligned.m8n8.x4.shared.b16 {%0,%1,%2,%3}, [%4];"
                 : "=r"(r[0]), "=r"(r[1]), "=r"(r[2]), "=r"(r[3]) : "r"(addr));
}
__device__ __forceinline__ void mma16816h(float* d, const uint32_t* a, const uint32_t* b) {
    asm volatile(
        "mma.sync.aligned.m16n8k16.row.col.f32.f16.f16.f32 "
        "{%0,%1,%2,%3}, {%4,%5,%6,%7}, {%8,%9}, {%0,%1,%2,%3};\n"
        : "+f"(d[0]), "+f"(d[1]), "+f"(d[2]), "+f"(d[3])
        : "r"(a[0]), "r"(a[1]), "r"(a[2]), "r"(a[3]), "r"(b[0]), "r"(b[1]));
}

#define TPAD 144
#define TILE_B (128 * TPAD)
#define STAGE_B (3 * TILE_B)
#define NSTAGE 2
#define SMEM_TOT (NSTAGE * STAGE_B)  // 110592 -> 2 CTAs/SM

template <bool SPLIT2>
__device__ __forceinline__ void load_chunk(
    const __half* __restrict__ Ah, const __half* __restrict__ Al,
    const __half* __restrict__ B,
    int m0, int n0, int kc, int Kdim, uint32_t sb, int tid, bool active)
{
    if (active) {
#pragma unroll
        for (int j = 0; j < 12; ++j) {
            const int g = j * 256 + tid;
            const int tile = g >> 10;
            if (!SPLIT2 && tile == 1) continue;
            const int w = g & 1023;
            const int row = w >> 3;
            const int col16 = w & 7;
            const __half* base = (tile == 0) ? Ah : (tile == 1) ? Al : B;
            const int r0 = (tile == 2) ? n0 : m0;
            const __half* src = base + (size_t)(r0 + row) * Kdim + kc + col16 * 8;
            cpa16(sb + (uint32_t)(tile * TILE_B + row * TPAD + col16 * 16),
                  (const void*)src);
        }
    }
    cpa_commit();
}

// ---------------------------------------------------------------------------
// HMMA fp16 GEMM: C[M,N] = A[M,K] * B[N,K]^T  (fp32 accum)
// ---------------------------------------------------------------------------
template <int MODE, bool SPLIT2>
__global__ void __launch_bounds__(256, 2)
tgemm(const __half* __restrict__ Ah, const __half* __restrict__ Al,
      const __half* __restrict__ B,
      int Kdim, int ostride,
      const float* __restrict__ bias,
      float* __restrict__ out0, float* __restrict__ out1,
      __half* __restrict__ obh, __half* __restrict__ obl,
      __half* __restrict__ obs)
{
    extern __shared__ char smem[];
    const uint32_t sb = smem_u32(smem);

    const int tid  = threadIdx.x;
    const int lane = tid & 31;
    const int wid  = tid >> 5;
    const int wm   = wid & 3;
    const int wn   = wid >> 2;
    const int m0 = blockIdx.y * 128;
    const int n0 = blockIdx.x * 128;

    const uint32_t a_off =
        (uint32_t)(wm * 32 + (lane & 15)) * TPAD + (uint32_t)((lane >> 4) * 16);
    const int p = lane >> 3;
    const uint32_t b_off =
        (uint32_t)(wn * 64 + (p >> 1) * 8 + (lane & 7)) * TPAD + (uint32_t)((p & 1) * 16);

    float acc[2][8][4];
#pragma unroll
    for (int i = 0; i < 2; ++i)
#pragma unroll
        for (int j = 0; j < 8; ++j)
#pragma unroll
            for (int q = 0; q < 4; ++q) acc[i][j][q] = 0.0f;

    const int NC = Kdim >> 6;

    load_chunk<SPLIT2>(Ah, Al, B, m0, n0, 0, Kdim, sb, tid, 0 < NC);

    for (int c = 0; c < NC; ++c) {
        asm volatile("cp.async.wait_group 0;" ::: "memory");
        __syncthreads();

        load_chunk<SPLIT2>(Ah, Al, B, m0, n0, (c + 1) * 64, Kdim,
                           sb + (uint32_t)((c + 1) & 1) * STAGE_B, tid, (c + 1) < NC);

        const uint32_t st = sb + (uint32_t)(c & 1) * STAGE_B;
        const uint32_t smAh = st;
        const uint32_t smAl = st + TILE_B;
        const uint32_t smB  = st + 2 * TILE_B;

#pragma unroll
        for (int k16 = 0; k16 < 4; ++k16) {
            const uint32_t kb = (uint32_t)(k16 * 32);
            uint32_t ah[2][4], al[2][4], bf[4][4];
#pragma unroll
            for (int mt = 0; mt < 2; ++mt) {
                ldsm4(ah[mt], smAh + kb + a_off + (uint32_t)(mt * 16 * TPAD));
                if (SPLIT2)
                    ldsm4(al[mt], smAl + kb + a_off + (uint32_t)(mt * 16 * TPAD));
            }
#pragma unroll
            for (int p2 = 0; p2 < 4; ++p2)
                ldsm4(bf[p2], smB + kb + b_off + (uint32_t)(p2 * 16 * TPAD));
#pragma unroll
            for (int mt = 0; mt < 2; ++mt)
#pragma unroll
                for (int nt = 0; nt < 8; ++nt)
                    mma16816h(acc[mt][nt], ah[mt], &bf[nt >> 1][(nt & 1) * 2]);
            if (SPLIT2) {
#pragma unroll
                for (int mt = 0; mt < 2; ++mt)
#pragma unroll
                    for (int nt = 0; nt < 8; ++nt)
                        mma16816h(acc[mt][nt], al[mt], &bf[nt >> 1][(nt & 1) * 2]);
            }
        }
    }

    __syncthreads();

    const int g2 = lane >> 2;
    const int c2 = (lane & 3) * 2;
#pragma unroll
    for (int mt = 0; mt < 2; ++mt) {
        const int r0 = m0 + wm * 32 + mt * 16 + g2;
#pragma unroll
        for (int nt = 0; nt < 8; ++nt) {
            const int col = n0 + wn * 64 + nt * 8 + c2;
            float v0 = acc[mt][nt][0], v1 = acc[mt][nt][1];
            float v2 = acc[mt][nt][2], v3 = acc[mt][nt][3];

            if (MODE == 0) {
                v0 = siluf(v0); v1 = siluf(v1); v2 = siluf(v2); v3 = siluf(v3);
                if (n0 < 2048) {
                    __half2 h0, l0, h1, l1;
                    h0.x = __float2half(v0); h0.y = __float2half(v1);
                    l0.x = __float2half(v0 - __half2float(h0.x));
                    l0.y = __float2half(v1 - __half2float(h0.y));
                    h1.x = __float2half(v2); h1.y = __float2half(v3);
                    l1.x = __float2half(v2 - __half2float(h1.x));
                    l1.y = __float2half(v3 - __half2float(h1.y));
                    *(__half2*)(obh + (size_t)r0 * 2048 + col)       = h0;
                    *(__half2*)(obl + (size_t)r0 * 2048 + col)       = l0;
                    *(__half2*)(obh + (size_t)(r0 + 8) * 2048 + col) = h1;
                    *(__half2*)(obl + (size_t)(r0 + 8) * 2048 + col) = l1;
                } else {
                    const int cs = col - 2048;
                    __half2 s0, s1;
                    s0.x = __float2half(v0); s0.y = __float2half(v1);
                    s1.x = __float2half(v2); s1.y = __float2half(v3);
                    *(__half2*)(obs + (size_t)r0 * 2048 + cs)       = s0;
                    *(__half2*)(obs + (size_t)(r0 + 8) * 2048 + cs) = s1;
                }
            } else if (MODE == 1) {
                if (col < 2048) {
                    const float b0 = bias[col], b1 = bias[col + 1];
                    *(float2*)(out0 + (size_t)r0 * ostride + col) =
                        make_float2(softplusf(v0 + b0), softplusf(v1 + b1));
                    *(float2*)(out0 + (size_t)(r0 + 8) * ostride + col) =
                        make_float2(softplusf(v2 + b0), softplusf(v3 + b1));
                } else if (col < 2080) {
                    const int n = col - 2048;
                    *(float2*)(out1 + (size_t)r0 * 32 + n)       = make_float2(v0, v1);
                    *(float2*)(out1 + (size_t)(r0 + 8) * 32 + n) = make_float2(v2, v3);
                }
            } else {
                *(float2*)(out0 + (size_t)r0 * ostride + col)       = make_float2(v0, v1);
                *(float2*)(out0 + (size_t)(r0 + 8) * ostride + col) = make_float2(v2, v3);
            }
        }
    }
}

// ---------------------------------------------------------------------------
// prep_all: weight transposes + WB/WC rows + zero pad + x->fp16 conversion
// ---------------------------------------------------------------------------
__device__ __forceinline__ void transp_tile(
    const float* __restrict__ in, __half* __restrict__ oh,
    int K, int N, int nb, int kb, int tid)
{
    __shared__ float t[32][33];
    const int n0 = nb * 32, k0 = kb * 32;
    const int tx = tid & 31, ty = tid >> 5;
#pragma unroll
    for (int i = 0; i < 32; i += 8)
        t[ty + i][tx] = in[(size_t)(k0 + ty + i) * N + n0 + tx];
    __syncthreads();
#pragma unroll
    for (int i = 0; i < 32; i += 8) {
        const int n = n0 + ty + i, k = k0 + tx;
        oh[(size_t)n * K + k] = __float2half(t[tx][ty + i]);
    }
}

__global__ void __launch_bounds__(256)
prep_all(const float* __restrict__ W_in, const float* __restrict__ W_delta,
         const float* __restrict__ W_out,
         const float* __restrict__ WB, const float* __restrict__ WC,
         const float* __restrict__ x,
         __half* __restrict__ Wi, __half* __restrict__ Wd, __half* __restrict__ Wo,
         __half* __restrict__ xh)
{
    const int blk = blockIdx.x;
    const int tid = threadIdx.x;
    if (blk < 4096) {
        transp_tile(W_in, Wi, DM, 2 * DI, blk & 127, blk >> 7, tid);
    } else if (blk < 8192) {
        const int t2 = blk - 4096;
        transp_tile(W_delta, Wd, DI, DI, t2 & 63, t2 >> 6, tid);
    } else if (blk < 10240) {
        const int t3 = blk - 8192;
        transp_tile(W_out, Wo, DI, DM, t3 & 31, t3 >> 5, tid);
    } else if (blk < 10304) {
        const int base = (blk - 10240) * 1024 + tid * 4;
#pragma unroll
        for (int i = 0; i < 4; ++i) {
            const int id = base + i;
            const int n = id >> 11;
            const int k = id & 2047;
            const float v = (n < DS) ? WB[(size_t)k * DS + n]
                                     : WC[(size_t)k * DS + (n - DS)];
            Wd[(size_t)(2048 + n) * DI + k] = __float2half(v);
        }
    } else if (blk < 10496) {
        const int base = (blk - 10304) * 1024 + tid * 4;
        __half2 z; z.x = __float2half(0.f); z.y = __float2half(0.f);
        *(__half2*)(Wd + (size_t)2080 * DI + base)     = z;
        *(__half2*)(Wd + (size_t)2080 * DI + base + 2) = z;
    } else {
        const int i = (blk - 10496) * 256 + tid;
        float4 v = ((const float4*)x)[i];
        __half2 hh0, hh1;
        hh0.x = __float2half(v.x); hh0.y = __float2half(v.y);
        hh1.x = __float2half(v.z); hh1.y = __float2half(v.w);
        ((__half2*)xh)[2*i]   = hh0;
        ((__half2*)xh)[2*i+1] = hh1;
    }
}

// ---------------------------------------------------------------------------
// Chunked scan: ONE thread per channel, 16 states in registers.
// Uniform-spacing fast path keeps only (A0, d10): a_i = a0 * r^i.
// P accumulated as sdelta (sum of deltas): P_i = exp(A_i * sdelta).
// General fallback recomputes A_i from Alog per step (never taken here,
// keeps register allocation low).
// ---------------------------------------------------------------------------
__device__ __forceinline__ float loadU(const __half* Uh, const __half* Ul, size_t i) {
    return __half2float(Uh[i]) + __half2float(Ul[i]);
}

// check uniform spacing of A-row without keeping the array; returns A0, d10
__device__ __forceinline__ bool a_uniform(const float* Alog, int d,
                                          float& A0, float& d10)
{
    A0 = -__expf(Alog[d * DS + 0]);
    float prev = -__expf(Alog[d * DS + 1]);
    d10 = prev - A0;
    bool uni = true;
#pragma unroll
    for (int i = 2; i < DS; ++i) {
        const float cur = -__expf(Alog[d * DS + i]);
        uni = uni && (fabsf((cur - prev) - d10) <= 1e-4f * fabsf(d10) + 1e-20f);
        prev = cur;
    }
    return uni;
}

__device__ __forceinline__ void chain_a(float a0, float r, float* a)
{
    const float r2 = r * r;
    const float r4 = r2 * r2;
    const float r8 = r4 * r4;
    a[0] = a0;
    a[1] = a0 * r;  a[2] = a0 * r2; a[3] = a[1] * r2;
    a[4] = a0 * r4; a[5] = a[1] * r4; a[6] = a[2] * r4; a[7] = a[3] * r4;
#pragma unroll
    for (int i = 0; i < 8; ++i) a[8 + i] = a[i] * r8;
}

__global__ void __launch_bounds__(128)
scanA(const float* __restrict__ DEL,
      const __half* __restrict__ Uh, const __half* __restrict__ Ul,
      const float* __restrict__ BC, const float* __restrict__ Alog,
      float4* __restrict__ P4, float4* __restrict__ Q4)
{
    const int c = blockIdx.y;
    const int g = blockIdx.x * 128 + threadIdx.x;   // channel 0..4095
    const int b = g >> 11;
    const int d = g & (DI - 1);

    float A0, d10;
    const bool uni = a_uniform(Alog, d, A0, d10);

    float h[DS];
#pragma unroll
    for (int i = 0; i < DS; ++i) h[i] = 0.f;

    size_t xbase = ((size_t)b * Lseq + (size_t)c * TL) * DI + d;
    size_t rbase = ((size_t)b * Lseq + (size_t)c * TL) * 32;

    if (uni) {
        float sdelta = 0.f;
#pragma unroll 2
        for (int t = 0; t < TL; ++t) {
            const float delta = DEL[xbase];
            const float uu    = loadU(Uh, Ul, xbase);
            float Bv[DS];
#pragma unroll
            for (int q = 0; q < 4; ++q)
                *(float4*)&Bv[q * 4] = *(const float4*)(BC + rbase + q * 4);

            float a[DS];
            chain_a(__expf(delta * A0), __expf(delta * d10), a);
            const float db = delta * uu;
#pragma unroll
            for (int i = 0; i < DS; ++i)
                h[i] = fmaf(a[i], h[i], db * Bv[i]);
            sdelta += delta;
            xbase += DI;
            rbase += 32;
        }
        const int idx = (((c * 2 + b) * DI) + d) * 4;
#pragma unroll
        for (int s = 0; s < 4; ++s) {
            float4 Pv;
            Pv.x = __expf(sdelta * (A0 + (4*s + 0) * d10));
            Pv.y = __expf(sdelta * (A0 + (4*s + 1) * d10));
            Pv.z = __expf(sdelta * (A0 + (4*s + 2) * d10));
            Pv.w = __expf(sdelta * (A0 + (4*s + 3) * d10));
            P4[idx + s] = Pv;
            Q4[idx + s] = make_float4(h[4*s], h[4*s+1], h[4*s+2], h[4*s+3]);
        }
    } else {
        float P[DS];
#pragma unroll
        for (int i = 0; i < DS; ++i) P[i] = 1.f;
        for (int t = 0; t < TL; ++t) {
            const float delta = DEL[xbase];
            const float uu    = loadU(Uh, Ul, xbase);
            const float db = delta * uu;
#pragma unroll
            for (int i = 0; i < DS; ++i) {
                const float Ai = -__expf(Alog[d * DS + i]);
                const float a = __expf(delta * Ai);
                h[i] = fmaf(a, h[i], db * BC[rbase + i]);
                P[i] *= a;
            }
            xbase += DI;
            rbase += 32;
        }
        const int idx = (((c * 2 + b) * DI) + d) * 4;
#pragma unroll
        for (int s = 0; s < 4; ++s) {
            P4[idx + s] = make_float4(P[4*s], P[4*s+1], P[4*s+2], P[4*s+3]);
            Q4[idx + s] = make_float4(h[4*s], h[4*s+1], h[4*s+2], h[4*s+3]);
        }
    }
}

__global__ void __launch_bounds__(256)
scanB(const float4* __restrict__ P4, const float4* __restrict__ Q4,
      float4* __restrict__ H4)
{
    const int gs = blockIdx.x * 256 + threadIdx.x;
    const int g = gs >> 2;
    const int sub = gs & 3;
    const int b = g >> 11;
    const int d = g & (DI - 1);

    float4 h = make_float4(0.f, 0.f, 0.f, 0.f);
#pragma unroll
    for (int c = 0; c < CH; ++c) {
        const int idx = (((c * 2 + b) * DI) + d) * 4 + sub;
        H4[idx] = h;
        const float4 P = P4[idx];
        const float4 q = Q4[idx];
        h.x = fmaf(P.x, h.x, q.x);
        h.y = fmaf(P.y, h.y, q.y);
        h.z = fmaf(P.z, h.z, q.z);
        h.w = fmaf(P.w, h.w, q.w);
    }
}

__global__ void __launch_bounds__(128)
scanC(const float* __restrict__ DEL,
      const __half* __restrict__ Uh, const __half* __restrict__ Ul,
      const __half* __restrict__ Sh,
      const float* __restrict__ BC,
      const float* __restrict__ Alog, const float* __restrict__ Dp,
      const float4* __restrict__ H4,
      __half* __restrict__ Yh)
{
    const int c = blockIdx.y;
    const int g = blockIdx.x * 128 + threadIdx.x;   // channel 0..4095
    const int b = g >> 11;
    const int d = g & (DI - 1);

    float A0, d10;
    const bool uni = a_uniform(Alog, d, A0, d10);
    const float Dd = Dp[d];

    const int idx = (((c * 2 + b) * DI) + d) * 4;
    float h[DS];
#pragma unroll
    for (int s = 0; s < 4; ++s) {
        const float4 hv = H4[idx + s];
        h[4*s] = hv.x; h[4*s+1] = hv.y; h[4*s+2] = hv.z; h[4*s+3] = hv.w;
    }

    size_t xbase = ((size_t)b * Lseq + (size_t)c * TL) * DI + d;
    size_t rbase = ((size_t)b * Lseq + (size_t)c * TL) * 32;

    if (uni) {
#pragma unroll 2
        for (int t = 0; t < TL; ++t) {
            const float delta = DEL[xbase];
            const float uu    = loadU(Uh, Ul, xbase);
            float Bv[DS], Cv[DS];
#pragma unroll
            for (int q = 0; q < 4; ++q) {
                *(float4*)&Bv[q * 4] = *(const float4*)(BC + rbase + q * 4);
                *(float4*)&Cv[q * 4] = *(const float4*)(BC + rbase + 16 + q * 4);
            }
            float a[DS];
            chain_a(__expf(delta * A0), __expf(delta * d10), a);
            const float db = delta * uu;
            float y0 = 0.f, y1 = 0.f, y2 = 0.f, y3 = 0.f;
#pragma unroll
            for (int i = 0; i < DS; i += 4) {
                h[i]   = fmaf(a[i],   h[i],   db * Bv[i]);
                h[i+1] = fmaf(a[i+1], h[i+1], db * Bv[i+1]);
                h[i+2] = fmaf(a[i+2], h[i+2], db * Bv[i+2]);
                h[i+3] = fmaf(a[i+3], h[i+3], db * Bv[i+3]);
                y0 = fmaf(h[i],   Cv[i],   y0);
                y1 = fmaf(h[i+1], Cv[i+1], y1);
                y2 = fmaf(h[i+2], Cv[i+2], y2);
                y3 = fmaf(h[i+3], Cv[i+3], y3);
            }
            const float yv = (((y0 + y1) + (y2 + y3)) + uu * Dd) * __half2float(Sh[xbase]);
            Yh[xbase] = __float2half(yv);
            xbase += DI;
            rbase += 32;
        }
    } else {
        for (int t = 0; t < TL; ++t) {
            const float delta = DEL[xbase];
            const float uu    = loadU(Uh, Ul, xbase);
            const float db = delta * uu;
            float yv = 0.f;
#pragma unroll
            for (int i = 0; i < DS; ++i) {
                const float Ai = -__expf(Alog[d * DS + i]);
                const float a = __expf(delta * Ai);
                h[i] = fmaf(a, h[i], db * BC[rbase + i]);
                yv = fmaf(h[i], BC[rbase + 16 + i], yv);
            }
            yv = (yv + uu * Dd) * __half2float(Sh[xbase]);
            Yh[xbase] = __float2half(yv);
            xbase += DI;
            rbase += 32;
        }
    }
}

// ---------------------------------------------------------------------------
extern "C" void kernel_launch(void* const* d_in, const int* in_sizes, int n_in,
                              void* d_out, int out_size)
{
    const float* x       = (const float*)d_in[0];
    const float* W_in    = (const float*)d_in[1];
    const float* W_delta = (const float*)d_in[2];
    const float* b_delta = (const float*)d_in[3];
    const float* W_B     = (const float*)d_in[4];
    const float* W_C     = (const float*)d_in[5];
    const float* A_log   = (const float*)d_in[6];
    const float* D_param = (const float*)d_in[7];
    const float* W_out   = (const float*)d_in[8];
    float* out = (float*)d_out;

    float *pDel, *pBC;
    __half *pSh, *pUh, *pUl, *pYh, *pxh, *pWi, *pWd, *pWo;
    float4 *pP4, *pQ4, *pH4;
    cudaGetSymbolAddress((void**)&pSh,  g_Sh);
    cudaGetSymbolAddress((void**)&pDel, g_DELTA);
    cudaGetSymbolAddress((void**)&pBC,  g_BC);
    cudaGetSymbolAddress((void**)&pUh,  g_Uh);
    cudaGetSymbolAddress((void**)&pUl,  g_Ul);
    cudaGetSymbolAddress((void**)&pYh,  g_Yh);
    cudaGetSymbolAddress((void**)&pxh,  g_xh);
    cudaGetSymbolAddress((void**)&pWi,  g_WinT);
    cudaGetSymbolAddress((void**)&pWd,  g_WdT);
    cudaGetSymbolAddress((void**)&pWo,  g_WoT);
    cudaGetSymbolAddress((void**)&pP4,  g_P4);
    cudaGetSymbolAddress((void**)&pQ4,  g_Q4);
    cudaGetSymbolAddress((void**)&pH4,  g_H4);

    cudaFuncSetAttribute((const void*)tgemm<0, false>, cudaFuncAttributeMaxDynamicSharedMemorySize, SMEM_TOT);
    cudaFuncSetAttribute((const void*)tgemm<1, true>,  cudaFuncAttributeMaxDynamicSharedMemorySize, SMEM_TOT);
    cudaFuncSetAttribute((const void*)tgemm<2, false>, cudaFuncAttributeMaxDynamicSharedMemorySize, SMEM_TOT);

    // Order: prep(1) tgemm0(2) tgemm1(3) scanA(4 <- ncu slot)
    //        scanB(5) scanC(6) tgemm2(7)
    prep_all<<<14592, 256>>>(W_in, W_delta, W_out, W_B, W_C, x,
                             pWi, pWd, pWo, pxh);

    // 1) x @ W_in -> U (silu, fp16 hi/lo) | S (silu, fp16)
    tgemm<0, false><<<dim3(2 * DI / 128, Mrows / 128), 256, SMEM_TOT>>>(
        pxh, pxh, pWi, DM, 2048, nullptr, nullptr, nullptr, pUh, pUl, pSh);

    // 2+3) DELTA = softplus(U @ W_delta + b) fused with Bm|Cm
    tgemm<1, true><<<dim3(ND / 128, Mrows / 128), 256, SMEM_TOT>>>(
        pUh, pUl, pWd, DI, DI, b_delta, pDel, pBC, nullptr, nullptr, nullptr);

    // 4) chunked selective scan -> Y (fp16)
    scanA<<<dim3(Mrows / 128, CH), 128>>>(pDel, pUh, pUl, pBC, A_log, pP4, pQ4);
    scanB<<<64, 256>>>(pP4, pQ4, pH4);
    scanC<<<dim3(Mrows / 128, CH), 128>>>(pDel, pUh, pUl, pSh, pBC, A_log,
                                          D_param, pH4, pYh);

    // 5) out = Y @ W_out   [single-term Y]
    tgemm<2, false><<<dim3(DM / 128, Mrows / 128), 256, SMEM_TOT>>>(
        pYh, pYh, pWo, DI, DM, nullptr, out, nullptr, nullptr, nullptr, nullptr);
}

// round 16
// speedup vs baseline: 3.6794x; 1.1283x over previous
#include <cuda_runtime.h>
#include <cuda_fp16.h>
#include <cstdint>

#define DM 1024
#define DI 2048
#define DS 16
#define Mrows 4096
#define Lseq 2048
#define CH 32      // chunks
#define TL 64      // timesteps per chunk
#define ND 2176    // padded N for fused delta+B+C GEMM (17 tiles of 128)

// ---------------- scratch (device globals; allocation-free) ----------------
__device__ __half g_Sh[Mrows * DI];
__device__ float g_DELTA[Mrows * DI];
__device__ float g_BC[Mrows * 32];         // [m][0..15]=Bm, [16..31]=Cm
__device__ __half g_Uh[Mrows * DI], g_Ul[Mrows * DI];
__device__ __half g_Yh[Mrows * DI];
__device__ __half g_xh[Mrows * DM];
__device__ __half g_WinT[2 * DI * DM];
__device__ __half g_WdT[ND * DI];          // rows: 0..2047 Wd^T, 2048..2079 WB^T|WC^T, rest 0
__device__ __half g_WoT[DM * DI];
__device__ float4 g_P4[CH * 2 * DI * 4];   // per-chunk decay products
__device__ float4 g_Q4[CH * 2 * DI * 4];   // per-chunk partial states
__device__ float4 g_H4[CH * 2 * DI * 4];   // chunk entry states

// ---------------- helpers ----------------
__device__ __forceinline__ float siluf(float x) { return x / (1.0f + __expf(-x)); }
__device__ __forceinline__ float softplusf(float x) {
    return (x > 20.0f) ? x : log1pf(__expf(x));
}
__device__ __forceinline__ uint32_t smem_u32(const void* p) {
    uint32_t a;
    asm("{ .reg .u64 t; cvta.to.shared.u64 t, %1; cvt.u32.u64 %0, t; }" : "=r"(a) : "l"(p));
    return a;
}
__device__ __forceinline__ void cpa16(uint32_t s, const void* g) {
    asm volatile("cp.async.cg.shared.global [%0], [%1], 16;" :: "r"(s), "l"(g));
}
__device__ __forceinline__ void cpa_commit() { asm volatile("cp.async.commit_group;"); }

__device__ __forceinline__ void ldsm4(uint32_t* r, uint32_t addr) {
    asm volatile("ldmatrix.sync.aligned.m8n8.x4.shared.b16 {%0,%1,%2,%3}, [%4];"
                 : "=r"(r[0]), "=r"(r[1]), "=r"(r[2]), "=r"(r[3]) : "r"(addr));
}
__device__ __forceinline__ void mma16816h(float* d, const uint32_t* a, const uint32_t* b) {
    asm volatile(
        "mma.sync.aligned.m16n8k16.row.col.f32.f16.f16.f32 "
        "{%0,%1,%2,%3}, {%4,%5,%6,%7}, {%8,%9}, {%0,%1,%2,%3};\n"
        : "+f"(d[0]), "+f"(d[1]), "+f"(d[2]), "+f"(d[3])
        : "r"(a[0]), "r"(a[1]), "r"(a[2]), "r"(a[3]), "r"(b[0]), "r"(b[1]));
}

#define TPAD 144
#define TILE_B (128 * TPAD)
#define STAGE_B (3 * TILE_B)
#define NSTAGE 2
#define SMEM_TOT (NSTAGE * STAGE_B)  // 110592 -> 2 CTAs/SM

template <bool SPLIT2>
__device__ __forceinline__ void load_chunk(
    const __half* __restrict__ Ah, const __half* __restrict__ Al,
    const __half* __restrict__ B,
    int m0, int n0, int kc, int Kdim, uint32_t sb, int tid, bool active)
{
    if (active) {
#pragma unroll
        for (int j = 0; j < 12; ++j) {
            const int g = j * 256 + tid;
            const int tile = g >> 10;
            if (!SPLIT2 && tile == 1) continue;
            const int w = g & 1023;
            const int row = w >> 3;
            const int col16 = w & 7;
            const __half* base = (tile == 0) ? Ah : (tile == 1) ? Al : B;
            const int r0 = (tile == 2) ? n0 : m0;
            const __half* src = base + (size_t)(r0 + row) * Kdim + kc + col16 * 8;
            cpa16(sb + (uint32_t)(tile * TILE_B + row * TPAD + col16 * 16),
                  (const void*)src);
        }
    }
    cpa_commit();
}

// ---------------------------------------------------------------------------
// HMMA fp16 GEMM: C[M,N] = A[M,K] * B[N,K]^T  (fp32 accum)
// SPLIT2: C ~= Ah*B + Al*B ; else C = Ah*B.  nofs = column offset for grid.x.
// MODE 0: col<2048 -> U=silu -> (obh,obl) fp16 split; else S=silu -> obs (fp16)
// MODE 1: col<2048 -> softplus(c+bias) -> out0(DELTA); col in [2048,2080) -> BC
// MODE 2: plain -> out0
// ---------------------------------------------------------------------------
template <int MODE, bool SPLIT2>
__global__ void __launch_bounds__(256, 2)
tgemm(const __half* __restrict__ Ah, const __half* __restrict__ Al,
      const __half* __restrict__ B,
      int Kdim, int ostride, int nofs,
      const float* __restrict__ bias,
      float* __restrict__ out0, float* __restrict__ out1,
      __half* __restrict__ obh, __half* __restrict__ obl,
      __half* __restrict__ obs)
{
    extern __shared__ char smem[];
    const uint32_t sb = smem_u32(smem);

    const int tid  = threadIdx.x;
    const int lane = tid & 31;
    const int wid  = tid >> 5;
    const int wm   = wid & 3;
    const int wn   = wid >> 2;
    const int m0 = blockIdx.y * 128;
    const int n0 = blockIdx.x * 128 + nofs;

    const uint32_t a_off =
        (uint32_t)(wm * 32 + (lane & 15)) * TPAD + (uint32_t)((lane >> 4) * 16);
    const int p = lane >> 3;
    const uint32_t b_off =
        (uint32_t)(wn * 64 + (p >> 1) * 8 + (lane & 7)) * TPAD + (uint32_t)((p & 1) * 16);

    float acc[2][8][4];
#pragma unroll
    for (int i = 0; i < 2; ++i)
#pragma unroll
        for (int j = 0; j < 8; ++j)
#pragma unroll
            for (int q = 0; q < 4; ++q) acc[i][j][q] = 0.0f;

    const int NC = Kdim >> 6;

    load_chunk<SPLIT2>(Ah, Al, B, m0, n0, 0, Kdim, sb, tid, 0 < NC);

    for (int c = 0; c < NC; ++c) {
        asm volatile("cp.async.wait_group 0;" ::: "memory");
        __syncthreads();

        load_chunk<SPLIT2>(Ah, Al, B, m0, n0, (c + 1) * 64, Kdim,
                           sb + (uint32_t)((c + 1) & 1) * STAGE_B, tid, (c + 1) < NC);

        const uint32_t st = sb + (uint32_t)(c & 1) * STAGE_B;
        const uint32_t smAh = st;
        const uint32_t smAl = st + TILE_B;
        const uint32_t smB  = st + 2 * TILE_B;

#pragma unroll
        for (int k16 = 0; k16 < 4; ++k16) {
            const uint32_t kb = (uint32_t)(k16 * 32);
            uint32_t ah[2][4], al[2][4], bf[4][4];
#pragma unroll
            for (int mt = 0; mt < 2; ++mt) {
                ldsm4(ah[mt], smAh + kb + a_off + (uint32_t)(mt * 16 * TPAD));
                if (SPLIT2)
                    ldsm4(al[mt], smAl + kb + a_off + (uint32_t)(mt * 16 * TPAD));
            }
#pragma unroll
            for (int p2 = 0; p2 < 4; ++p2)
                ldsm4(bf[p2], smB + kb + b_off + (uint32_t)(p2 * 16 * TPAD));
#pragma unroll
            for (int mt = 0; mt < 2; ++mt)
#pragma unroll
                for (int nt = 0; nt < 8; ++nt)
                    mma16816h(acc[mt][nt], ah[mt], &bf[nt >> 1][(nt & 1) * 2]);
            if (SPLIT2) {
#pragma unroll
                for (int mt = 0; mt < 2; ++mt)
#pragma unroll
                    for (int nt = 0; nt < 8; ++nt)
                        mma16816h(acc[mt][nt], al[mt], &bf[nt >> 1][(nt & 1) * 2]);
            }
        }
    }

    __syncthreads();

    const int g2 = lane >> 2;
    const int c2 = (lane & 3) * 2;
#pragma unroll
    for (int mt = 0; mt < 2; ++mt) {
        const int r0 = m0 + wm * 32 + mt * 16 + g2;
#pragma unroll
        for (int nt = 0; nt < 8; ++nt) {
            const int col = n0 + wn * 64 + nt * 8 + c2;
            float v0 = acc[mt][nt][0], v1 = acc[mt][nt][1];
            float v2 = acc[mt][nt][2], v3 = acc[mt][nt][3];

            if (MODE == 0) {
                v0 = siluf(v0); v1 = siluf(v1); v2 = siluf(v2); v3 = siluf(v3);
                if (col < 2048) {
                    __half2 h0, l0, h1, l1;
                    h0.x = __float2half(v0); h0.y = __float2half(v1);
                    l0.x = __float2half(v0 - __half2float(h0.x));
                    l0.y = __float2half(v1 - __half2float(h0.y));
                    h1.x = __float2half(v2); h1.y = __float2half(v3);
                    l1.x = __float2half(v2 - __half2float(h1.x));
                    l1.y = __float2half(v3 - __half2float(h1.y));
                    *(__half2*)(obh + (size_t)r0 * 2048 + col)       = h0;
                    *(__half2*)(obl + (size_t)r0 * 2048 + col)       = l0;
                    *(__half2*)(obh + (size_t)(r0 + 8) * 2048 + col) = h1;
                    *(__half2*)(obl + (size_t)(r0 + 8) * 2048 + col) = l1;
                } else {
                    const int cs = col - 2048;
                    __half2 s0, s1;
                    s0.x = __float2half(v0); s0.y = __float2half(v1);
                    s1.x = __float2half(v2); s1.y = __float2half(v3);
                    *(__half2*)(obs + (size_t)r0 * 2048 + cs)       = s0;
                    *(__half2*)(obs + (size_t)(r0 + 8) * 2048 + cs) = s1;
                }
            } else if (MODE == 1) {
                if (col < 2048) {
                    const float b0 = bias[col], b1 = bias[col + 1];
                    *(float2*)(out0 + (size_t)r0 * ostride + col) =
                        make_float2(softplusf(v0 + b0), softplusf(v1 + b1));
                    *(float2*)(out0 + (size_t)(r0 + 8) * ostride + col) =
                        make_float2(softplusf(v2 + b0), softplusf(v3 + b1));
                } else if (col < 2080) {
                    const int n = col - 2048;
                    *(float2*)(out1 + (size_t)r0 * 32 + n)       = make_float2(v0, v1);
                    *(float2*)(out1 + (size_t)(r0 + 8) * 32 + n) = make_float2(v2, v3);
                }
            } else {
                *(float2*)(out0 + (size_t)r0 * ostride + col)       = make_float2(v0, v1);
                *(float2*)(out0 + (size_t)(r0 + 8) * ostride + col) = make_float2(v2, v3);
            }
        }
    }
}

// ---------------------------------------------------------------------------
// prep_all: weight transposes + WB/WC rows + zero pad + x->fp16 conversion
// ---------------------------------------------------------------------------
__device__ __forceinline__ void transp_tile(
    const float* __restrict__ in, __half* __restrict__ oh,
    int K, int N, int nb, int kb, int tid)
{
    __shared__ float t[32][33];
    const int n0 = nb * 32, k0 = kb * 32;
    const int tx = tid & 31, ty = tid >> 5;
#pragma unroll
    for (int i = 0; i < 32; i += 8)
        t[ty + i][tx] = in[(size_t)(k0 + ty + i) * N + n0 + tx];
    __syncthreads();
#pragma unroll
    for (int i = 0; i < 32; i += 8) {
        const int n = n0 + ty + i, k = k0 + tx;
        oh[(size_t)n * K + k] = __float2half(t[tx][ty + i]);
    }
}

__global__ void __launch_bounds__(256)
prep_all(const float* __restrict__ W_in, const float* __restrict__ W_delta,
         const float* __restrict__ W_out,
         const float* __restrict__ WB, const float* __restrict__ WC,
         const float* __restrict__ x,
         __half* __restrict__ Wi, __half* __restrict__ Wd, __half* __restrict__ Wo,
         __half* __restrict__ xh)
{
    const int blk = blockIdx.x;
    const int tid = threadIdx.x;
    if (blk < 4096) {
        transp_tile(W_in, Wi, DM, 2 * DI, blk & 127, blk >> 7, tid);
    } else if (blk < 8192) {
        const int t2 = blk - 4096;
        transp_tile(W_delta, Wd, DI, DI, t2 & 63, t2 >> 6, tid);
    } else if (blk < 10240) {
        const int t3 = blk - 8192;
        transp_tile(W_out, Wo, DI, DM, t3 & 31, t3 >> 5, tid);
    } else if (blk < 10304) {
        const int base = (blk - 10240) * 1024 + tid * 4;
#pragma unroll
        for (int i = 0; i < 4; ++i) {
            const int id = base + i;
            const int n = id >> 11;
            const int k = id & 2047;
            const float v = (n < DS) ? WB[(size_t)k * DS + n]
                                     : WC[(size_t)k * DS + (n - DS)];
            Wd[(size_t)(2048 + n) * DI + k] = __float2half(v);
        }
    } else if (blk < 10496) {
        const int base = (blk - 10304) * 1024 + tid * 4;
        __half2 z; z.x = __float2half(0.f); z.y = __float2half(0.f);
        *(__half2*)(Wd + (size_t)2080 * DI + base)     = z;
        *(__half2*)(Wd + (size_t)2080 * DI + base + 2) = z;
    } else {
        const int i = (blk - 10496) * 256 + tid;
        float4 v = ((const float4*)x)[i];
        __half2 hh0, hh1;
        hh0.x = __float2half(v.x); hh0.y = __float2half(v.y);
        hh1.x = __float2half(v.z); hh1.y = __float2half(v.w);
        ((__half2*)xh)[2*i]   = hh0;
        ((__half2*)xh)[2*i+1] = hh1;
    }
}

// ---------------------------------------------------------------------------
// Chunked scan: ONE thread per channel, 16 states in registers.
// ---------------------------------------------------------------------------
__device__ __forceinline__ float loadU(const __half* Uh, const __half* Ul, size_t i) {
    return __half2float(Uh[i]) + __half2float(Ul[i]);
}

__device__ __forceinline__ bool a_uniform(const float* Alog, int d,
                                          float& A0, float& d10)
{
    A0 = -__expf(Alog[d * DS + 0]);
    float prev = -__expf(Alog[d * DS + 1]);
    d10 = prev - A0;
    bool uni = true;
#pragma unroll
    for (int i = 2; i < DS; ++i) {
        const float cur = -__expf(Alog[d * DS + i]);
        uni = uni && (fabsf((cur - prev) - d10) <= 1e-4f * fabsf(d10) + 1e-20f);
        prev = cur;
    }
    return uni;
}

__device__ __forceinline__ void chain_a(float a0, float r, float* a)
{
    const float r2 = r * r;
    const float r4 = r2 * r2;
    const float r8 = r4 * r4;
    a[0] = a0;
    a[1] = a0 * r;  a[2] = a0 * r2; a[3] = a[1] * r2;
    a[4] = a0 * r4; a[5] = a[1] * r4; a[6] = a[2] * r4; a[7] = a[3] * r4;
#pragma unroll
    for (int i = 0; i < 8; ++i) a[8 + i] = a[i] * r8;
}

__global__ void __launch_bounds__(128)
scanA(const float* __restrict__ DEL,
      const __half* __restrict__ Uh, const __half* __restrict__ Ul,
      const float* __restrict__ BC, const float* __restrict__ Alog,
      float4* __restrict__ P4, float4* __restrict__ Q4)
{
    const int c = blockIdx.y;
    const int g = blockIdx.x * 128 + threadIdx.x;
    const int b = g >> 11;
    const int d = g & (DI - 1);

    float A0, d10;
    const bool uni = a_uniform(Alog, d, A0, d10);

    float h[DS];
#pragma unroll
    for (int i = 0; i < DS; ++i) h[i] = 0.f;

    size_t xbase = ((size_t)b * Lseq + (size_t)c * TL) * DI + d;
    size_t rbase = ((size_t)b * Lseq + (size_t)c * TL) * 32;

    if (uni) {
        float sdelta = 0.f;
#pragma unroll 2
        for (int t = 0; t < TL; ++t) {
            const float delta = DEL[xbase];
            const float uu    = loadU(Uh, Ul, xbase);
            float Bv[DS];
#pragma unroll
            for (int q = 0; q < 4; ++q)
                *(float4*)&Bv[q * 4] = *(const float4*)(BC + rbase + q * 4);

            float a[DS];
            chain_a(__expf(delta * A0), __expf(delta * d10), a);
            const float db = delta * uu;
#pragma unroll
            for (int i = 0; i < DS; ++i)
                h[i] = fmaf(a[i], h[i], db * Bv[i]);
            sdelta += delta;
            xbase += DI;
            rbase += 32;
        }
        const int idx = (((c * 2 + b) * DI) + d) * 4;
#pragma unroll
        for (int s = 0; s < 4; ++s) {
            float4 Pv;
            Pv.x = __expf(sdelta * (A0 + (4*s + 0) * d10));
            Pv.y = __expf(sdelta * (A0 + (4*s + 1) * d10));
            Pv.z = __expf(sdelta * (A0 + (4*s + 2) * d10));
            Pv.w = __expf(sdelta * (A0 + (4*s + 3) * d10));
            P4[idx + s] = Pv;
            Q4[idx + s] = make_float4(h[4*s], h[4*s+1], h[4*s+2], h[4*s+3]);
        }
    } else {
        float P[DS];
#pragma unroll
        for (int i = 0; i < DS; ++i) P[i] = 1.f;
        for (int t = 0; t < TL; ++t) {
            const float delta = DEL[xbase];
            const float uu    = loadU(Uh, Ul, xbase);
            const float db = delta * uu;
#pragma unroll
            for (int i = 0; i < DS; ++i) {
                const float Ai = -__expf(Alog[d * DS + i]);
                const float a = __expf(delta * Ai);
                h[i] = fmaf(a, h[i], db * BC[rbase + i]);
                P[i] *= a;
            }
            xbase += DI;
            rbase += 32;
        }
        const int idx = (((c * 2 + b) * DI) + d) * 4;
#pragma unroll
        for (int s = 0; s < 4; ++s) {
            P4[idx + s] = make_float4(P[4*s], P[4*s+1], P[4*s+2], P[4*s+3]);
            Q4[idx + s] = make_float4(h[4*s], h[4*s+1], h[4*s+2], h[4*s+3]);
        }
    }
}

__global__ void __launch_bounds__(256)
scanB(const float4* __restrict__ P4, const float4* __restrict__ Q4,
      float4* __restrict__ H4)
{
    const int gs = blockIdx.x * 256 + threadIdx.x;
    const int g = gs >> 2;
    const int sub = gs & 3;
    const int b = g >> 11;
    const int d = g & (DI - 1);

    float4 h = make_float4(0.f, 0.f, 0.f, 0.f);
#pragma unroll
    for (int c = 0; c < CH; ++c) {
        const int idx = (((c * 2 + b) * DI) + d) * 4 + sub;
        H4[idx] = h;
        const float4 P = P4[idx];
        const float4 q = Q4[idx];
        h.x = fmaf(P.x, h.x, q.x);
        h.y = fmaf(P.y, h.y, q.y);
        h.z = fmaf(P.z, h.z, q.z);
        h.w = fmaf(P.w, h.w, q.w);
    }
}

__global__ void __launch_bounds__(128)
scanC(const float* __restrict__ DEL,
      const __half* __restrict__ Uh, const __half* __restrict__ Ul,
      const __half* __restrict__ Sh,
      const float* __restrict__ BC,
      const float* __restrict__ Alog, const float* __restrict__ Dp,
      const float4* __restrict__ H4,
      __half* __restrict__ Yh)
{
    const int c = blockIdx.y;
    const int g = blockIdx.x * 128 + threadIdx.x;
    const int b = g >> 11;
    const int d = g & (DI - 1);

    float A0, d10;
    const bool uni = a_uniform(Alog, d, A0, d10);
    const float Dd = Dp[d];

    const int idx = (((c * 2 + b) * DI) + d) * 4;
    float h[DS];
#pragma unroll
    for (int s = 0; s < 4; ++s) {
        const float4 hv = H4[idx + s];
        h[4*s] = hv.x; h[4*s+1] = hv.y; h[4*s+2] = hv.z; h[4*s+3] = hv.w;
    }

    size_t xbase = ((size_t)b * Lseq + (size_t)c * TL) * DI + d;
    size_t rbase = ((size_t)b * Lseq + (size_t)c * TL) * 32;

    if (uni) {
#pragma unroll 2
        for (int t = 0; t < TL; ++t) {
            const float delta = DEL[xbase];
            const float uu    = loadU(Uh, Ul, xbase);
            float Bv[DS], Cv[DS];
#pragma unroll
            for (int q = 0; q < 4; ++q) {
                *(float4*)&Bv[q * 4] = *(const float4*)(BC + rbase + q * 4);
                *(float4*)&Cv[q * 4] = *(const float4*)(BC + rbase + 16 + q * 4);
            }
            float a[DS];
            chain_a(__expf(delta * A0), __expf(delta * d10), a);
            const float db = delta * uu;
            float y0 = 0.f, y1 = 0.f, y2 = 0.f, y3 = 0.f;
#pragma unroll
            for (int i = 0; i < DS; i += 4) {
                h[i]   = fmaf(a[i],   h[i],   db * Bv[i]);
                h[i+1] = fmaf(a[i+1], h[i+1], db * Bv[i+1]);
                h[i+2] = fmaf(a[i+2], h[i+2], db * Bv[i+2]);
                h[i+3] = fmaf(a[i+3], h[i+3], db * Bv[i+3]);
                y0 = fmaf(h[i],   Cv[i],   y0);
                y1 = fmaf(h[i+1], Cv[i+1], y1);
                y2 = fmaf(h[i+2], Cv[i+2], y2);
                y3 = fmaf(h[i+3], Cv[i+3], y3);
            }
            const float yv = (((y0 + y1) + (y2 + y3)) + uu * Dd) * __half2float(Sh[xbase]);
            Yh[xbase] = __float2half(yv);
            xbase += DI;
            rbase += 32;
        }
    } else {
        for (int t = 0; t < TL; ++t) {
            const float delta = DEL[xbase];
            const float uu    = loadU(Uh, Ul, xbase);
            const float db = delta * uu;
            float yv = 0.f;
#pragma unroll
            for (int i = 0; i < DS; ++i) {
                const float Ai = -__expf(Alog[d * DS + i]);
                const float a = __expf(delta * Ai);
                h[i] = fmaf(a, h[i], db * BC[rbase + i]);
                yv = fmaf(h[i], BC[rbase + 16 + i], yv);
            }
            yv = (yv + uu * Dd) * __half2float(Sh[xbase]);
            Yh[xbase] = __float2half(yv);
            xbase += DI;
            rbase += 32;
        }
    }
}

// ---------------------------------------------------------------------------
extern "C" void kernel_launch(void* const* d_in, const int* in_sizes, int n_in,
                              void* d_out, int out_size)
{
    const float* x       = (const float*)d_in[0];
    const float* W_in    = (const float*)d_in[1];
    const float* W_delta = (const float*)d_in[2];
    const float* b_delta = (const float*)d_in[3];
    const float* W_B     = (const float*)d_in[4];
    const float* W_C     = (const float*)d_in[5];
    const float* A_log   = (const float*)d_in[6];
    const float* D_param = (const float*)d_in[7];
    const float* W_out   = (const float*)d_in[8];
    float* out = (float*)d_out;

    float *pDel, *pBC;
    __half *pSh, *pUh, *pUl, *pYh, *pxh, *pWi, *pWd, *pWo;
    float4 *pP4, *pQ4, *pH4;
    cudaGetSymbolAddress((void**)&pSh,  g_Sh);
    cudaGetSymbolAddress((void**)&pDel, g_DELTA);
    cudaGetSymbolAddress((void**)&pBC,  g_BC);
    cudaGetSymbolAddress((void**)&pUh,  g_Uh);
    cudaGetSymbolAddress((void**)&pUl,  g_Ul);
    cudaGetSymbolAddress((void**)&pYh,  g_Yh);
    cudaGetSymbolAddress((void**)&pxh,  g_xh);
    cudaGetSymbolAddress((void**)&pWi,  g_WinT);
    cudaGetSymbolAddress((void**)&pWd,  g_WdT);
    cudaGetSymbolAddress((void**)&pWo,  g_WoT);
    cudaGetSymbolAddress((void**)&pP4,  g_P4);
    cudaGetSymbolAddress((void**)&pQ4,  g_Q4);
    cudaGetSymbolAddress((void**)&pH4,  g_H4);

    cudaFuncSetAttribute((const void*)tgemm<0, false>, cudaFuncAttributeMaxDynamicSharedMemorySize, SMEM_TOT);
    cudaFuncSetAttribute((const void*)tgemm<1, false>, cudaFuncAttributeMaxDynamicSharedMemorySize, SMEM_TOT);
    cudaFuncSetAttribute((const void*)tgemm<2, false>, cudaFuncAttributeMaxDynamicSharedMemorySize, SMEM_TOT);

    // Order: prep(1) tgemm0U(2) tgemm0S(3) tgemm1(4 <- ncu slot)
    //        scanA(5) scanB(6) scanC(7) tgemm2(8)
    prep_all<<<14592, 256>>>(W_in, W_delta, W_out, W_B, W_C, x,
                             pWi, pWd, pWo, pxh);

    // 1a) x @ W_in[:, :2048] -> U (silu, fp16 hi/lo)
    tgemm<0, false><<<dim3(16, Mrows / 128), 256, SMEM_TOT>>>(
        pxh, pxh, pWi, DM, 2048, 0, nullptr, nullptr, nullptr, pUh, pUl, pSh);

    // 1b) x @ W_in[:, 2048:] -> S (silu, fp16)
    tgemm<0, false><<<dim3(16, Mrows / 128), 256, SMEM_TOT>>>(
        pxh, pxh, pWi, DM, 2048, 2048, nullptr, nullptr, nullptr, pUh, pUl, pSh);

    // 2+3) DELTA = softplus(Uh @ W_delta + b) fused with Bm|Cm [single-term]
    tgemm<1, false><<<dim3(ND / 128, Mrows / 128), 256, SMEM_TOT>>>(
        pUh, pUh, pWd, DI, DI, 0, b_delta, pDel, pBC, nullptr, nullptr, nullptr);

    // 4) chunked selective scan -> Y (fp16)   [scans keep 2-term U]
    scanA<<<dim3(Mrows / 128, CH), 128>>>(pDel, pUh, pUl, pBC, A_log, pP4, pQ4);
    scanB<<<64, 256>>>(pP4, pQ4, pH4);
    scanC<<<dim3(Mrows / 128, CH), 128>>>(pDel, pUh, pUl, pSh, pBC, A_log,
                                          D_param, pH4, pYh);

    // 5) out = Y @ W_out   [single-term Y]
    tgemm<2, false><<<dim3(DM / 128, Mrows / 128), 256, SMEM_TOT>>>(
        pYh, pYh, pWo, DI, DM, 0, nullptr, out, nullptr, nullptr, nullptr, nullptr);
}

// round 17
// speedup vs baseline: 3.9832x; 1.0826x over previous
#include <cuda_runtime.h>
#include <cuda_fp16.h>
#include <cstdint>

#define DM 1024
#define DI 2048
#define DS 16
#define Mrows 4096
#define Lseq 2048
#define CH 32      // chunks
#define TL 64      // timesteps per chunk
#define ND 2176    // padded N for fused delta+B+C GEMM (17 tiles of 128)

// ---------------- scratch (device globals; allocation-free) ----------------
__device__ __half g_Sh[Mrows * DI];
__device__ __half g_Dh[Mrows * DI];        // DELTA (fp16)
__device__ float g_BC[Mrows * 32];         // [m][0..15]=Bm, [16..31]=Cm
__device__ __half g_Uh[Mrows * DI];
__device__ __half g_Yh[Mrows * DI];
__device__ __half g_xh[Mrows * DM];
__device__ __half g_WinT[2 * DI * DM];
__device__ __half g_WdT[ND * DI];          // rows: 0..2047 Wd^T, 2048..2079 WB^T|WC^T, rest 0
__device__ __half g_WoT[DM * DI];
__device__ float4 g_P4[CH * 2 * DI * 4];   // per-chunk decay products
__device__ float4 g_Q4[CH * 2 * DI * 4];   // per-chunk partial states
__device__ float4 g_H4[CH * 2 * DI * 4];   // chunk entry states

// ---------------- helpers ----------------
__device__ __forceinline__ float siluf(float x) { return x / (1.0f + __expf(-x)); }
__device__ __forceinline__ float softplusf(float x) {
    return (x > 20.0f) ? x : log1pf(__expf(x));
}
__device__ __forceinline__ uint32_t smem_u32(const void* p) {
    uint32_t a;
    asm("{ .reg .u64 t; cvta.to.shared.u64 t, %1; cvt.u32.u64 %0, t; }" : "=r"(a) : "l"(p));
    return a;
}
__device__ __forceinline__ void cpa16(uint32_t s, const void* g) {
    asm volatile("cp.async.cg.shared.global [%0], [%1], 16;" :: "r"(s), "l"(g));
}
__device__ __forceinline__ void cpa_commit() { asm volatile("cp.async.commit_group;"); }

__device__ __forceinline__ void ldsm4(uint32_t* r, uint32_t addr) {
    asm volatile("ldmatrix.sync.aligned.m8n8.x4.shared.b16 {%0,%1,%2,%3}, [%4];"
                 : "=r"(r[0]), "=r"(r[1]), "=r"(r[2]), "=r"(r[3]) : "r"(addr));
}
__device__ __forceinline__ void mma16816h(float* d, const uint32_t* a, const uint32_t* b) {
    asm volatile(
        "mma.sync.aligned.m16n8k16.row.col.f32.f16.f16.f32 "
        "{%0,%1,%2,%3}, {%4,%5,%6,%7}, {%8,%9}, {%0,%1,%2,%3};\n"
        : "+f"(d[0]), "+f"(d[1]), "+f"(d[2]), "+f"(d[3])
        : "r"(a[0]), "r"(a[1]), "r"(a[2]), "r"(a[3]), "r"(b[0]), "r"(b[1]));
}

#define TPAD 144
#define TILE_B (128 * TPAD)
#define STAGE_B (3 * TILE_B)
#define NSTAGE 2
#define SMEM_TOT (NSTAGE * STAGE_B)  // 110592 -> 2 CTAs/SM

__device__ __forceinline__ void load_chunk1(
    const __half* __restrict__ Ah, const __half* __restrict__ B,
    int m0, int n0, int kc, int Kdim, uint32_t sb, int tid, bool active)
{
    if (active) {
#pragma unroll
        for (int j = 0; j < 12; ++j) {
            const int g = j * 256 + tid;
            const int tile = g >> 10;
            if (tile == 1) continue;   // Al slot unused (single-term)
            const int w = g & 1023;
            const int row = w >> 3;
            const int col16 = w & 7;
            const __half* base = (tile == 0) ? Ah : B;
            const int r0 = (tile == 2) ? n0 : m0;
            const __half* src = base + (size_t)(r0 + row) * Kdim + kc + col16 * 8;
            cpa16(sb + (uint32_t)(tile * TILE_B + row * TPAD + col16 * 16),
                  (const void*)src);
        }
    }
    cpa_commit();
}

// ---------------------------------------------------------------------------
// HMMA fp16 GEMM: C[M,N] = A[M,K] * B[N,K]^T  (fp32 accum), single-term A.
// MODE 0: col<2048 -> U=silu -> obh (fp16); else S=silu -> obs (fp16)
// MODE 1: col<2048 -> softplus(c+bias) -> obh (fp16 DELTA); [2048,2080) -> BC
// MODE 2: plain fp32 -> out0
// ---------------------------------------------------------------------------
template <int MODE>
__global__ void __launch_bounds__(256, 2)
tgemm(const __half* __restrict__ Ah, const __half* __restrict__ B,
      int Kdim, int ostride, int nofs,
      const float* __restrict__ bias,
      float* __restrict__ out0, float* __restrict__ out1,
      __half* __restrict__ obh, __half* __restrict__ obs)
{
    extern __shared__ char smem[];
    const uint32_t sb = smem_u32(smem);

    const int tid  = threadIdx.x;
    const int lane = tid & 31;
    const int wid  = tid >> 5;
    const int wm   = wid & 3;
    const int wn   = wid >> 2;
    const int m0 = blockIdx.y * 128;
    const int n0 = blockIdx.x * 128 + nofs;

    const uint32_t a_off =
        (uint32_t)(wm * 32 + (lane & 15)) * TPAD + (uint32_t)((lane >> 4) * 16);
    const int p = lane >> 3;
    const uint32_t b_off =
        (uint32_t)(wn * 64 + (p >> 1) * 8 + (lane & 7)) * TPAD + (uint32_t)((p & 1) * 16);

    float acc[2][8][4];
#pragma unroll
    for (int i = 0; i < 2; ++i)
#pragma unroll
        for (int j = 0; j < 8; ++j)
#pragma unroll
            for (int q = 0; q < 4; ++q) acc[i][j][q] = 0.0f;

    const int NC = Kdim >> 6;

    load_chunk1(Ah, B, m0, n0, 0, Kdim, sb, tid, 0 < NC);

    for (int c = 0; c < NC; ++c) {
        asm volatile("cp.async.wait_group 0;" ::: "memory");
        __syncthreads();

        load_chunk1(Ah, B, m0, n0, (c + 1) * 64, Kdim,
                    sb + (uint32_t)((c + 1) & 1) * STAGE_B, tid, (c + 1) < NC);

        const uint32_t st = sb + (uint32_t)(c & 1) * STAGE_B;
        const uint32_t smAh = st;
        const uint32_t smB  = st + 2 * TILE_B;

#pragma unroll
        for (int k16 = 0; k16 < 4; ++k16) {
            const uint32_t kb = (uint32_t)(k16 * 32);
            uint32_t ah[2][4], bf[4][4];
#pragma unroll
            for (int mt = 0; mt < 2; ++mt)
                ldsm4(ah[mt], smAh + kb + a_off + (uint32_t)(mt * 16 * TPAD));
#pragma unroll
            for (int p2 = 0; p2 < 4; ++p2)
                ldsm4(bf[p2], smB + kb + b_off + (uint32_t)(p2 * 16 * TPAD));
#pragma unroll
            for (int mt = 0; mt < 2; ++mt)
#pragma unroll
                for (int nt = 0; nt < 8; ++nt)
                    mma16816h(acc[mt][nt], ah[mt], &bf[nt >> 1][(nt & 1) * 2]);
        }
    }

    __syncthreads();

    const int g2 = lane >> 2;
    const int c2 = (lane & 3) * 2;
#pragma unroll
    for (int mt = 0; mt < 2; ++mt) {
        const int r0 = m0 + wm * 32 + mt * 16 + g2;
#pragma unroll
        for (int nt = 0; nt < 8; ++nt) {
            const int col = n0 + wn * 64 + nt * 8 + c2;
            float v0 = acc[mt][nt][0], v1 = acc[mt][nt][1];
            float v2 = acc[mt][nt][2], v3 = acc[mt][nt][3];

            if (MODE == 0) {
                v0 = siluf(v0); v1 = siluf(v1); v2 = siluf(v2); v3 = siluf(v3);
                __half* dst;
                int cc;
                if (col < 2048) { dst = obh; cc = col; }
                else            { dst = obs; cc = col - 2048; }
                __half2 s0, s1;
                s0.x = __float2half(v0); s0.y = __float2half(v1);
                s1.x = __float2half(v2); s1.y = __float2half(v3);
                *(__half2*)(dst + (size_t)r0 * 2048 + cc)       = s0;
                *(__half2*)(dst + (size_t)(r0 + 8) * 2048 + cc) = s1;
            } else if (MODE == 1) {
                if (col < 2048) {
                    const float b0 = bias[col], b1 = bias[col + 1];
                    __half2 d0, d1;
                    d0.x = __float2half(softplusf(v0 + b0));
                    d0.y = __float2half(softplusf(v1 + b1));
                    d1.x = __float2half(softplusf(v2 + b0));
                    d1.y = __float2half(softplusf(v3 + b1));
                    *(__half2*)(obh + (size_t)r0 * 2048 + col)       = d0;
                    *(__half2*)(obh + (size_t)(r0 + 8) * 2048 + col) = d1;
                } else if (col < 2080) {
                    const int n = col - 2048;
                    *(float2*)(out1 + (size_t)r0 * 32 + n)       = make_float2(v0, v1);
                    *(float2*)(out1 + (size_t)(r0 + 8) * 32 + n) = make_float2(v2, v3);
                }
            } else {
                *(float2*)(out0 + (size_t)r0 * ostride + col)       = make_float2(v0, v1);
                *(float2*)(out0 + (size_t)(r0 + 8) * ostride + col) = make_float2(v2, v3);
            }
        }
    }
}

// ---------------------------------------------------------------------------
// prep_all: weight transposes + WB/WC rows + zero pad + x->fp16 conversion
// ---------------------------------------------------------------------------
__device__ __forceinline__ void transp_tile(
    const float* __restrict__ in, __half* __restrict__ oh,
    int K, int N, int nb, int kb, int tid)
{
    __shared__ float t[32][33];
    const int n0 = nb * 32, k0 = kb * 32;
    const int tx = tid & 31, ty = tid >> 5;
#pragma unroll
    for (int i = 0; i < 32; i += 8)
        t[ty + i][tx] = in[(size_t)(k0 + ty + i) * N + n0 + tx];
    __syncthreads();
#pragma unroll
    for (int i = 0; i < 32; i += 8) {
        const int n = n0 + ty + i, k = k0 + tx;
        oh[(size_t)n * K + k] = __float2half(t[tx][ty + i]);
    }
}

__global__ void __launch_bounds__(256)
prep_all(const float* __restrict__ W_in, const float* __restrict__ W_delta,
         const float* __restrict__ W_out,
         const float* __restrict__ WB, const float* __restrict__ WC,
         const float* __restrict__ x,
         __half* __restrict__ Wi, __half* __restrict__ Wd, __half* __restrict__ Wo,
         __half* __restrict__ xh)
{
    const int blk = blockIdx.x;
    const int tid = threadIdx.x;
    if (blk < 4096) {
        transp_tile(W_in, Wi, DM, 2 * DI, blk & 127, blk >> 7, tid);
    } else if (blk < 8192) {
        const int t2 = blk - 4096;
        transp_tile(W_delta, Wd, DI, DI, t2 & 63, t2 >> 6, tid);
    } else if (blk < 10240) {
        const int t3 = blk - 8192;
        transp_tile(W_out, Wo, DI, DM, t3 & 31, t3 >> 5, tid);
    } else if (blk < 10304) {
        const int base = (blk - 10240) * 1024 + tid * 4;
#pragma unroll
        for (int i = 0; i < 4; ++i) {
            const int id = base + i;
            const int n = id >> 11;
            const int k = id & 2047;
            const float v = (n < DS) ? WB[(size_t)k * DS + n]
                                     : WC[(size_t)k * DS + (n - DS)];
            Wd[(size_t)(2048 + n) * DI + k] = __float2half(v);
        }
    } else if (blk < 10496) {
        const int base = (blk - 10304) * 1024 + tid * 4;
        __half2 z; z.x = __float2half(0.f); z.y = __float2half(0.f);
        *(__half2*)(Wd + (size_t)2080 * DI + base)     = z;
        *(__half2*)(Wd + (size_t)2080 * DI + base + 2) = z;
    } else {
        const int i = (blk - 10496) * 256 + tid;
        float4 v = ((const float4*)x)[i];
        __half2 hh0, hh1;
        hh0.x = __float2half(v.x); hh0.y = __float2half(v.y);
        hh1.x = __float2half(v.z); hh1.y = __float2half(v.w);
        ((__half2*)xh)[2*i]   = hh0;
        ((__half2*)xh)[2*i+1] = hh1;
    }
}

// ---------------------------------------------------------------------------
// Chunked scan: ONE thread per channel, 16 states in registers.
// u and delta read as fp16; BC broadcast per warp; exp power-chain.
// ---------------------------------------------------------------------------
__device__ __forceinline__ bool a_uniform(const float* Alog, int d,
                                          float& A0, float& d10)
{
    A0 = -__expf(Alog[d * DS + 0]);
    float prev = -__expf(Alog[d * DS + 1]);
    d10 = prev - A0;
    bool uni = true;
#pragma unroll
    for (int i = 2; i < DS; ++i) {
        const float cur = -__expf(Alog[d * DS + i]);
        uni = uni && (fabsf((cur - prev) - d10) <= 1e-4f * fabsf(d10) + 1e-20f);
        prev = cur;
    }
    return uni;
}

__device__ __forceinline__ void chain_a(float a0, float r, float* a)
{
    const float r2 = r * r;
    const float r4 = r2 * r2;
    const float r8 = r4 * r4;
    a[0] = a0;
    a[1] = a0 * r;  a[2] = a0 * r2; a[3] = a[1] * r2;
    a[4] = a0 * r4; a[5] = a[1] * r4; a[6] = a[2] * r4; a[7] = a[3] * r4;
#pragma unroll
    for (int i = 0; i < 8; ++i) a[8 + i] = a[i] * r8;
}

__global__ void __launch_bounds__(128)
scanA(const __half* __restrict__ Dh,
      const __half* __restrict__ Uh,
      const float* __restrict__ BC, const float* __restrict__ Alog,
      float4* __restrict__ P4, float4* __restrict__ Q4)
{
    const int c = blockIdx.y;
    const int g = blockIdx.x * 128 + threadIdx.x;
    const int b = g >> 11;
    const int d = g & (DI - 1);

    float A0, d10;
    const bool uni = a_uniform(Alog, d, A0, d10);

    float h[DS];
#pragma unroll
    for (int i = 0; i < DS; ++i) h[i] = 0.f;

    size_t xbase = ((size_t)b * Lseq + (size_t)c * TL) * DI + d;
    size_t rbase = ((size_t)b * Lseq + (size_t)c * TL) * 32;

    if (uni) {
        float sdelta = 0.f;
#pragma unroll 2
        for (int t = 0; t < TL; ++t) {
            const float delta = __half2float(Dh[xbase]);
            const float uu    = __half2float(Uh[xbase]);
            float Bv[DS];
#pragma unroll
            for (int q = 0; q < 4; ++q)
                *(float4*)&Bv[q * 4] = *(const float4*)(BC + rbase + q * 4);

            float a[DS];
            chain_a(__expf(delta * A0), __expf(delta * d10), a);
            const float db = delta * uu;
#pragma unroll
            for (int i = 0; i < DS; ++i)
                h[i] = fmaf(a[i], h[i], db * Bv[i]);
            sdelta += delta;
            xbase += DI;
            rbase += 32;
        }
        const int idx = (((c * 2 + b) * DI) + d) * 4;
#pragma unroll
        for (int s = 0; s < 4; ++s) {
            float4 Pv;
            Pv.x = __expf(sdelta * (A0 + (4*s + 0) * d10));
            Pv.y = __expf(sdelta * (A0 + (4*s + 1) * d10));
            Pv.z = __expf(sdelta * (A0 + (4*s + 2) * d10));
            Pv.w = __expf(sdelta * (A0 + (4*s + 3) * d10));
            P4[idx + s] = Pv;
            Q4[idx + s] = make_float4(h[4*s], h[4*s+1], h[4*s+2], h[4*s+3]);
        }
    } else {
        float P[DS];
#pragma unroll
        for (int i = 0; i < DS; ++i) P[i] = 1.f;
        for (int t = 0; t < TL; ++t) {
            const float delta = __half2float(Dh[xbase]);
            const float uu    = __half2float(Uh[xbase]);
            const float db = delta * uu;
#pragma unroll
            for (int i = 0; i < DS; ++i) {
                const float Ai = -__expf(Alog[d * DS + i]);
                const float a = __expf(delta * Ai);
                h[i] = fmaf(a, h[i], db * BC[rbase + i]);
                P[i] *= a;
            }
            xbase += DI;
            rbase += 32;
        }
        const int idx = (((c * 2 + b) * DI) + d) * 4;
#pragma unroll
        for (int s = 0; s < 4; ++s) {
            P4[idx + s] = make_float4(P[4*s], P[4*s+1], P[4*s+2], P[4*s+3]);
            Q4[idx + s] = make_float4(h[4*s], h[4*s+1], h[4*s+2], h[4*s+3]);
        }
    }
}

__global__ void __launch_bounds__(256)
scanB(const float4* __restrict__ P4, const float4* __restrict__ Q4,
      float4* __restrict__ H4)
{
    const int gs = blockIdx.x * 256 + threadIdx.x;
    const int g = gs >> 2;
    const int sub = gs & 3;
    const int b = g >> 11;
    const int d = g & (DI - 1);

    float4 h = make_float4(0.f, 0.f, 0.f, 0.f);
#pragma unroll
    for (int c = 0; c < CH; ++c) {
        const int idx = (((c * 2 + b) * DI) + d) * 4 + sub;
        H4[idx] = h;
        const float4 P = P4[idx];
        const float4 q = Q4[idx];
        h.x = fmaf(P.x, h.x, q.x);
        h.y = fmaf(P.y, h.y, q.y);
        h.z = fmaf(P.z, h.z, q.z);
        h.w = fmaf(P.w, h.w, q.w);
    }
}

__global__ void __launch_bounds__(128)
scanC(const __half* __restrict__ Dh,
      const __half* __restrict__ Uh,
      const __half* __restrict__ Sh,
      const float* __restrict__ BC,
      const float* __restrict__ Alog, const float* __restrict__ Dp,
      const float4* __restrict__ H4,
      __half* __restrict__ Yh)
{
    const int c = blockIdx.y;
    const int g = blockIdx.x * 128 + threadIdx.x;
    const int b = g >> 11;
    const int d = g & (DI - 1);

    float A0, d10;
    const bool uni = a_uniform(Alog, d, A0, d10);
    const float Dd = Dp[d];

    const int idx = (((c * 2 + b) * DI) + d) * 4;
    float h[DS];
#pragma unroll
    for (int s = 0; s < 4; ++s) {
        const float4 hv = H4[idx + s];
        h[4*s] = hv.x; h[4*s+1] = hv.y; h[4*s+2] = hv.z; h[4*s+3] = hv.w;
    }

    size_t xbase = ((size_t)b * Lseq + (size_t)c * TL) * DI + d;
    size_t rbase = ((size_t)b * Lseq + (size_t)c * TL) * 32;

    if (uni) {
#pragma unroll 2
        for (int t = 0; t < TL; ++t) {
            const float delta = __half2float(Dh[xbase]);
            const float uu    = __half2float(Uh[xbase]);
            float Bv[DS], Cv[DS];
#pragma unroll
            for (int q = 0; q < 4; ++q) {
                *(float4*)&Bv[q * 4] = *(const float4*)(BC + rbase + q * 4);
                *(float4*)&Cv[q * 4] = *(const float4*)(BC + rbase + 16 + q * 4);
            }
            float a[DS];
            chain_a(__expf(delta * A0), __expf(delta * d10), a);
            const float db = delta * uu;
            float y0 = 0.f, y1 = 0.f, y2 = 0.f, y3 = 0.f;
#pragma unroll
            for (int i = 0; i < DS; i += 4) {
                h[i]   = fmaf(a[i],   h[i],   db * Bv[i]);
                h[i+1] = fmaf(a[i+1], h[i+1], db * Bv[i+1]);
                h[i+2] = fmaf(a[i+2], h[i+2], db * Bv[i+2]);
                h[i+3] = fmaf(a[i+3], h[i+3], db * Bv[i+3]);
                y0 = fmaf(h[i],   Cv[i],   y0);
                y1 = fmaf(h[i+1], Cv[i+1], y1);
                y2 = fmaf(h[i+2], Cv[i+2], y2);
                y3 = fmaf(h[i+3], Cv[i+3], y3);
            }
            const float yv = (((y0 + y1) + (y2 + y3)) + uu * Dd) * __half2float(Sh[xbase]);
            Yh[xbase] = __float2half(yv);
            xbase += DI;
            rbase += 32;
        }
    } else {
        for (int t = 0; t < TL; ++t) {
            const float delta = __half2float(Dh[xbase]);
            const float uu    = __half2float(Uh[xbase]);
            const float db = delta * uu;
            float yv = 0.f;
#pragma unroll
            for (int i = 0; i < DS; ++i) {
                const float Ai = -__expf(Alog[d * DS + i]);
                const float a = __expf(delta * Ai);
                h[i] = fmaf(a, h[i], db * BC[rbase + i]);
                yv = fmaf(h[i], BC[rbase + 16 + i], yv);
            }
            yv = (yv + uu * Dd) * __half2float(Sh[xbase]);
            Yh[xbase] = __float2half(yv);
            xbase += DI;
            rbase += 32;
        }
    }
}

// ---------------------------------------------------------------------------
extern "C" void kernel_launch(void* const* d_in, const int* in_sizes, int n_in,
                              void* d_out, int out_size)
{
    const float* x       = (const float*)d_in[0];
    const float* W_in    = (const float*)d_in[1];
    const float* W_delta = (const float*)d_in[2];
    const float* b_delta = (const float*)d_in[3];
    const float* W_B     = (const float*)d_in[4];
    const float* W_C     = (const float*)d_in[5];
    const float* A_log   = (const float*)d_in[6];
    const float* D_param = (const float*)d_in[7];
    const float* W_out   = (const float*)d_in[8];
    float* out = (float*)d_out;

    float *pBC;
    __half *pSh, *pDh, *pUh, *pYh, *pxh, *pWi, *pWd, *pWo;
    float4 *pP4, *pQ4, *pH4;
    cudaGetSymbolAddress((void**)&pSh,  g_Sh);
    cudaGetSymbolAddress((void**)&pDh,  g_Dh);
    cudaGetSymbolAddress((void**)&pBC,  g_BC);
    cudaGetSymbolAddress((void**)&pUh,  g_Uh);
    cudaGetSymbolAddress((void**)&pYh,  g_Yh);
    cudaGetSymbolAddress((void**)&pxh,  g_xh);
    cudaGetSymbolAddress((void**)&pWi,  g_WinT);
    cudaGetSymbolAddress((void**)&pWd,  g_WdT);
    cudaGetSymbolAddress((void**)&pWo,  g_WoT);
    cudaGetSymbolAddress((void**)&pP4,  g_P4);
    cudaGetSymbolAddress((void**)&pQ4,  g_Q4);
    cudaGetSymbolAddress((void**)&pH4,  g_H4);

    cudaFuncSetAttribute((const void*)tgemm<0>, cudaFuncAttributeMaxDynamicSharedMemorySize, SMEM_TOT);
    cudaFuncSetAttribute((const void*)tgemm<1>, cudaFuncAttributeMaxDynamicSharedMemorySize, SMEM_TOT);
    cudaFuncSetAttribute((const void*)tgemm<2>, cudaFuncAttributeMaxDynamicSharedMemorySize, SMEM_TOT);

    // Order: prep(1) tgemm0(2) tgemm1(3) scanA(4 <- ncu slot)
    //        scanB(5) scanC(6) tgemm2(7)
    prep_all<<<14592, 256>>>(W_in, W_delta, W_out, W_B, W_C, x,
                             pWi, pWd, pWo, pxh);

    // 1) x @ W_in -> U (silu, fp16) | S (silu, fp16)
    tgemm<0><<<dim3(32, Mrows / 128), 256, SMEM_TOT>>>(
        pxh, pWi, DM, 2048, 0, nullptr, nullptr, nullptr, pUh, pSh);

    // 2+3) DELTA (fp16) = softplus(Uh @ W_delta + b) fused with Bm|Cm
    tgemm<1><<<dim3(ND / 128, Mrows / 128), 256, SMEM_TOT>>>(
        pUh, pWd, DI, DI, 0, b_delta, nullptr, pBC, pDh, nullptr);

    // 4) chunked selective scan -> Y (fp16)
    scanA<<<dim3(Mrows / 128, CH), 128>>>(pDh, pUh, pBC, A_log, pP4, pQ4);
    scanB<<<64, 256>>>(pP4, pQ4, pH4);
    scanC<<<dim3(Mrows / 128, CH), 128>>>(pDh, pUh, pSh, pBC, A_log,
                                          D_param, pH4, pYh);

    // 5) out = Y @ W_out
    tgemm<2><<<dim3(DM / 128, Mrows / 128), 256, SMEM_TOT>>>(
        pYh, pWo, DI, DM, 0, nullptr, out, nullptr, nullptr, nullptr);
}